// round 1
// baseline (speedup 1.0000x reference)
#include <cuda_runtime.h>
#include <math.h>

#define D_MODEL 2048
#define SEQ     2048
#define BATCH   2
#define NHEAD   16
#define HD      128
#define MROWS   (BATCH*SEQ)   // 4096

// Scratch (allocation-free rule: __device__ globals)
__device__ float g_q[MROWS * D_MODEL];
__device__ float g_k[MROWS * D_MODEL];
__device__ float g_v[MROWS * D_MODEL];
__device__ float g_attn[MROWS * D_MODEL];

// ---------------------------------------------------------------------------
// fp32 tiled GEMM: C[M,N] = A[M,K] @ B[K,N]; M,N multiples of 128, K of 16.
// 256 threads, 128x128 block tile, BK=16, 8x8 per-thread microtile.
// ---------------------------------------------------------------------------
__global__ __launch_bounds__(256)
void gemm128(const float* __restrict__ A, const float* __restrict__ B,
             float* __restrict__ C, int M, int N, int K) {
    __shared__ float Ast[16][128];   // A transposed: Ast[k][m]
    __shared__ float Bs[16][128];    // Bs[k][n]

    const int tid = threadIdx.x;
    const int tx = tid & 15;
    const int ty = tid >> 4;
    const int bx = blockIdx.x;
    const int by = blockIdx.y;

    const float* Ab = A + (size_t)by * 128 * K;
    const float* Bb = B + (size_t)bx * 128;

    const int arow = tid >> 2;          // 0..63
    const int akc  = (tid & 3) << 2;    // 0,4,8,12
    const int brow = tid >> 5;          // 0..7
    const int bcc  = (tid & 31) << 2;   // 0..124

    float acc[8][8];
    #pragma unroll
    for (int i = 0; i < 8; i++)
        #pragma unroll
        for (int j = 0; j < 8; j++) acc[i][j] = 0.f;

    for (int k0 = 0; k0 < K; k0 += 16) {
        float4 a0 = *(const float4*)(Ab + (size_t)arow * K + k0 + akc);
        float4 a1 = *(const float4*)(Ab + (size_t)(arow + 64) * K + k0 + akc);
        float4 b0 = *(const float4*)(Bb + (size_t)(k0 + brow) * N + bcc);
        float4 b1 = *(const float4*)(Bb + (size_t)(k0 + brow + 8) * N + bcc);

        __syncthreads();
        Ast[akc + 0][arow] = a0.x;  Ast[akc + 1][arow] = a0.y;
        Ast[akc + 2][arow] = a0.z;  Ast[akc + 3][arow] = a0.w;
        Ast[akc + 0][arow + 64] = a1.x;  Ast[akc + 1][arow + 64] = a1.y;
        Ast[akc + 2][arow + 64] = a1.z;  Ast[akc + 3][arow + 64] = a1.w;
        *(float4*)&Bs[brow][bcc]     = b0;
        *(float4*)&Bs[brow + 8][bcc] = b1;
        __syncthreads();

        #pragma unroll
        for (int kk = 0; kk < 16; kk++) {
            float a[8], b[8];
            *(float4*)(a)     = *(const float4*)&Ast[kk][ty * 8];
            *(float4*)(a + 4) = *(const float4*)&Ast[kk][ty * 8 + 4];
            *(float4*)(b)     = *(const float4*)&Bs[kk][tx * 8];
            *(float4*)(b + 4) = *(const float4*)&Bs[kk][tx * 8 + 4];
            #pragma unroll
            for (int i = 0; i < 8; i++)
                #pragma unroll
                for (int j = 0; j < 8; j++)
                    acc[i][j] = fmaf(a[i], b[j], acc[i][j]);
        }
    }

    #pragma unroll
    for (int i = 0; i < 8; i++) {
        float* crow = C + (size_t)(by * 128 + ty * 8 + i) * N + bx * 128 + tx * 8;
        float4 v0 = make_float4(acc[i][0], acc[i][1], acc[i][2], acc[i][3]);
        float4 v1 = make_float4(acc[i][4], acc[i][5], acc[i][6], acc[i][7]);
        *(float4*)(crow)     = v0;
        *(float4*)(crow + 4) = v1;
    }
}

// ---------------------------------------------------------------------------
// Interleaved RoPE applied in-place to q and k.
// Matches the reference float32 math: inv_freq = 10000^(-2u/Hd), ang = s*inv_freq.
// ---------------------------------------------------------------------------
__global__ void rope_kernel(float* __restrict__ q, float* __restrict__ k) {
    const int total = MROWS * NHEAD * (HD / 2);   // 4,194,304
    int idx = blockIdx.x * blockDim.x + threadIdx.x;
    if (idx >= total) return;
    int u   = idx & 63;            // pair index within head (0..63)
    int h   = (idx >> 6) & 15;     // head
    int row = idx >> 10;           // 0..4095  (b*SEQ + s)
    int s   = row & (SEQ - 1);

    // inv_freq = 10000^(-(2u)/128) = 2^(-log2(10000) * 2u/128)
    float inv_freq = exp2f(-13.287712379549449f * ((float)(2 * u) * (1.0f / 128.0f)));
    float ang = (float)s * inv_freq;
    float sn, cs;
    sincosf(ang, &sn, &cs);

    size_t off = (size_t)row * D_MODEL + h * HD + 2 * u;
    float2 qv = *(float2*)(q + off);
    float2 kv = *(float2*)(k + off);
    float2 qo, ko;
    qo.x = qv.x * cs - qv.y * sn;  qo.y = qv.x * sn + qv.y * cs;
    ko.x = kv.x * cs - kv.y * sn;  ko.y = kv.x * sn + kv.y * cs;
    *(float2*)(q + off) = qo;
    *(float2*)(k + off) = ko;
}

// ---------------------------------------------------------------------------
// Causal flash attention, fp32, online softmax.
// Block: 256 threads; tile: 64 q-rows x 64 k-cols, Hd=128 in smem.
// grid.x = SEQ/64 (q tile), grid.y = B*H.
// ---------------------------------------------------------------------------
#define FLASH_SMEM_BYTES ((3 * 64 * 129 + 64 * 65) * 4)

__global__ __launch_bounds__(256)
void flash64(const float* __restrict__ Q, const float* __restrict__ K,
             const float* __restrict__ V, float* __restrict__ O) {
    extern __shared__ float sm[];
    float* Qs = sm;                  // [64][129]
    float* Ks = Qs + 64 * 129;       // [64][129]
    float* Vs = Ks + 64 * 129;       // [64][129]
    float* Ps = Vs + 64 * 129;       // [64][65]

    const int tid = threadIdx.x;
    const int tx = tid & 15;
    const int ty = tid >> 4;
    const int qt = blockIdx.x;
    const int bh = blockIdx.y;
    const int b  = bh >> 4;
    const int h  = bh & 15;

    const size_t base = ((size_t)b * SEQ) * D_MODEL + (size_t)h * HD;
    const int lrow = tid >> 5;           // 0..7
    const int lcol = (tid & 31) << 2;    // 0..124

    // load Q tile
    #pragma unroll
    for (int it = 0; it < 8; it++) {
        int r = lrow + it * 8;
        float4 v = *(const float4*)(Q + base + (size_t)(qt * 64 + r) * D_MODEL + lcol);
        float* dst = Qs + r * 129 + lcol;
        dst[0] = v.x; dst[1] = v.y; dst[2] = v.z; dst[3] = v.w;
    }

    float o[4][8];
    #pragma unroll
    for (int i = 0; i < 4; i++)
        #pragma unroll
        for (int j = 0; j < 8; j++) o[i][j] = 0.f;

    float m_[4], l_[4];
    #pragma unroll
    for (int i = 0; i < 4; i++) { m_[i] = -INFINITY; l_[i] = 0.f; }

    const float sc = 0.08838834764831845f * 1.4426950408889634f; // rsqrt(128)*log2(e)

    for (int kt = 0; kt <= qt; kt++) {
        __syncthreads();   // guard Ks/Vs overwrite vs previous PV reads
        #pragma unroll
        for (int it = 0; it < 8; it++) {
            int r = lrow + it * 8;
            size_t goff = base + (size_t)(kt * 64 + r) * D_MODEL + lcol;
            float4 kv4 = *(const float4*)(K + goff);
            float4 vv4 = *(const float4*)(V + goff);
            float* kd = Ks + r * 129 + lcol;
            kd[0] = kv4.x; kd[1] = kv4.y; kd[2] = kv4.z; kd[3] = kv4.w;
            float* vd = Vs + r * 129 + lcol;
            vd[0] = vv4.x; vd[1] = vv4.y; vd[2] = vv4.z; vd[3] = vv4.w;
        }
        __syncthreads();

        // S = Q K^T  (64x64 tile; thread owns rows ty+16i, cols tx+16j)
        float s[4][4];
        #pragma unroll
        for (int i = 0; i < 4; i++)
            #pragma unroll
            for (int j = 0; j < 4; j++) s[i][j] = 0.f;

        #pragma unroll 4
        for (int d = 0; d < HD; d++) {
            float qv[4], kv[4];
            #pragma unroll
            for (int i = 0; i < 4; i++) qv[i] = Qs[(ty + 16 * i) * 129 + d];
            #pragma unroll
            for (int j = 0; j < 4; j++) kv[j] = Ks[(tx + 16 * j) * 129 + d];
            #pragma unroll
            for (int i = 0; i < 4; i++)
                #pragma unroll
                for (int j = 0; j < 4; j++)
                    s[i][j] = fmaf(qv[i], kv[j], s[i][j]);
        }

        #pragma unroll
        for (int i = 0; i < 4; i++)
            #pragma unroll
            for (int j = 0; j < 4; j++) s[i][j] *= sc;

        if (kt == qt) {
            #pragma unroll
            for (int i = 0; i < 4; i++)
                #pragma unroll
                for (int j = 0; j < 4; j++)
                    if (tx + 16 * j > ty + 16 * i) s[i][j] = -INFINITY;
        }

        // online softmax (log2 domain)
        #pragma unroll
        for (int i = 0; i < 4; i++) {
            float mx = fmaxf(fmaxf(s[i][0], s[i][1]), fmaxf(s[i][2], s[i][3]));
            mx = fmaxf(mx, __shfl_xor_sync(0xffffffffu, mx, 1));
            mx = fmaxf(mx, __shfl_xor_sync(0xffffffffu, mx, 2));
            mx = fmaxf(mx, __shfl_xor_sync(0xffffffffu, mx, 4));
            mx = fmaxf(mx, __shfl_xor_sync(0xffffffffu, mx, 8));
            float mn = fmaxf(m_[i], mx);
            float alpha = exp2f(m_[i] - mn);
            m_[i] = mn;
            float ps = 0.f;
            #pragma unroll
            for (int j = 0; j < 4; j++) {
                float p = exp2f(s[i][j] - mn);
                Ps[(ty + 16 * i) * 65 + tx + 16 * j] = p;
                ps += p;
            }
            ps += __shfl_xor_sync(0xffffffffu, ps, 1);
            ps += __shfl_xor_sync(0xffffffffu, ps, 2);
            ps += __shfl_xor_sync(0xffffffffu, ps, 4);
            ps += __shfl_xor_sync(0xffffffffu, ps, 8);
            l_[i] = l_[i] * alpha + ps;
            #pragma unroll
            for (int j = 0; j < 8; j++) o[i][j] *= alpha;
        }
        __syncthreads();   // Ps visible to all before PV

        // O += P V   (thread owns rows ty+16i, d-cols tx+16j)
        #pragma unroll 2
        for (int kk = 0; kk < 64; kk++) {
            float pv[4], vv[8];
            #pragma unroll
            for (int i = 0; i < 4; i++) pv[i] = Ps[(ty + 16 * i) * 65 + kk];
            #pragma unroll
            for (int j = 0; j < 8; j++) vv[j] = Vs[kk * 129 + tx + 16 * j];
            #pragma unroll
            for (int i = 0; i < 4; i++)
                #pragma unroll
                for (int j = 0; j < 8; j++)
                    o[i][j] = fmaf(pv[i], vv[j], o[i][j]);
        }
    }

    #pragma unroll
    for (int i = 0; i < 4; i++) {
        float inv = 1.0f / l_[i];
        #pragma unroll
        for (int j = 0; j < 8; j++) {
            O[base + (size_t)(qt * 64 + ty + 16 * i) * D_MODEL + tx + 16 * j] = o[i][j] * inv;
        }
    }
}

// ---------------------------------------------------------------------------
extern "C" void kernel_launch(void* const* d_in, const int* in_sizes, int n_in,
                              void* d_out, int out_size) {
    const float* x  = (const float*)d_in[0];
    const float* Wq = (const float*)d_in[1];
    const float* Wk = (const float*)d_in[2];
    const float* Wv = (const float*)d_in[3];
    const float* Wo = (const float*)d_in[4];
    float* out = (float*)d_out;

    float *qp, *kp, *vp, *ap;
    cudaGetSymbolAddress((void**)&qp, g_q);
    cudaGetSymbolAddress((void**)&kp, g_k);
    cudaGetSymbolAddress((void**)&vp, g_v);
    cudaGetSymbolAddress((void**)&ap, g_attn);

    cudaFuncSetAttribute(flash64, cudaFuncAttributeMaxDynamicSharedMemorySize,
                         FLASH_SMEM_BYTES);

    dim3 gblk(256);
    dim3 ggrid(D_MODEL / 128, MROWS / 128);   // (16, 32)

    gemm128<<<ggrid, gblk>>>(x, Wq, qp, MROWS, D_MODEL, D_MODEL);
    gemm128<<<ggrid, gblk>>>(x, Wk, kp, MROWS, D_MODEL, D_MODEL);
    gemm128<<<ggrid, gblk>>>(x, Wv, vp, MROWS, D_MODEL, D_MODEL);

    {
        int total = MROWS * NHEAD * (HD / 2);
        int blocks = (total + 255) / 256;
        rope_kernel<<<blocks, 256>>>(qp, kp);
    }

    {
        dim3 fgrid(SEQ / 64, BATCH * NHEAD);  // (32, 32)
        flash64<<<fgrid, 256, FLASH_SMEM_BYTES>>>(qp, kp, vp, ap);
    }

    gemm128<<<ggrid, gblk>>>(ap, Wo, out, MROWS, D_MODEL, D_MODEL);
}

// round 3
// speedup vs baseline: 1.6091x; 1.6091x over previous
#include <cuda_runtime.h>
#include <cuda_bf16.h>
#include <cstdint>
#include <math.h>

#define D_MODEL 2048
#define SEQ     2048
#define BATCH   2
#define NHEAD   16
#define HD      128
#define MROWS   (BATCH*SEQ)   // 4096

// ---------------------------------------------------------------------------
// Scratch (__device__ globals: allocation-free rule)
// ---------------------------------------------------------------------------
__device__ float g_q[MROWS * D_MODEL];
__device__ float g_k[MROWS * D_MODEL];
__device__ float g_v[MROWS * D_MODEL];
__device__ float g_attn[MROWS * D_MODEL];

__device__ __nv_bfloat16 g_xh[MROWS * D_MODEL];
__device__ __nv_bfloat16 g_xl[MROWS * D_MODEL];
__device__ __nv_bfloat16 g_ah[MROWS * D_MODEL];
__device__ __nv_bfloat16 g_al[MROWS * D_MODEL];

__device__ __nv_bfloat16 g_wqh[D_MODEL * D_MODEL];
__device__ __nv_bfloat16 g_wql[D_MODEL * D_MODEL];
__device__ __nv_bfloat16 g_wkh[D_MODEL * D_MODEL];
__device__ __nv_bfloat16 g_wkl[D_MODEL * D_MODEL];
__device__ __nv_bfloat16 g_wvh[D_MODEL * D_MODEL];
__device__ __nv_bfloat16 g_wvl[D_MODEL * D_MODEL];
__device__ __nv_bfloat16 g_woh[D_MODEL * D_MODEL];
__device__ __nv_bfloat16 g_wol[D_MODEL * D_MODEL];

// ---------------------------------------------------------------------------
// PTX helpers (plain sm_103: no tcgen05!)
// ---------------------------------------------------------------------------
__device__ __forceinline__ uint32_t smem_u32(const void* p) {
    uint32_t a;
    asm("{ .reg .u64 t; cvta.to.shared.u64 t, %1; cvt.u32.u64 %0, t; }" : "=r"(a) : "l"(p));
    return a;
}
__device__ __forceinline__ void cp16(uint32_t dst, const void* src) {
    asm volatile("cp.async.cg.shared.global [%0], [%1], 16;" :: "r"(dst), "l"(src) : "memory");
}
#define CP_COMMIT() asm volatile("cp.async.commit_group;" ::: "memory")
#define CP_WAIT(n)  asm volatile("cp.async.wait_group %0;" :: "n"(n) : "memory")

#define LDSM_X4(r, addr) \
    asm volatile("ldmatrix.sync.aligned.m8n8.x4.shared.b16 {%0,%1,%2,%3}, [%4];" \
        : "=r"((r)[0]), "=r"((r)[1]), "=r"((r)[2]), "=r"((r)[3]) : "r"(addr))

#define MMA_BF16(c, a, b) \
    asm volatile("mma.sync.aligned.m16n8k16.row.col.f32.bf16.bf16.f32 " \
        "{%0,%1,%2,%3}, {%4,%5,%6,%7}, {%8,%9}, {%0,%1,%2,%3};" \
        : "+f"((c)[0]), "+f"((c)[1]), "+f"((c)[2]), "+f"((c)[3]) \
        : "r"((a)[0]), "r"((a)[1]), "r"((a)[2]), "r"((a)[3]), "r"((b)[0]), "r"((b)[1]))

// ---------------------------------------------------------------------------
// fp32 -> (bf16 hi, bf16 lo) elementwise split
// ---------------------------------------------------------------------------
__global__ void split_e(const float* __restrict__ in, __nv_bfloat16* __restrict__ hi,
                        __nv_bfloat16* __restrict__ lo, int n4) {
    int i = blockIdx.x * blockDim.x + threadIdx.x;
    if (i >= n4) return;
    float4 v = ((const float4*)in)[i];
    __nv_bfloat16 h0 = __float2bfloat16(v.x), h1 = __float2bfloat16(v.y);
    __nv_bfloat16 h2 = __float2bfloat16(v.z), h3 = __float2bfloat16(v.w);
    __nv_bfloat16 l0 = __float2bfloat16(v.x - __bfloat162float(h0));
    __nv_bfloat16 l1 = __float2bfloat16(v.y - __bfloat162float(h1));
    __nv_bfloat16 l2 = __float2bfloat16(v.z - __bfloat162float(h2));
    __nv_bfloat16 l3 = __float2bfloat16(v.w - __bfloat162float(h3));
    ((__nv_bfloat162*)hi)[2*i]   = __nv_bfloat162(h0, h1);
    ((__nv_bfloat162*)hi)[2*i+1] = __nv_bfloat162(h2, h3);
    ((__nv_bfloat162*)lo)[2*i]   = __nv_bfloat162(l0, l1);
    ((__nv_bfloat162*)lo)[2*i+1] = __nv_bfloat162(l2, l3);
}

// fp32 W[K,N] -> transposed bf16 hi/lo [N,K]
__global__ void split_t(const float* __restrict__ in, __nv_bfloat16* __restrict__ hiT,
                        __nv_bfloat16* __restrict__ loT) {
    __shared__ float t[32][33];
    int tx = threadIdx.x, ty = threadIdx.y;
    int bn = blockIdx.x, bk = blockIdx.y;
    #pragma unroll
    for (int j = 0; j < 4; j++) {
        int k = bk * 32 + ty + j * 8;
        t[ty + j * 8][tx] = in[(size_t)k * D_MODEL + bn * 32 + tx];
    }
    __syncthreads();
    #pragma unroll
    for (int j = 0; j < 4; j++) {
        int n = bn * 32 + ty + j * 8;
        float v = t[tx][ty + j * 8];
        __nv_bfloat16 h = __float2bfloat16(v);
        __nv_bfloat16 l = __float2bfloat16(v - __bfloat162float(h));
        size_t off = (size_t)n * D_MODEL + bk * 32 + tx;
        hiT[off] = h;
        loT[off] = l;
    }
}

// ---------------------------------------------------------------------------
// HMMA GEMM: C[4096,2048] = A[4096,2048] @ W (W given transposed [N,K], hi/lo)
// CTA 128x128, BK=32, 3-stage cp.async pipeline, 8 warps (2x4), warp 64x32.
// Split-bf16: acc += Ah*Bh + Ah*Bl + Al*Bh  (all fp32 accum).
// ---------------------------------------------------------------------------
#define PADB   80                 // 40 bf16 per row (32 data + 8 pad)
#define MATB   (128 * PADB)       // 10240 B per matrix tile
#define STAGEB (4 * MATB)         // 40960 B per stage (Ah, Al, Bh, Bl)
#define NSTAGE 3
#define GEMM_SMEM (NSTAGE * STAGEB)   // 122880 B

__global__ __launch_bounds__(256)
void gemm_hmma(const __nv_bfloat16* __restrict__ Ah, const __nv_bfloat16* __restrict__ Al,
               const __nv_bfloat16* __restrict__ Bh, const __nv_bfloat16* __restrict__ Bl,
               float* __restrict__ C) {
    extern __shared__ char smem[];
    const uint32_t sb = smem_u32(smem);
    const int tid  = threadIdx.x;
    const int wid  = tid >> 5;
    const int lane = tid & 31;
    const int tileN = blockIdx.x;
    const int tileM = blockIdx.y;

    const int m0w = (wid >> 2) * 64;   // 0 or 64
    const int n0w = (wid & 3) * 32;    // 0,32,64,96

    const __nv_bfloat16* gp[4] = {
        Ah + (size_t)tileM * 128 * D_MODEL,
        Al + (size_t)tileM * 128 * D_MODEL,
        Bh + (size_t)tileN * 128 * D_MODEL,
        Bl + (size_t)tileN * 128 * D_MODEL
    };

    const int lrow = tid >> 2;       // 0..63? no: flat below
    (void)lrow;

    auto load_stage = [&](int s, int k0) {
        uint32_t sbase = sb + s * STAGEB;
        #pragma unroll
        for (int mat = 0; mat < 4; mat++) {
            #pragma unroll
            for (int rep = 0; rep < 2; rep++) {
                int flat = rep * 256 + tid;       // 0..511
                int row = flat >> 2;              // 0..127
                int c   = flat & 3;               // 16B chunk
                cp16(sbase + mat * MATB + row * PADB + c * 16,
                     gp[mat] + (size_t)row * D_MODEL + k0 + c * 8);
            }
        }
        CP_COMMIT();
    };

    float acc[4][4][4];
    #pragma unroll
    for (int i = 0; i < 4; i++)
        #pragma unroll
        for (int j = 0; j < 4; j++)
            #pragma unroll
            for (int r = 0; r < 4; r++) acc[i][j][r] = 0.f;

    load_stage(0, 0);
    load_stage(1, 32);

    const int NCH = D_MODEL / 32;   // 64
    for (int c = 0; c < NCH; c++) {
        if (c + 2 < NCH) { CP_WAIT(1); } else { CP_WAIT(0); }
        __syncthreads();
        if (c + 2 < NCH) load_stage((c + 2) % NSTAGE, (c + 2) * 32);

        const uint32_t st = sb + (c % NSTAGE) * STAGEB;
        #pragma unroll
        for (int ks = 0; ks < 2; ks++) {
            uint32_t ah[4][4], al[4][4];
            const uint32_t arow = (lane & 15);
            const uint32_t akb  = (ks * 16 + (lane >> 4) * 8) * 2;
            #pragma unroll
            for (int mt = 0; mt < 4; mt++) {
                uint32_t ra = st + (m0w + mt * 16 + arow) * PADB + akb;
                LDSM_X4(ah[mt], ra);
                LDSM_X4(al[mt], ra + MATB);
            }
            const uint32_t brow = (lane & 7) + ((lane >> 4) & 1) * 8;
            const uint32_t bkb  = (ks * 16 + ((lane >> 3) & 1) * 8) * 2;
            #pragma unroll
            for (int np = 0; np < 2; np++) {
                uint32_t rb = st + 2 * MATB + (n0w + np * 16 + brow) * PADB + bkb;
                uint32_t bh4[4], bl4[4];
                LDSM_X4(bh4, rb);
                LDSM_X4(bl4, rb + MATB);
                #pragma unroll
                for (int half = 0; half < 2; half++) {
                    const int nt = np * 2 + half;
                    uint32_t* bh = bh4 + half * 2;
                    uint32_t* bl = bl4 + half * 2;
                    #pragma unroll
                    for (int mt = 0; mt < 4; mt++) {
                        MMA_BF16(acc[mt][nt], ah[mt], bh);
                        MMA_BF16(acc[mt][nt], ah[mt], bl);
                        MMA_BF16(acc[mt][nt], al[mt], bh);
                    }
                }
            }
        }
    }

    // epilogue: regs -> smem staging [128][132] -> coalesced STG
    __syncthreads();
    float* stg = (float*)smem;
    {
        const int r  = lane >> 2;
        const int cq = (lane & 3) * 2;
        #pragma unroll
        for (int mt = 0; mt < 4; mt++) {
            #pragma unroll
            for (int nt = 0; nt < 4; nt++) {
                int row = m0w + mt * 16 + r;
                int col = n0w + nt * 8 + cq;
                *(float2*)&stg[row * 132 + col]       = make_float2(acc[mt][nt][0], acc[mt][nt][1]);
                *(float2*)&stg[(row + 8) * 132 + col] = make_float2(acc[mt][nt][2], acc[mt][nt][3]);
            }
        }
    }
    __syncthreads();
    float* crow = C + (size_t)tileM * 128 * D_MODEL + tileN * 128;
    #pragma unroll
    for (int i = 0; i < 16; i++) {
        int flat = (i << 8) + tid;          // 0..4095 float4s
        int r = flat >> 5;
        int c4 = (flat & 31) << 2;
        *(float4*)(crow + (size_t)r * D_MODEL + c4) = *(const float4*)&stg[r * 132 + c4];
    }
}

// ---------------------------------------------------------------------------
// Interleaved RoPE (in-place on q, k); matches reference fp32 math.
// ---------------------------------------------------------------------------
__global__ void rope_kernel(float* __restrict__ q, float* __restrict__ k) {
    const int total = MROWS * NHEAD * (HD / 2);
    int idx = blockIdx.x * blockDim.x + threadIdx.x;
    if (idx >= total) return;
    int u   = idx & 63;
    int h   = (idx >> 6) & 15;
    int row = idx >> 10;
    int s   = row & (SEQ - 1);

    float inv_freq = exp2f(-13.287712379549449f * ((float)(2 * u) * (1.0f / 128.0f)));
    float ang = (float)s * inv_freq;
    float sn, cs;
    sincosf(ang, &sn, &cs);

    size_t off = (size_t)row * D_MODEL + h * HD + 2 * u;
    float2 qv = *(float2*)(q + off);
    float2 kv = *(float2*)(k + off);
    float2 qo, ko;
    qo.x = qv.x * cs - qv.y * sn;  qo.y = qv.x * sn + qv.y * cs;
    ko.x = kv.x * cs - kv.y * sn;  ko.y = kv.x * sn + kv.y * cs;
    *(float2*)(q + off) = qo;
    *(float2*)(k + off) = ko;
}

// ---------------------------------------------------------------------------
// Causal flash attention, fp32 (unchanged from round 1 — known good)
// ---------------------------------------------------------------------------
#define FLASH_SMEM_BYTES ((3 * 64 * 129 + 64 * 65) * 4)

__global__ __launch_bounds__(256)
void flash64(const float* __restrict__ Q, const float* __restrict__ K,
             const float* __restrict__ V, float* __restrict__ O) {
    extern __shared__ float sm[];
    float* Qs = sm;
    float* Ks = Qs + 64 * 129;
    float* Vs = Ks + 64 * 129;
    float* Ps = Vs + 64 * 129;

    const int tid = threadIdx.x;
    const int tx = tid & 15;
    const int ty = tid >> 4;
    const int qt = blockIdx.x;
    const int bh = blockIdx.y;
    const int b  = bh >> 4;
    const int h  = bh & 15;

    const size_t base = ((size_t)b * SEQ) * D_MODEL + (size_t)h * HD;
    const int lrow = tid >> 5;
    const int lcol = (tid & 31) << 2;

    #pragma unroll
    for (int it = 0; it < 8; it++) {
        int r = lrow + it * 8;
        float4 v = *(const float4*)(Q + base + (size_t)(qt * 64 + r) * D_MODEL + lcol);
        float* dst = Qs + r * 129 + lcol;
        dst[0] = v.x; dst[1] = v.y; dst[2] = v.z; dst[3] = v.w;
    }

    float o[4][8];
    #pragma unroll
    for (int i = 0; i < 4; i++)
        #pragma unroll
        for (int j = 0; j < 8; j++) o[i][j] = 0.f;

    float m_[4], l_[4];
    #pragma unroll
    for (int i = 0; i < 4; i++) { m_[i] = -INFINITY; l_[i] = 0.f; }

    const float sc = 0.08838834764831845f * 1.4426950408889634f;

    for (int kt = 0; kt <= qt; kt++) {
        __syncthreads();
        #pragma unroll
        for (int it = 0; it < 8; it++) {
            int r = lrow + it * 8;
            size_t goff = base + (size_t)(kt * 64 + r) * D_MODEL + lcol;
            float4 kv4 = *(const float4*)(K + goff);
            float4 vv4 = *(const float4*)(V + goff);
            float* kd = Ks + r * 129 + lcol;
            kd[0] = kv4.x; kd[1] = kv4.y; kd[2] = kv4.z; kd[3] = kv4.w;
            float* vd = Vs + r * 129 + lcol;
            vd[0] = vv4.x; vd[1] = vv4.y; vd[2] = vv4.z; vd[3] = vv4.w;
        }
        __syncthreads();

        float s[4][4];
        #pragma unroll
        for (int i = 0; i < 4; i++)
            #pragma unroll
            for (int j = 0; j < 4; j++) s[i][j] = 0.f;

        #pragma unroll 4
        for (int d = 0; d < HD; d++) {
            float qv[4], kv[4];
            #pragma unroll
            for (int i = 0; i < 4; i++) qv[i] = Qs[(ty + 16 * i) * 129 + d];
            #pragma unroll
            for (int j = 0; j < 4; j++) kv[j] = Ks[(tx + 16 * j) * 129 + d];
            #pragma unroll
            for (int i = 0; i < 4; i++)
                #pragma unroll
                for (int j = 0; j < 4; j++)
                    s[i][j] = fmaf(qv[i], kv[j], s[i][j]);
        }

        #pragma unroll
        for (int i = 0; i < 4; i++)
            #pragma unroll
            for (int j = 0; j < 4; j++) s[i][j] *= sc;

        if (kt == qt) {
            #pragma unroll
            for (int i = 0; i < 4; i++)
                #pragma unroll
                for (int j = 0; j < 4; j++)
                    if (tx + 16 * j > ty + 16 * i) s[i][j] = -INFINITY;
        }

        #pragma unroll
        for (int i = 0; i < 4; i++) {
            float mx = fmaxf(fmaxf(s[i][0], s[i][1]), fmaxf(s[i][2], s[i][3]));
            mx = fmaxf(mx, __shfl_xor_sync(0xffffffffu, mx, 1));
            mx = fmaxf(mx, __shfl_xor_sync(0xffffffffu, mx, 2));
            mx = fmaxf(mx, __shfl_xor_sync(0xffffffffu, mx, 4));
            mx = fmaxf(mx, __shfl_xor_sync(0xffffffffu, mx, 8));
            float mn = fmaxf(m_[i], mx);
            float alpha = exp2f(m_[i] - mn);
            m_[i] = mn;
            float ps = 0.f;
            #pragma unroll
            for (int j = 0; j < 4; j++) {
                float p = exp2f(s[i][j] - mn);
                Ps[(ty + 16 * i) * 65 + tx + 16 * j] = p;
                ps += p;
            }
            ps += __shfl_xor_sync(0xffffffffu, ps, 1);
            ps += __shfl_xor_sync(0xffffffffu, ps, 2);
            ps += __shfl_xor_sync(0xffffffffu, ps, 4);
            ps += __shfl_xor_sync(0xffffffffu, ps, 8);
            l_[i] = l_[i] * alpha + ps;
            #pragma unroll
            for (int j = 0; j < 8; j++) o[i][j] *= alpha;
        }
        __syncthreads();

        #pragma unroll 2
        for (int kk = 0; kk < 64; kk++) {
            float pv[4], vv[8];
            #pragma unroll
            for (int i = 0; i < 4; i++) pv[i] = Ps[(ty + 16 * i) * 65 + kk];
            #pragma unroll
            for (int j = 0; j < 8; j++) vv[j] = Vs[kk * 129 + tx + 16 * j];
            #pragma unroll
            for (int i = 0; i < 4; i++)
                #pragma unroll
                for (int j = 0; j < 8; j++)
                    o[i][j] = fmaf(pv[i], vv[j], o[i][j]);
        }
    }

    #pragma unroll
    for (int i = 0; i < 4; i++) {
        float inv = 1.0f / l_[i];
        #pragma unroll
        for (int j = 0; j < 8; j++) {
            O[base + (size_t)(qt * 64 + ty + 16 * i) * D_MODEL + tx + 16 * j] = o[i][j] * inv;
        }
    }
}

// ---------------------------------------------------------------------------
extern "C" void kernel_launch(void* const* d_in, const int* in_sizes, int n_in,
                              void* d_out, int out_size) {
    const float* x  = (const float*)d_in[0];
    const float* Wq = (const float*)d_in[1];
    const float* Wk = (const float*)d_in[2];
    const float* Wv = (const float*)d_in[3];
    const float* Wo = (const float*)d_in[4];
    float* out = (float*)d_out;

    float *qp, *kp, *vp, *ap;
    cudaGetSymbolAddress((void**)&qp, g_q);
    cudaGetSymbolAddress((void**)&kp, g_k);
    cudaGetSymbolAddress((void**)&vp, g_v);
    cudaGetSymbolAddress((void**)&ap, g_attn);

    __nv_bfloat16 *xh, *xl, *ah, *al;
    cudaGetSymbolAddress((void**)&xh, g_xh);
    cudaGetSymbolAddress((void**)&xl, g_xl);
    cudaGetSymbolAddress((void**)&ah, g_ah);
    cudaGetSymbolAddress((void**)&al, g_al);

    __nv_bfloat16 *wqh, *wql, *wkh, *wkl, *wvh, *wvl, *woh, *wol;
    cudaGetSymbolAddress((void**)&wqh, g_wqh);
    cudaGetSymbolAddress((void**)&wql, g_wql);
    cudaGetSymbolAddress((void**)&wkh, g_wkh);
    cudaGetSymbolAddress((void**)&wkl, g_wkl);
    cudaGetSymbolAddress((void**)&wvh, g_wvh);
    cudaGetSymbolAddress((void**)&wvl, g_wvl);
    cudaGetSymbolAddress((void**)&woh, g_woh);
    cudaGetSymbolAddress((void**)&wol, g_wol);

    cudaFuncSetAttribute(gemm_hmma, cudaFuncAttributeMaxDynamicSharedMemorySize, GEMM_SMEM);
    cudaFuncSetAttribute(flash64, cudaFuncAttributeMaxDynamicSharedMemorySize, FLASH_SMEM_BYTES);

    // split inputs
    {
        int n4 = MROWS * D_MODEL / 4;
        split_e<<<(n4 + 255) / 256, 256>>>(x, xh, xl, n4);
        dim3 tb(32, 8), tg(D_MODEL / 32, D_MODEL / 32);
        split_t<<<tg, tb>>>(Wq, wqh, wql);
        split_t<<<tg, tb>>>(Wk, wkh, wkl);
        split_t<<<tg, tb>>>(Wv, wvh, wvl);
        split_t<<<tg, tb>>>(Wo, woh, wol);
    }

    dim3 ggrid(D_MODEL / 128, MROWS / 128);   // (16, 32)
    gemm_hmma<<<ggrid, 256, GEMM_SMEM>>>(xh, xl, wqh, wql, qp);
    gemm_hmma<<<ggrid, 256, GEMM_SMEM>>>(xh, xl, wkh, wkl, kp);
    gemm_hmma<<<ggrid, 256, GEMM_SMEM>>>(xh, xl, wvh, wvl, vp);

    {
        int total = MROWS * NHEAD * (HD / 2);
        rope_kernel<<<(total + 255) / 256, 256>>>(qp, kp);
    }

    {
        dim3 fgrid(SEQ / 64, BATCH * NHEAD);
        flash64<<<fgrid, 256, FLASH_SMEM_BYTES>>>(qp, kp, vp, ap);
    }

    {
        int n4 = MROWS * D_MODEL / 4;
        split_e<<<(n4 + 255) / 256, 256>>>(ap, ah, al, n4);
    }
    gemm_hmma<<<ggrid, 256, GEMM_SMEM>>>(ah, al, woh, wol, out);
}

// round 4
// speedup vs baseline: 2.5665x; 1.5950x over previous
#include <cuda_runtime.h>
#include <cuda_bf16.h>
#include <cstdint>
#include <math.h>

#define D_MODEL 2048
#define SEQ     2048
#define BATCH   2
#define NHEAD   16
#define HD      128
#define MROWS   (BATCH*SEQ)   // 4096

// ---------------------------------------------------------------------------
// Scratch (__device__ globals: allocation-free rule)
// ---------------------------------------------------------------------------
__device__ float g_q[MROWS * D_MODEL];
__device__ float g_k[MROWS * D_MODEL];
__device__ float g_v[MROWS * D_MODEL];

__device__ __nv_bfloat16 g_xh[MROWS * D_MODEL];
__device__ __nv_bfloat16 g_xl[MROWS * D_MODEL];
__device__ __nv_bfloat16 g_ah[MROWS * D_MODEL];
__device__ __nv_bfloat16 g_al[MROWS * D_MODEL];

__device__ __nv_bfloat16 g_qh[MROWS * D_MODEL];
__device__ __nv_bfloat16 g_ql[MROWS * D_MODEL];
__device__ __nv_bfloat16 g_kh[MROWS * D_MODEL];
__device__ __nv_bfloat16 g_kl[MROWS * D_MODEL];
__device__ __nv_bfloat16 g_vh[MROWS * D_MODEL];
__device__ __nv_bfloat16 g_vl[MROWS * D_MODEL];

__device__ __nv_bfloat16 g_wqh[D_MODEL * D_MODEL];
__device__ __nv_bfloat16 g_wql[D_MODEL * D_MODEL];
__device__ __nv_bfloat16 g_wkh[D_MODEL * D_MODEL];
__device__ __nv_bfloat16 g_wkl[D_MODEL * D_MODEL];
__device__ __nv_bfloat16 g_wvh[D_MODEL * D_MODEL];
__device__ __nv_bfloat16 g_wvl[D_MODEL * D_MODEL];
__device__ __nv_bfloat16 g_woh[D_MODEL * D_MODEL];
__device__ __nv_bfloat16 g_wol[D_MODEL * D_MODEL];

// ---------------------------------------------------------------------------
// PTX helpers (plain sm_103: no tcgen05)
// ---------------------------------------------------------------------------
__device__ __forceinline__ uint32_t smem_u32(const void* p) {
    uint32_t a;
    asm("{ .reg .u64 t; cvta.to.shared.u64 t, %1; cvt.u32.u64 %0, t; }" : "=r"(a) : "l"(p));
    return a;
}
__device__ __forceinline__ void cp16(uint32_t dst, const void* src) {
    asm volatile("cp.async.cg.shared.global [%0], [%1], 16;" :: "r"(dst), "l"(src) : "memory");
}
#define CP_COMMIT() asm volatile("cp.async.commit_group;" ::: "memory")
#define CP_WAIT(n)  asm volatile("cp.async.wait_group %0;" :: "n"(n) : "memory")

#define LDSM_X4(r, addr) \
    asm volatile("ldmatrix.sync.aligned.m8n8.x4.shared.b16 {%0,%1,%2,%3}, [%4];" \
        : "=r"((r)[0]), "=r"((r)[1]), "=r"((r)[2]), "=r"((r)[3]) : "r"(addr))
#define LDSM_T_X4(r, addr) \
    asm volatile("ldmatrix.sync.aligned.m8n8.x4.trans.shared.b16 {%0,%1,%2,%3}, [%4];" \
        : "=r"((r)[0]), "=r"((r)[1]), "=r"((r)[2]), "=r"((r)[3]) : "r"(addr))

#define MMA_BF16(c, a, b) \
    asm volatile("mma.sync.aligned.m16n8k16.row.col.f32.bf16.bf16.f32 " \
        "{%0,%1,%2,%3}, {%4,%5,%6,%7}, {%8,%9}, {%0,%1,%2,%3};" \
        : "+f"((c)[0]), "+f"((c)[1]), "+f"((c)[2]), "+f"((c)[3]) \
        : "r"((a)[0]), "r"((a)[1]), "r"((a)[2]), "r"((a)[3]), "r"((b)[0]), "r"((b)[1]))

__device__ __forceinline__ void split2(float a, float b, uint32_t& hi, uint32_t& lo) {
    __nv_bfloat16 ha = __float2bfloat16(a), hb = __float2bfloat16(b);
    float ra = a - __bfloat162float(ha), rb = b - __bfloat162float(hb);
    __nv_bfloat16 la = __float2bfloat16(ra), lb = __float2bfloat16(rb);
    hi = (uint32_t)__bfloat16_as_ushort(ha) | ((uint32_t)__bfloat16_as_ushort(hb) << 16);
    lo = (uint32_t)__bfloat16_as_ushort(la) | ((uint32_t)__bfloat16_as_ushort(lb) << 16);
}

// ---------------------------------------------------------------------------
// fp32 -> (bf16 hi, bf16 lo) elementwise split
// ---------------------------------------------------------------------------
__global__ void split_e(const float* __restrict__ in, __nv_bfloat16* __restrict__ hi,
                        __nv_bfloat16* __restrict__ lo, int n4) {
    int i = blockIdx.x * blockDim.x + threadIdx.x;
    if (i >= n4) return;
    float4 v = ((const float4*)in)[i];
    __nv_bfloat16 h0 = __float2bfloat16(v.x), h1 = __float2bfloat16(v.y);
    __nv_bfloat16 h2 = __float2bfloat16(v.z), h3 = __float2bfloat16(v.w);
    __nv_bfloat16 l0 = __float2bfloat16(v.x - __bfloat162float(h0));
    __nv_bfloat16 l1 = __float2bfloat16(v.y - __bfloat162float(h1));
    __nv_bfloat16 l2 = __float2bfloat16(v.z - __bfloat162float(h2));
    __nv_bfloat16 l3 = __float2bfloat16(v.w - __bfloat162float(h3));
    ((__nv_bfloat162*)hi)[2*i]   = __nv_bfloat162(h0, h1);
    ((__nv_bfloat162*)hi)[2*i+1] = __nv_bfloat162(h2, h3);
    ((__nv_bfloat162*)lo)[2*i]   = __nv_bfloat162(l0, l1);
    ((__nv_bfloat162*)lo)[2*i+1] = __nv_bfloat162(l2, l3);
}

// fp32 W[K,N] -> transposed bf16 hi/lo [N,K]
__global__ void split_t(const float* __restrict__ in, __nv_bfloat16* __restrict__ hiT,
                        __nv_bfloat16* __restrict__ loT) {
    __shared__ float t[32][33];
    int tx = threadIdx.x, ty = threadIdx.y;
    int bn = blockIdx.x, bk = blockIdx.y;
    #pragma unroll
    for (int j = 0; j < 4; j++) {
        int k = bk * 32 + ty + j * 8;
        t[ty + j * 8][tx] = in[(size_t)k * D_MODEL + bn * 32 + tx];
    }
    __syncthreads();
    #pragma unroll
    for (int j = 0; j < 4; j++) {
        int n = bn * 32 + ty + j * 8;
        float v = t[tx][ty + j * 8];
        __nv_bfloat16 h = __float2bfloat16(v);
        __nv_bfloat16 l = __float2bfloat16(v - __bfloat162float(h));
        size_t off = (size_t)n * D_MODEL + bk * 32 + tx;
        hiT[off] = h;
        loT[off] = l;
    }
}

// ---------------------------------------------------------------------------
// HMMA GEMM (unchanged from round 3 — known good)
// ---------------------------------------------------------------------------
#define PADB   80
#define MATB   (128 * PADB)
#define STAGEB (4 * MATB)
#define NSTAGE 3
#define GEMM_SMEM (NSTAGE * STAGEB)

__global__ __launch_bounds__(256)
void gemm_hmma(const __nv_bfloat16* __restrict__ Ah, const __nv_bfloat16* __restrict__ Al,
               const __nv_bfloat16* __restrict__ Bh, const __nv_bfloat16* __restrict__ Bl,
               float* __restrict__ C) {
    extern __shared__ char smem[];
    const uint32_t sb = smem_u32(smem);
    const int tid  = threadIdx.x;
    const int wid  = tid >> 5;
    const int lane = tid & 31;
    const int tileN = blockIdx.x;
    const int tileM = blockIdx.y;

    const int m0w = (wid >> 2) * 64;
    const int n0w = (wid & 3) * 32;

    const __nv_bfloat16* gp[4] = {
        Ah + (size_t)tileM * 128 * D_MODEL,
        Al + (size_t)tileM * 128 * D_MODEL,
        Bh + (size_t)tileN * 128 * D_MODEL,
        Bl + (size_t)tileN * 128 * D_MODEL
    };

    auto load_stage = [&](int s, int k0) {
        uint32_t sbase = sb + s * STAGEB;
        #pragma unroll
        for (int mat = 0; mat < 4; mat++) {
            #pragma unroll
            for (int rep = 0; rep < 2; rep++) {
                int flat = rep * 256 + tid;
                int row = flat >> 2;
                int c   = flat & 3;
                cp16(sbase + mat * MATB + row * PADB + c * 16,
                     gp[mat] + (size_t)row * D_MODEL + k0 + c * 8);
            }
        }
        CP_COMMIT();
    };

    float acc[4][4][4];
    #pragma unroll
    for (int i = 0; i < 4; i++)
        #pragma unroll
        for (int j = 0; j < 4; j++)
            #pragma unroll
            for (int r = 0; r < 4; r++) acc[i][j][r] = 0.f;

    load_stage(0, 0);
    load_stage(1, 32);

    const int NCH = D_MODEL / 32;
    for (int c = 0; c < NCH; c++) {
        if (c + 2 < NCH) { CP_WAIT(1); } else { CP_WAIT(0); }
        __syncthreads();
        if (c + 2 < NCH) load_stage((c + 2) % NSTAGE, (c + 2) * 32);

        const uint32_t st = sb + (c % NSTAGE) * STAGEB;
        #pragma unroll
        for (int ks = 0; ks < 2; ks++) {
            uint32_t ah[4][4], al[4][4];
            const uint32_t arow = (lane & 15);
            const uint32_t akb  = (ks * 16 + (lane >> 4) * 8) * 2;
            #pragma unroll
            for (int mt = 0; mt < 4; mt++) {
                uint32_t ra = st + (m0w + mt * 16 + arow) * PADB + akb;
                LDSM_X4(ah[mt], ra);
                LDSM_X4(al[mt], ra + MATB);
            }
            const uint32_t brow = (lane & 7) + ((lane >> 4) & 1) * 8;
            const uint32_t bkb  = (ks * 16 + ((lane >> 3) & 1) * 8) * 2;
            #pragma unroll
            for (int np = 0; np < 2; np++) {
                uint32_t rb = st + 2 * MATB + (n0w + np * 16 + brow) * PADB + bkb;
                uint32_t bh4[4], bl4[4];
                LDSM_X4(bh4, rb);
                LDSM_X4(bl4, rb + MATB);
                #pragma unroll
                for (int half = 0; half < 2; half++) {
                    const int nt = np * 2 + half;
                    uint32_t* bh = bh4 + half * 2;
                    uint32_t* bl = bl4 + half * 2;
                    #pragma unroll
                    for (int mt = 0; mt < 4; mt++) {
                        MMA_BF16(acc[mt][nt], ah[mt], bh);
                        MMA_BF16(acc[mt][nt], ah[mt], bl);
                        MMA_BF16(acc[mt][nt], al[mt], bh);
                    }
                }
            }
        }
    }

    __syncthreads();
    float* stg = (float*)smem;
    {
        const int r  = lane >> 2;
        const int cq = (lane & 3) * 2;
        #pragma unroll
        for (int mt = 0; mt < 4; mt++) {
            #pragma unroll
            for (int nt = 0; nt < 4; nt++) {
                int row = m0w + mt * 16 + r;
                int col = n0w + nt * 8 + cq;
                *(float2*)&stg[row * 132 + col]       = make_float2(acc[mt][nt][0], acc[mt][nt][1]);
                *(float2*)&stg[(row + 8) * 132 + col] = make_float2(acc[mt][nt][2], acc[mt][nt][3]);
            }
        }
    }
    __syncthreads();
    float* crow = C + (size_t)tileM * 128 * D_MODEL + tileN * 128;
    #pragma unroll
    for (int i = 0; i < 16; i++) {
        int flat = (i << 8) + tid;
        int r = flat >> 5;
        int c4 = (flat & 31) << 2;
        *(float4*)(crow + (size_t)r * D_MODEL + c4) = *(const float4*)&stg[r * 132 + c4];
    }
}

// ---------------------------------------------------------------------------
// RoPE + split: q,k roped (q also scaled by rsqrt(128)*log2e), v passthrough;
// all emitted as bf16 hi/lo pairs.
// ---------------------------------------------------------------------------
__global__ void rope_split(const float* __restrict__ q, const float* __restrict__ k,
                           const float* __restrict__ v,
                           __nv_bfloat16* __restrict__ qh, __nv_bfloat16* __restrict__ ql,
                           __nv_bfloat16* __restrict__ kh, __nv_bfloat16* __restrict__ kl,
                           __nv_bfloat16* __restrict__ vh, __nv_bfloat16* __restrict__ vl) {
    const int total = MROWS * NHEAD * (HD / 2);
    int idx = blockIdx.x * blockDim.x + threadIdx.x;
    if (idx >= total) return;
    int u   = idx & 63;
    int h   = (idx >> 6) & 15;
    int row = idx >> 10;
    int s   = row & (SEQ - 1);

    float inv_freq = exp2f(-13.287712379549449f * ((float)(2 * u) * (1.0f / 128.0f)));
    float ang = (float)s * inv_freq;
    float sn, cs;
    sincosf(ang, &sn, &cs);

    const float SCF = 0.08838834764831845f * 1.4426950408889634f;

    size_t off = (size_t)row * D_MODEL + h * HD + 2 * u;
    float2 qv = *(const float2*)(q + off);
    float2 kv = *(const float2*)(k + off);
    float2 vv = *(const float2*)(v + off);

    float q0 = (qv.x * cs - qv.y * sn) * SCF;
    float q1 = (qv.x * sn + qv.y * cs) * SCF;
    float k0 = kv.x * cs - kv.y * sn;
    float k1 = kv.x * sn + kv.y * cs;

    uint32_t hi, lo;
    split2(q0, q1, hi, lo);
    *(uint32_t*)(qh + off) = hi;  *(uint32_t*)(ql + off) = lo;
    split2(k0, k1, hi, lo);
    *(uint32_t*)(kh + off) = hi;  *(uint32_t*)(kl + off) = lo;
    split2(vv.x, vv.y, hi, lo);
    *(uint32_t*)(vh + off) = hi;  *(uint32_t*)(vl + off) = lo;
}

// ---------------------------------------------------------------------------
// HMMA flash attention: 128 q-rows/CTA, 8 warps (16 rows each), K/V chunks of
// 64 double-buffered via cp.async. Split-bf16 QK^T and PV, fp32 softmax in
// exp2 domain (scale*log2e pre-folded into Q). Emits O as bf16 hi/lo.
// ---------------------------------------------------------------------------
#define FL_STRIDE 272                   // 136 bf16 per row (128 data + 8 pad)
#define FL_MAT    (64 * FL_STRIDE)      // 17408
#define FL_STAGE  (4 * FL_MAT)          // 69632 (Kh,Kl,Vh,Vl)
#define FL_SMEM   (2 * FL_STAGE)        // 139264
#define FL_QMAT   (128 * FL_STRIDE)     // 34816

__global__ __launch_bounds__(256, 1)
void flash_hmma(const __nv_bfloat16* __restrict__ qh, const __nv_bfloat16* __restrict__ ql,
                const __nv_bfloat16* __restrict__ kh, const __nv_bfloat16* __restrict__ kl,
                const __nv_bfloat16* __restrict__ vh, const __nv_bfloat16* __restrict__ vl,
                __nv_bfloat16* __restrict__ oh, __nv_bfloat16* __restrict__ ol) {
    extern __shared__ char smem[];
    const uint32_t sb = smem_u32(smem);
    const int tid  = threadIdx.x;
    const int w    = tid >> 5;
    const int lane = tid & 31;
    const int qt = blockIdx.x;
    const int bh = blockIdx.y;
    const int b  = bh >> 4;
    const int h  = bh & 15;

    const size_t gbase = (size_t)b * SEQ * D_MODEL + (size_t)h * HD;
    const int q0 = qt * 128;

    // --- prologue: Q into stage-1 region + chunk 0 into stage 0 (one group) ---
    const uint32_t qsm = sb + FL_STAGE;
    {
        const __nv_bfloat16* gq[2] = { qh + gbase + (size_t)q0 * D_MODEL,
                                       ql + gbase + (size_t)q0 * D_MODEL };
        #pragma unroll
        for (int m = 0; m < 2; m++)
            #pragma unroll
            for (int i = 0; i < 8; i++) {
                int idx = i * 256 + tid;
                int r = idx >> 4, c = idx & 15;
                cp16(qsm + m * FL_QMAT + r * FL_STRIDE + c * 16,
                     gq[m] + (size_t)r * D_MODEL + c * 8);
            }
    }
    auto load_chunk = [&](int stage, int kt) {
        uint32_t st = sb + stage * FL_STAGE;
        const __nv_bfloat16* gp[4] = {
            kh + gbase + (size_t)(kt * 64) * D_MODEL,
            kl + gbase + (size_t)(kt * 64) * D_MODEL,
            vh + gbase + (size_t)(kt * 64) * D_MODEL,
            vl + gbase + (size_t)(kt * 64) * D_MODEL };
        #pragma unroll
        for (int m = 0; m < 4; m++)
            #pragma unroll
            for (int i = 0; i < 4; i++) {
                int idx = i * 256 + tid;
                int r = idx >> 4, c = idx & 15;
                cp16(st + m * FL_MAT + r * FL_STRIDE + c * 16,
                     gp[m] + (size_t)r * D_MODEL + c * 8);
            }
        CP_COMMIT();
    };
    load_chunk(0, 0);      // group G0 = Q + chunk0
    CP_WAIT(0);
    __syncthreads();

    // --- Q fragments (held in registers for the whole kernel) ---
    uint32_t fqh[8][4], fql[8][4];
    #pragma unroll
    for (int kk = 0; kk < 8; kk++) {
        uint32_t ra = qsm + (w * 16 + (lane & 15)) * FL_STRIDE + (kk * 16 + (lane >> 4) * 8) * 2;
        LDSM_X4(fqh[kk], ra);
        LDSM_X4(fql[kk], ra + FL_QMAT);
    }
    __syncthreads();                 // all warps done with Q smem
    const int C = 2 * qt + 2;        // causal chunk count
    if (1 < C) load_chunk(1, 1);     // overwrites Q region

    float o[16][4];
    #pragma unroll
    for (int nt = 0; nt < 16; nt++)
        #pragma unroll
        for (int r = 0; r < 4; r++) o[nt][r] = 0.f;
    float m0 = -1e30f, m1 = -1e30f, l0 = 0.f, l1 = 0.f;

    const int r0 = q0 + w * 16 + (lane >> 2);
    const int r1 = r0 + 8;

    for (int c = 0; c < C; c++) {
        if (c + 1 < C) { CP_WAIT(1); } else { CP_WAIT(0); }
        __syncthreads();
        const uint32_t st = sb + (c & 1) * FL_STAGE;

        const bool skip = (64 * c > q0 + w * 16 + 15);
        if (!skip) {
            // ---- S = Q K^T (split bf16, fp32 acc) ----
            float s8[8][4];
            #pragma unroll
            for (int t = 0; t < 8; t++)
                #pragma unroll
                for (int r = 0; r < 4; r++) s8[t][r] = 0.f;

            #pragma unroll
            for (int kk = 0; kk < 8; kk++) {
                #pragma unroll
                for (int np = 0; np < 4; np++) {
                    uint32_t rb = st + (np * 16 + (lane & 7) + ((lane >> 4) & 1) * 8) * FL_STRIDE
                                     + (((lane >> 3) & 1) * 8 + kk * 16) * 2;
                    uint32_t bh4[4], bl4[4];
                    LDSM_X4(bh4, rb);
                    LDSM_X4(bl4, rb + FL_MAT);
                    MMA_BF16(s8[np*2],   fqh[kk], bh4);
                    MMA_BF16(s8[np*2],   fqh[kk], bl4);
                    MMA_BF16(s8[np*2],   fql[kk], bh4);
                    MMA_BF16(s8[np*2+1], fqh[kk], bh4 + 2);
                    MMA_BF16(s8[np*2+1], fqh[kk], bl4 + 2);
                    MMA_BF16(s8[np*2+1], fql[kk], bh4 + 2);
                }
            }

            // ---- causal mask (diagonal chunks only) ----
            if (64 * c + 63 > q0 + w * 16) {
                #pragma unroll
                for (int t = 0; t < 8; t++) {
                    int col = c * 64 + t * 8 + (lane & 3) * 2;
                    if (col     > r0) s8[t][0] = -1e30f;
                    if (col + 1 > r0) s8[t][1] = -1e30f;
                    if (col     > r1) s8[t][2] = -1e30f;
                    if (col + 1 > r1) s8[t][3] = -1e30f;
                }
            }

            // ---- online softmax (log2 domain) ----
            float mx0 = -1e30f, mx1 = -1e30f;
            #pragma unroll
            for (int t = 0; t < 8; t++) {
                mx0 = fmaxf(mx0, fmaxf(s8[t][0], s8[t][1]));
                mx1 = fmaxf(mx1, fmaxf(s8[t][2], s8[t][3]));
            }
            mx0 = fmaxf(mx0, __shfl_xor_sync(0xffffffffu, mx0, 1));
            mx0 = fmaxf(mx0, __shfl_xor_sync(0xffffffffu, mx0, 2));
            mx1 = fmaxf(mx1, __shfl_xor_sync(0xffffffffu, mx1, 1));
            mx1 = fmaxf(mx1, __shfl_xor_sync(0xffffffffu, mx1, 2));
            float mn0 = fmaxf(m0, mx0), mn1 = fmaxf(m1, mx1);
            float a0 = exp2f(m0 - mn0), a1 = exp2f(m1 - mn1);
            m0 = mn0;  m1 = mn1;
            float sum0 = 0.f, sum1 = 0.f;
            #pragma unroll
            for (int t = 0; t < 8; t++) {
                s8[t][0] = exp2f(s8[t][0] - mn0);
                s8[t][1] = exp2f(s8[t][1] - mn0);
                s8[t][2] = exp2f(s8[t][2] - mn1);
                s8[t][3] = exp2f(s8[t][3] - mn1);
                sum0 += s8[t][0] + s8[t][1];
                sum1 += s8[t][2] + s8[t][3];
            }
            l0 = l0 * a0 + sum0;
            l1 = l1 * a1 + sum1;
            #pragma unroll
            for (int nt = 0; nt < 16; nt++) {
                o[nt][0] *= a0;  o[nt][1] *= a0;
                o[nt][2] *= a1;  o[nt][3] *= a1;
            }

            // ---- O += P V (split bf16) ----
            #pragma unroll
            for (int kk2 = 0; kk2 < 4; kk2++) {
                uint32_t pah[4], pal[4];
                split2(s8[2*kk2][0],   s8[2*kk2][1],   pah[0], pal[0]);
                split2(s8[2*kk2][2],   s8[2*kk2][3],   pah[1], pal[1]);
                split2(s8[2*kk2+1][0], s8[2*kk2+1][1], pah[2], pal[2]);
                split2(s8[2*kk2+1][2], s8[2*kk2+1][3], pah[3], pal[3]);
                #pragma unroll
                for (int np = 0; np < 8; np++) {
                    uint32_t rv = st + 2 * FL_MAT
                                + (kk2 * 16 + (lane & 15)) * FL_STRIDE
                                + (np * 16 + (lane >> 4) * 8) * 2;
                    uint32_t vh4[4], vl4[4];
                    LDSM_T_X4(vh4, rv);
                    LDSM_T_X4(vl4, rv + FL_MAT);
                    MMA_BF16(o[np*2],   pah, vh4);
                    MMA_BF16(o[np*2],   pah, vl4);
                    MMA_BF16(o[np*2],   pal, vh4);
                    MMA_BF16(o[np*2+1], pah, vh4 + 2);
                    MMA_BF16(o[np*2+1], pah, vl4 + 2);
                    MMA_BF16(o[np*2+1], pal, vh4 + 2);
                }
            }
        }
        __syncthreads();
        if (c + 2 < C) load_chunk(c & 1, c + 2);
    }

    // ---- epilogue: normalize, split to bf16 hi/lo, store ----
    l0 += __shfl_xor_sync(0xffffffffu, l0, 1);
    l0 += __shfl_xor_sync(0xffffffffu, l0, 2);
    l1 += __shfl_xor_sync(0xffffffffu, l1, 1);
    l1 += __shfl_xor_sync(0xffffffffu, l1, 2);
    float inv0 = 1.0f / l0, inv1 = 1.0f / l1;

    const size_t orow0 = (size_t)(b * SEQ + r0) * D_MODEL + h * HD;
    const size_t orow1 = (size_t)(b * SEQ + r1) * D_MODEL + h * HD;
    #pragma unroll
    for (int nt = 0; nt < 16; nt++) {
        int col = nt * 8 + (lane & 3) * 2;
        uint32_t hi, lo;
        split2(o[nt][0] * inv0, o[nt][1] * inv0, hi, lo);
        *(uint32_t*)(oh + orow0 + col) = hi;
        *(uint32_t*)(ol + orow0 + col) = lo;
        split2(o[nt][2] * inv1, o[nt][3] * inv1, hi, lo);
        *(uint32_t*)(oh + orow1 + col) = hi;
        *(uint32_t*)(ol + orow1 + col) = lo;
    }
}

// ---------------------------------------------------------------------------
extern "C" void kernel_launch(void* const* d_in, const int* in_sizes, int n_in,
                              void* d_out, int out_size) {
    const float* x  = (const float*)d_in[0];
    const float* Wq = (const float*)d_in[1];
    const float* Wk = (const float*)d_in[2];
    const float* Wv = (const float*)d_in[3];
    const float* Wo = (const float*)d_in[4];
    float* out = (float*)d_out;

    float *qp, *kp, *vp;
    cudaGetSymbolAddress((void**)&qp, g_q);
    cudaGetSymbolAddress((void**)&kp, g_k);
    cudaGetSymbolAddress((void**)&vp, g_v);

    __nv_bfloat16 *xh, *xl, *ah, *al;
    cudaGetSymbolAddress((void**)&xh, g_xh);
    cudaGetSymbolAddress((void**)&xl, g_xl);
    cudaGetSymbolAddress((void**)&ah, g_ah);
    cudaGetSymbolAddress((void**)&al, g_al);

    __nv_bfloat16 *qhp, *qlp, *khp, *klp, *vhp, *vlp;
    cudaGetSymbolAddress((void**)&qhp, g_qh);
    cudaGetSymbolAddress((void**)&qlp, g_ql);
    cudaGetSymbolAddress((void**)&khp, g_kh);
    cudaGetSymbolAddress((void**)&klp, g_kl);
    cudaGetSymbolAddress((void**)&vhp, g_vh);
    cudaGetSymbolAddress((void**)&vlp, g_vl);

    __nv_bfloat16 *wqh, *wql, *wkh, *wkl, *wvh, *wvl, *woh, *wol;
    cudaGetSymbolAddress((void**)&wqh, g_wqh);
    cudaGetSymbolAddress((void**)&wql, g_wql);
    cudaGetSymbolAddress((void**)&wkh, g_wkh);
    cudaGetSymbolAddress((void**)&wkl, g_wkl);
    cudaGetSymbolAddress((void**)&wvh, g_wvh);
    cudaGetSymbolAddress((void**)&wvl, g_wvl);
    cudaGetSymbolAddress((void**)&woh, g_woh);
    cudaGetSymbolAddress((void**)&wol, g_wol);

    cudaFuncSetAttribute(gemm_hmma, cudaFuncAttributeMaxDynamicSharedMemorySize, GEMM_SMEM);
    cudaFuncSetAttribute(flash_hmma, cudaFuncAttributeMaxDynamicSharedMemorySize, FL_SMEM);

    // split inputs
    {
        int n4 = MROWS * D_MODEL / 4;
        split_e<<<(n4 + 255) / 256, 256>>>(x, xh, xl, n4);
        dim3 tb(32, 8), tg(D_MODEL / 32, D_MODEL / 32);
        split_t<<<tg, tb>>>(Wq, wqh, wql);
        split_t<<<tg, tb>>>(Wk, wkh, wkl);
        split_t<<<tg, tb>>>(Wv, wvh, wvl);
        split_t<<<tg, tb>>>(Wo, woh, wol);
    }

    dim3 ggrid(D_MODEL / 128, MROWS / 128);   // (16, 32)
    gemm_hmma<<<ggrid, 256, GEMM_SMEM>>>(xh, xl, wqh, wql, qp);
    gemm_hmma<<<ggrid, 256, GEMM_SMEM>>>(xh, xl, wkh, wkl, kp);
    gemm_hmma<<<ggrid, 256, GEMM_SMEM>>>(xh, xl, wvh, wvl, vp);

    {
        int total = MROWS * NHEAD * (HD / 2);
        rope_split<<<(total + 255) / 256, 256>>>(qp, kp, vp, qhp, qlp, khp, klp, vhp, vlp);
    }

    {
        dim3 fgrid(SEQ / 128, BATCH * NHEAD);  // (16, 32)
        flash_hmma<<<fgrid, 256, FL_SMEM>>>(qhp, qlp, khp, klp, vhp, vlp, ah, al);
    }

    gemm_hmma<<<ggrid, 256, GEMM_SMEM>>>(ah, al, woh, wol, out);
}

// round 5
// speedup vs baseline: 2.7894x; 1.0869x over previous
#include <cuda_runtime.h>
#include <cuda_bf16.h>
#include <cstdint>
#include <math.h>

#define D_MODEL 2048
#define SEQ     2048
#define BATCH   2
#define NHEAD   16
#define HD      128
#define MROWS   (BATCH*SEQ)   // 4096

// ---------------------------------------------------------------------------
// Scratch (__device__ globals: allocation-free rule)
// ---------------------------------------------------------------------------
__device__ float g_q[MROWS * D_MODEL];
__device__ float g_k[MROWS * D_MODEL];
__device__ float g_v[MROWS * D_MODEL];

__device__ __nv_bfloat16 g_xh[MROWS * D_MODEL];
__device__ __nv_bfloat16 g_xl[MROWS * D_MODEL];
__device__ __nv_bfloat16 g_ah[MROWS * D_MODEL];
__device__ __nv_bfloat16 g_al[MROWS * D_MODEL];

__device__ __nv_bfloat16 g_qh[MROWS * D_MODEL];
__device__ __nv_bfloat16 g_ql[MROWS * D_MODEL];
__device__ __nv_bfloat16 g_kh[MROWS * D_MODEL];
__device__ __nv_bfloat16 g_kl[MROWS * D_MODEL];
__device__ __nv_bfloat16 g_vh[MROWS * D_MODEL];
__device__ __nv_bfloat16 g_vl[MROWS * D_MODEL];

__device__ __nv_bfloat16 g_wqh[D_MODEL * D_MODEL];
__device__ __nv_bfloat16 g_wql[D_MODEL * D_MODEL];
__device__ __nv_bfloat16 g_wkh[D_MODEL * D_MODEL];
__device__ __nv_bfloat16 g_wkl[D_MODEL * D_MODEL];
__device__ __nv_bfloat16 g_wvh[D_MODEL * D_MODEL];
__device__ __nv_bfloat16 g_wvl[D_MODEL * D_MODEL];
__device__ __nv_bfloat16 g_woh[D_MODEL * D_MODEL];
__device__ __nv_bfloat16 g_wol[D_MODEL * D_MODEL];

// ---------------------------------------------------------------------------
// PTX helpers (plain sm_103: no tcgen05)
// ---------------------------------------------------------------------------
__device__ __forceinline__ uint32_t smem_u32(const void* p) {
    uint32_t a;
    asm("{ .reg .u64 t; cvta.to.shared.u64 t, %1; cvt.u32.u64 %0, t; }" : "=r"(a) : "l"(p));
    return a;
}
__device__ __forceinline__ void cp16(uint32_t dst, const void* src) {
    asm volatile("cp.async.cg.shared.global [%0], [%1], 16;" :: "r"(dst), "l"(src) : "memory");
}
#define CP_COMMIT() asm volatile("cp.async.commit_group;" ::: "memory")
#define CP_WAIT(n)  asm volatile("cp.async.wait_group %0;" :: "n"(n) : "memory")

#define LDSM_X4(r, addr) \
    asm volatile("ldmatrix.sync.aligned.m8n8.x4.shared.b16 {%0,%1,%2,%3}, [%4];" \
        : "=r"((r)[0]), "=r"((r)[1]), "=r"((r)[2]), "=r"((r)[3]) : "r"(addr))
#define LDSM_T_X4(r, addr) \
    asm volatile("ldmatrix.sync.aligned.m8n8.x4.trans.shared.b16 {%0,%1,%2,%3}, [%4];" \
        : "=r"((r)[0]), "=r"((r)[1]), "=r"((r)[2]), "=r"((r)[3]) : "r"(addr))

#define MMA_BF16(c, a, b) \
    asm volatile("mma.sync.aligned.m16n8k16.row.col.f32.bf16.bf16.f32 " \
        "{%0,%1,%2,%3}, {%4,%5,%6,%7}, {%8,%9}, {%0,%1,%2,%3};" \
        : "+f"((c)[0]), "+f"((c)[1]), "+f"((c)[2]), "+f"((c)[3]) \
        : "r"((a)[0]), "r"((a)[1]), "r"((a)[2]), "r"((a)[3]), "r"((b)[0]), "r"((b)[1]))

__device__ __forceinline__ void split2(float a, float b, uint32_t& hi, uint32_t& lo) {
    __nv_bfloat16 ha = __float2bfloat16(a), hb = __float2bfloat16(b);
    float ra = a - __bfloat162float(ha), rb = b - __bfloat162float(hb);
    __nv_bfloat16 la = __float2bfloat16(ra), lb = __float2bfloat16(rb);
    hi = (uint32_t)__bfloat16_as_ushort(ha) | ((uint32_t)__bfloat16_as_ushort(hb) << 16);
    lo = (uint32_t)__bfloat16_as_ushort(la) | ((uint32_t)__bfloat16_as_ushort(lb) << 16);
}

// ---------------------------------------------------------------------------
// fp32 -> (bf16 hi, bf16 lo) elementwise split
// ---------------------------------------------------------------------------
__global__ void split_e(const float* __restrict__ in, __nv_bfloat16* __restrict__ hi,
                        __nv_bfloat16* __restrict__ lo, int n4) {
    int i = blockIdx.x * blockDim.x + threadIdx.x;
    if (i >= n4) return;
    float4 v = ((const float4*)in)[i];
    __nv_bfloat16 h0 = __float2bfloat16(v.x), h1 = __float2bfloat16(v.y);
    __nv_bfloat16 h2 = __float2bfloat16(v.z), h3 = __float2bfloat16(v.w);
    __nv_bfloat16 l0 = __float2bfloat16(v.x - __bfloat162float(h0));
    __nv_bfloat16 l1 = __float2bfloat16(v.y - __bfloat162float(h1));
    __nv_bfloat16 l2 = __float2bfloat16(v.z - __bfloat162float(h2));
    __nv_bfloat16 l3 = __float2bfloat16(v.w - __bfloat162float(h3));
    ((__nv_bfloat162*)hi)[2*i]   = __nv_bfloat162(h0, h1);
    ((__nv_bfloat162*)hi)[2*i+1] = __nv_bfloat162(h2, h3);
    ((__nv_bfloat162*)lo)[2*i]   = __nv_bfloat162(l0, l1);
    ((__nv_bfloat162*)lo)[2*i+1] = __nv_bfloat162(l2, l3);
}

// fp32 W[K,N] -> transposed bf16 hi/lo [N,K]
__global__ void split_t(const float* __restrict__ in, __nv_bfloat16* __restrict__ hiT,
                        __nv_bfloat16* __restrict__ loT) {
    __shared__ float t[32][33];
    int tx = threadIdx.x, ty = threadIdx.y;
    int bn = blockIdx.x, bk = blockIdx.y;
    #pragma unroll
    for (int j = 0; j < 4; j++) {
        int k = bk * 32 + ty + j * 8;
        t[ty + j * 8][tx] = in[(size_t)k * D_MODEL + bn * 32 + tx];
    }
    __syncthreads();
    #pragma unroll
    for (int j = 0; j < 4; j++) {
        int n = bn * 32 + ty + j * 8;
        float v = t[tx][ty + j * 8];
        __nv_bfloat16 h = __float2bfloat16(v);
        __nv_bfloat16 l = __float2bfloat16(v - __bfloat162float(h));
        size_t off = (size_t)n * D_MODEL + bk * 32 + tx;
        hiT[off] = h;
        loT[off] = l;
    }
}

// ---------------------------------------------------------------------------
// HMMA GEMM: C[4096,2048] = A[4096,2048] @ W (W transposed [N,K], hi/lo).
// CTA tile 128(M) x 256(N), BK=32, 3-stage cp.async, 8 warps (2x4),
// warp tile 64x64 -> 6.0 MMA per ldmatrix.x4.
// ---------------------------------------------------------------------------
#define PADB   80                  // 40 bf16 per row (32 data + 8 pad)
#define AMAT   (128 * PADB)        // 10240
#define BMAT   (256 * PADB)        // 20480
#define BOFF   (2 * AMAT)          // 20480
#define STAGEB (2 * AMAT + 2 * BMAT)  // 61440
#define NSTAGE 3
#define GEMM_SMEM (NSTAGE * STAGEB)   // 184320

__global__ __launch_bounds__(256)
void gemm_hmma(const __nv_bfloat16* __restrict__ Ah, const __nv_bfloat16* __restrict__ Al,
               const __nv_bfloat16* __restrict__ Bh, const __nv_bfloat16* __restrict__ Bl,
               float* __restrict__ C) {
    extern __shared__ char smem[];
    const uint32_t sb = smem_u32(smem);
    const int tid  = threadIdx.x;
    const int wid  = tid >> 5;
    const int lane = tid & 31;
    const int tileN = blockIdx.x;   // 256-wide
    const int tileM = blockIdx.y;   // 128-tall

    const int m0w = (wid >> 2) * 64;   // 0 or 64
    const int n0w = (wid & 3) * 64;    // 0,64,128,192

    const __nv_bfloat16* gpA[2] = {
        Ah + (size_t)tileM * 128 * D_MODEL,
        Al + (size_t)tileM * 128 * D_MODEL };
    const __nv_bfloat16* gpB[2] = {
        Bh + (size_t)tileN * 256 * D_MODEL,
        Bl + (size_t)tileN * 256 * D_MODEL };

    auto load_stage = [&](int s, int k0) {
        uint32_t sbase = sb + s * STAGEB;
        #pragma unroll
        for (int m = 0; m < 2; m++) {
            #pragma unroll
            for (int rep = 0; rep < 2; rep++) {           // A: 128 rows x 4 chunks
                int flat = rep * 256 + tid;
                int row = flat >> 2, ch = flat & 3;
                cp16(sbase + m * AMAT + row * PADB + ch * 16,
                     gpA[m] + (size_t)row * D_MODEL + k0 + ch * 8);
            }
        }
        #pragma unroll
        for (int m = 0; m < 2; m++) {
            #pragma unroll
            for (int rep = 0; rep < 4; rep++) {           // B: 256 rows x 4 chunks
                int flat = rep * 256 + tid;
                int row = flat >> 2, ch = flat & 3;
                cp16(sbase + BOFF + m * BMAT + row * PADB + ch * 16,
                     gpB[m] + (size_t)row * D_MODEL + k0 + ch * 8);
            }
        }
        CP_COMMIT();
    };

    float acc[4][8][4];
    #pragma unroll
    for (int i = 0; i < 4; i++)
        #pragma unroll
        for (int j = 0; j < 8; j++)
            #pragma unroll
            for (int r = 0; r < 4; r++) acc[i][j][r] = 0.f;

    load_stage(0, 0);
    load_stage(1, 32);

    const int NCH = D_MODEL / 32;   // 64
    for (int c = 0; c < NCH; c++) {
        if (c + 2 < NCH) { CP_WAIT(1); } else { CP_WAIT(0); }
        __syncthreads();
        if (c + 2 < NCH) load_stage((c + 2) % NSTAGE, (c + 2) * 32);

        const uint32_t st = sb + (c % NSTAGE) * STAGEB;
        #pragma unroll
        for (int ks = 0; ks < 2; ks++) {
            uint32_t ah[4][4], al[4][4];
            const uint32_t arow = (lane & 15);
            const uint32_t akb  = (ks * 16 + (lane >> 4) * 8) * 2;
            #pragma unroll
            for (int mt = 0; mt < 4; mt++) {
                uint32_t ra = st + (m0w + mt * 16 + arow) * PADB + akb;
                LDSM_X4(ah[mt], ra);
                LDSM_X4(al[mt], ra + AMAT);
            }
            const uint32_t brow = (lane & 7) + ((lane >> 4) & 1) * 8;
            const uint32_t bkb  = (ks * 16 + ((lane >> 3) & 1) * 8) * 2;
            #pragma unroll
            for (int np = 0; np < 4; np++) {
                uint32_t rb = st + BOFF + (n0w + np * 16 + brow) * PADB + bkb;
                uint32_t bh4[4], bl4[4];
                LDSM_X4(bh4, rb);
                LDSM_X4(bl4, rb + BMAT);
                #pragma unroll
                for (int half = 0; half < 2; half++) {
                    const int nt = np * 2 + half;
                    uint32_t* bh = bh4 + half * 2;
                    uint32_t* bl = bl4 + half * 2;
                    #pragma unroll
                    for (int mt = 0; mt < 4; mt++) {
                        MMA_BF16(acc[mt][nt], ah[mt], bh);
                        MMA_BF16(acc[mt][nt], ah[mt], bl);
                        MMA_BF16(acc[mt][nt], al[mt], bh);
                    }
                }
            }
        }
    }

    // epilogue: direct float2 global stores
    float* cbase = C + (size_t)tileM * 128 * D_MODEL + tileN * 256;
    const int rq = lane >> 2;
    const int cq = (lane & 3) * 2;
    #pragma unroll
    for (int mt = 0; mt < 4; mt++) {
        #pragma unroll
        for (int nt = 0; nt < 8; nt++) {
            int row = m0w + mt * 16 + rq;
            int col = n0w + nt * 8 + cq;
            *(float2*)(cbase + (size_t)row * D_MODEL + col) =
                make_float2(acc[mt][nt][0], acc[mt][nt][1]);
            *(float2*)(cbase + (size_t)(row + 8) * D_MODEL + col) =
                make_float2(acc[mt][nt][2], acc[mt][nt][3]);
        }
    }
}

// ---------------------------------------------------------------------------
// RoPE + split: q,k roped (q also scaled by rsqrt(128)*log2e), v passthrough;
// all emitted as bf16 hi/lo pairs.
// ---------------------------------------------------------------------------
__global__ void rope_split(const float* __restrict__ q, const float* __restrict__ k,
                           const float* __restrict__ v,
                           __nv_bfloat16* __restrict__ qh, __nv_bfloat16* __restrict__ ql,
                           __nv_bfloat16* __restrict__ kh, __nv_bfloat16* __restrict__ kl,
                           __nv_bfloat16* __restrict__ vh, __nv_bfloat16* __restrict__ vl) {
    const int total = MROWS * NHEAD * (HD / 2);
    int idx = blockIdx.x * blockDim.x + threadIdx.x;
    if (idx >= total) return;
    int u   = idx & 63;
    int h   = (idx >> 6) & 15;
    int row = idx >> 10;
    int s   = row & (SEQ - 1);

    float inv_freq = exp2f(-13.287712379549449f * ((float)(2 * u) * (1.0f / 128.0f)));
    float ang = (float)s * inv_freq;
    float sn, cs;
    sincosf(ang, &sn, &cs);

    const float SCF = 0.08838834764831845f * 1.4426950408889634f;

    size_t off = (size_t)row * D_MODEL + h * HD + 2 * u;
    float2 qv = *(const float2*)(q + off);
    float2 kv = *(const float2*)(k + off);
    float2 vv = *(const float2*)(v + off);

    float q0 = (qv.x * cs - qv.y * sn) * SCF;
    float q1 = (qv.x * sn + qv.y * cs) * SCF;
    float k0 = kv.x * cs - kv.y * sn;
    float k1 = kv.x * sn + kv.y * cs;

    uint32_t hi, lo;
    split2(q0, q1, hi, lo);
    *(uint32_t*)(qh + off) = hi;  *(uint32_t*)(ql + off) = lo;
    split2(k0, k1, hi, lo);
    *(uint32_t*)(kh + off) = hi;  *(uint32_t*)(kl + off) = lo;
    split2(vv.x, vv.y, hi, lo);
    *(uint32_t*)(vh + off) = hi;  *(uint32_t*)(vl + off) = lo;
}

// ---------------------------------------------------------------------------
// HMMA flash attention (unchanged from round 4 — known good)
// ---------------------------------------------------------------------------
#define FL_STRIDE 272
#define FL_MAT    (64 * FL_STRIDE)
#define FL_STAGE  (4 * FL_MAT)
#define FL_SMEM   (2 * FL_STAGE)
#define FL_QMAT   (128 * FL_STRIDE)

__global__ __launch_bounds__(256, 1)
void flash_hmma(const __nv_bfloat16* __restrict__ qh, const __nv_bfloat16* __restrict__ ql,
                const __nv_bfloat16* __restrict__ kh, const __nv_bfloat16* __restrict__ kl,
                const __nv_bfloat16* __restrict__ vh, const __nv_bfloat16* __restrict__ vl,
                __nv_bfloat16* __restrict__ oh, __nv_bfloat16* __restrict__ ol) {
    extern __shared__ char smem[];
    const uint32_t sb = smem_u32(smem);
    const int tid  = threadIdx.x;
    const int w    = tid >> 5;
    const int lane = tid & 31;
    const int qt = blockIdx.x;
    const int bh = blockIdx.y;
    const int b  = bh >> 4;
    const int h  = bh & 15;

    const size_t gbase = (size_t)b * SEQ * D_MODEL + (size_t)h * HD;
    const int q0 = qt * 128;

    const uint32_t qsm = sb + FL_STAGE;
    {
        const __nv_bfloat16* gq[2] = { qh + gbase + (size_t)q0 * D_MODEL,
                                       ql + gbase + (size_t)q0 * D_MODEL };
        #pragma unroll
        for (int m = 0; m < 2; m++)
            #pragma unroll
            for (int i = 0; i < 8; i++) {
                int idx = i * 256 + tid;
                int r = idx >> 4, c = idx & 15;
                cp16(qsm + m * FL_QMAT + r * FL_STRIDE + c * 16,
                     gq[m] + (size_t)r * D_MODEL + c * 8);
            }
    }
    auto load_chunk = [&](int stage, int kt) {
        uint32_t st = sb + stage * FL_STAGE;
        const __nv_bfloat16* gp[4] = {
            kh + gbase + (size_t)(kt * 64) * D_MODEL,
            kl + gbase + (size_t)(kt * 64) * D_MODEL,
            vh + gbase + (size_t)(kt * 64) * D_MODEL,
            vl + gbase + (size_t)(kt * 64) * D_MODEL };
        #pragma unroll
        for (int m = 0; m < 4; m++)
            #pragma unroll
            for (int i = 0; i < 4; i++) {
                int idx = i * 256 + tid;
                int r = idx >> 4, c = idx & 15;
                cp16(st + m * FL_MAT + r * FL_STRIDE + c * 16,
                     gp[m] + (size_t)r * D_MODEL + c * 8);
            }
        CP_COMMIT();
    };
    load_chunk(0, 0);
    CP_WAIT(0);
    __syncthreads();

    uint32_t fqh[8][4], fql[8][4];
    #pragma unroll
    for (int kk = 0; kk < 8; kk++) {
        uint32_t ra = qsm + (w * 16 + (lane & 15)) * FL_STRIDE + (kk * 16 + (lane >> 4) * 8) * 2;
        LDSM_X4(fqh[kk], ra);
        LDSM_X4(fql[kk], ra + FL_QMAT);
    }
    __syncthreads();
    const int C = 2 * qt + 2;
    if (1 < C) load_chunk(1, 1);

    float o[16][4];
    #pragma unroll
    for (int nt = 0; nt < 16; nt++)
        #pragma unroll
        for (int r = 0; r < 4; r++) o[nt][r] = 0.f;
    float m0 = -1e30f, m1 = -1e30f, l0 = 0.f, l1 = 0.f;

    const int r0 = q0 + w * 16 + (lane >> 2);
    const int r1 = r0 + 8;

    for (int c = 0; c < C; c++) {
        if (c + 1 < C) { CP_WAIT(1); } else { CP_WAIT(0); }
        __syncthreads();
        const uint32_t st = sb + (c & 1) * FL_STAGE;

        const bool skip = (64 * c > q0 + w * 16 + 15);
        if (!skip) {
            float s8[8][4];
            #pragma unroll
            for (int t = 0; t < 8; t++)
                #pragma unroll
                for (int r = 0; r < 4; r++) s8[t][r] = 0.f;

            #pragma unroll
            for (int kk = 0; kk < 8; kk++) {
                #pragma unroll
                for (int np = 0; np < 4; np++) {
                    uint32_t rb = st + (np * 16 + (lane & 7) + ((lane >> 4) & 1) * 8) * FL_STRIDE
                                     + (((lane >> 3) & 1) * 8 + kk * 16) * 2;
                    uint32_t bh4[4], bl4[4];
                    LDSM_X4(bh4, rb);
                    LDSM_X4(bl4, rb + FL_MAT);
                    MMA_BF16(s8[np*2],   fqh[kk], bh4);
                    MMA_BF16(s8[np*2],   fqh[kk], bl4);
                    MMA_BF16(s8[np*2],   fql[kk], bh4);
                    MMA_BF16(s8[np*2+1], fqh[kk], bh4 + 2);
                    MMA_BF16(s8[np*2+1], fqh[kk], bl4 + 2);
                    MMA_BF16(s8[np*2+1], fql[kk], bh4 + 2);
                }
            }

            if (64 * c + 63 > q0 + w * 16) {
                #pragma unroll
                for (int t = 0; t < 8; t++) {
                    int col = c * 64 + t * 8 + (lane & 3) * 2;
                    if (col     > r0) s8[t][0] = -1e30f;
                    if (col + 1 > r0) s8[t][1] = -1e30f;
                    if (col     > r1) s8[t][2] = -1e30f;
                    if (col + 1 > r1) s8[t][3] = -1e30f;
                }
            }

            float mx0 = -1e30f, mx1 = -1e30f;
            #pragma unroll
            for (int t = 0; t < 8; t++) {
                mx0 = fmaxf(mx0, fmaxf(s8[t][0], s8[t][1]));
                mx1 = fmaxf(mx1, fmaxf(s8[t][2], s8[t][3]));
            }
            mx0 = fmaxf(mx0, __shfl_xor_sync(0xffffffffu, mx0, 1));
            mx0 = fmaxf(mx0, __shfl_xor_sync(0xffffffffu, mx0, 2));
            mx1 = fmaxf(mx1, __shfl_xor_sync(0xffffffffu, mx1, 1));
            mx1 = fmaxf(mx1, __shfl_xor_sync(0xffffffffu, mx1, 2));
            float mn0 = fmaxf(m0, mx0), mn1 = fmaxf(m1, mx1);
            float a0 = exp2f(m0 - mn0), a1 = exp2f(m1 - mn1);
            m0 = mn0;  m1 = mn1;
            float sum0 = 0.f, sum1 = 0.f;
            #pragma unroll
            for (int t = 0; t < 8; t++) {
                s8[t][0] = exp2f(s8[t][0] - mn0);
                s8[t][1] = exp2f(s8[t][1] - mn0);
                s8[t][2] = exp2f(s8[t][2] - mn1);
                s8[t][3] = exp2f(s8[t][3] - mn1);
                sum0 += s8[t][0] + s8[t][1];
                sum1 += s8[t][2] + s8[t][3];
            }
            l0 = l0 * a0 + sum0;
            l1 = l1 * a1 + sum1;
            #pragma unroll
            for (int nt = 0; nt < 16; nt++) {
                o[nt][0] *= a0;  o[nt][1] *= a0;
                o[nt][2] *= a1;  o[nt][3] *= a1;
            }

            #pragma unroll
            for (int kk2 = 0; kk2 < 4; kk2++) {
                uint32_t pah[4], pal[4];
                split2(s8[2*kk2][0],   s8[2*kk2][1],   pah[0], pal[0]);
                split2(s8[2*kk2][2],   s8[2*kk2][3],   pah[1], pal[1]);
                split2(s8[2*kk2+1][0], s8[2*kk2+1][1], pah[2], pal[2]);
                split2(s8[2*kk2+1][2], s8[2*kk2+1][3], pah[3], pal[3]);
                #pragma unroll
                for (int np = 0; np < 8; np++) {
                    uint32_t rv = st + 2 * FL_MAT
                                + (kk2 * 16 + (lane & 15)) * FL_STRIDE
                                + (np * 16 + (lane >> 4) * 8) * 2;
                    uint32_t vh4[4], vl4[4];
                    LDSM_T_X4(vh4, rv);
                    LDSM_T_X4(vl4, rv + FL_MAT);
                    MMA_BF16(o[np*2],   pah, vh4);
                    MMA_BF16(o[np*2],   pah, vl4);
                    MMA_BF16(o[np*2],   pal, vh4);
                    MMA_BF16(o[np*2+1], pah, vh4 + 2);
                    MMA_BF16(o[np*2+1], pah, vl4 + 2);
                    MMA_BF16(o[np*2+1], pal, vh4 + 2);
                }
            }
        }
        __syncthreads();
        if (c + 2 < C) load_chunk(c & 1, c + 2);
    }

    l0 += __shfl_xor_sync(0xffffffffu, l0, 1);
    l0 += __shfl_xor_sync(0xffffffffu, l0, 2);
    l1 += __shfl_xor_sync(0xffffffffu, l1, 1);
    l1 += __shfl_xor_sync(0xffffffffu, l1, 2);
    float inv0 = 1.0f / l0, inv1 = 1.0f / l1;

    const size_t orow0 = (size_t)(b * SEQ + r0) * D_MODEL + h * HD;
    const size_t orow1 = (size_t)(b * SEQ + r1) * D_MODEL + h * HD;
    #pragma unroll
    for (int nt = 0; nt < 16; nt++) {
        int col = nt * 8 + (lane & 3) * 2;
        uint32_t hi, lo;
        split2(o[nt][0] * inv0, o[nt][1] * inv0, hi, lo);
        *(uint32_t*)(oh + orow0 + col) = hi;
        *(uint32_t*)(ol + orow0 + col) = lo;
        split2(o[nt][2] * inv1, o[nt][3] * inv1, hi, lo);
        *(uint32_t*)(oh + orow1 + col) = hi;
        *(uint32_t*)(ol + orow1 + col) = lo;
    }
}

// ---------------------------------------------------------------------------
extern "C" void kernel_launch(void* const* d_in, const int* in_sizes, int n_in,
                              void* d_out, int out_size) {
    const float* x  = (const float*)d_in[0];
    const float* Wq = (const float*)d_in[1];
    const float* Wk = (const float*)d_in[2];
    const float* Wv = (const float*)d_in[3];
    const float* Wo = (const float*)d_in[4];
    float* out = (float*)d_out;

    float *qp, *kp, *vp;
    cudaGetSymbolAddress((void**)&qp, g_q);
    cudaGetSymbolAddress((void**)&kp, g_k);
    cudaGetSymbolAddress((void**)&vp, g_v);

    __nv_bfloat16 *xh, *xl, *ah, *al;
    cudaGetSymbolAddress((void**)&xh, g_xh);
    cudaGetSymbolAddress((void**)&xl, g_xl);
    cudaGetSymbolAddress((void**)&ah, g_ah);
    cudaGetSymbolAddress((void**)&al, g_al);

    __nv_bfloat16 *qhp, *qlp, *khp, *klp, *vhp, *vlp;
    cudaGetSymbolAddress((void**)&qhp, g_qh);
    cudaGetSymbolAddress((void**)&qlp, g_ql);
    cudaGetSymbolAddress((void**)&khp, g_kh);
    cudaGetSymbolAddress((void**)&klp, g_kl);
    cudaGetSymbolAddress((void**)&vhp, g_vh);
    cudaGetSymbolAddress((void**)&vlp, g_vl);

    __nv_bfloat16 *wqh, *wql, *wkh, *wkl, *wvh, *wvl, *woh, *wol;
    cudaGetSymbolAddress((void**)&wqh, g_wqh);
    cudaGetSymbolAddress((void**)&wql, g_wql);
    cudaGetSymbolAddress((void**)&wkh, g_wkh);
    cudaGetSymbolAddress((void**)&wkl, g_wkl);
    cudaGetSymbolAddress((void**)&wvh, g_wvh);
    cudaGetSymbolAddress((void**)&wvl, g_wvl);
    cudaGetSymbolAddress((void**)&woh, g_woh);
    cudaGetSymbolAddress((void**)&wol, g_wol);

    cudaFuncSetAttribute(gemm_hmma, cudaFuncAttributeMaxDynamicSharedMemorySize, GEMM_SMEM);
    cudaFuncSetAttribute(flash_hmma, cudaFuncAttributeMaxDynamicSharedMemorySize, FL_SMEM);

    // split inputs
    {
        int n4 = MROWS * D_MODEL / 4;
        split_e<<<(n4 + 255) / 256, 256>>>(x, xh, xl, n4);
        dim3 tb(32, 8), tg(D_MODEL / 32, D_MODEL / 32);
        split_t<<<tg, tb>>>(Wq, wqh, wql);
        split_t<<<tg, tb>>>(Wk, wkh, wkl);
        split_t<<<tg, tb>>>(Wv, wvh, wvl);
        split_t<<<tg, tb>>>(Wo, woh, wol);
    }

    dim3 ggrid(D_MODEL / 256, MROWS / 128);   // (8, 32)
    gemm_hmma<<<ggrid, 256, GEMM_SMEM>>>(xh, xl, wqh, wql, qp);
    gemm_hmma<<<ggrid, 256, GEMM_SMEM>>>(xh, xl, wkh, wkl, kp);
    gemm_hmma<<<ggrid, 256, GEMM_SMEM>>>(xh, xl, wvh, wvl, vp);

    {
        int total = MROWS * NHEAD * (HD / 2);
        rope_split<<<(total + 255) / 256, 256>>>(qp, kp, vp, qhp, qlp, khp, klp, vhp, vlp);
    }

    {
        dim3 fgrid(SEQ / 128, BATCH * NHEAD);  // (16, 32)
        flash_hmma<<<fgrid, 256, FL_SMEM>>>(qhp, qlp, khp, klp, vhp, vlp, ah, al);
    }

    gemm_hmma<<<ggrid, 256, GEMM_SMEM>>>(ah, al, woh, wol, out);
}

// round 6
// speedup vs baseline: 2.7999x; 1.0037x over previous
#include <cuda_runtime.h>
#include <cuda_bf16.h>
#include <cstdint>
#include <math.h>

#define D_MODEL 2048
#define SEQ     2048
#define BATCH   2
#define NHEAD   16
#define HD      128
#define MROWS   (BATCH*SEQ)   // 4096

// ---------------------------------------------------------------------------
// Scratch (__device__ globals: allocation-free rule)
// ---------------------------------------------------------------------------
__device__ float g_q[MROWS * D_MODEL];
__device__ float g_k[MROWS * D_MODEL];
__device__ float g_v[MROWS * D_MODEL];

__device__ __nv_bfloat16 g_xh[MROWS * D_MODEL];
__device__ __nv_bfloat16 g_xl[MROWS * D_MODEL];
__device__ __nv_bfloat16 g_ah[MROWS * D_MODEL];
__device__ __nv_bfloat16 g_al[MROWS * D_MODEL];

__device__ __nv_bfloat16 g_qh[MROWS * D_MODEL];
__device__ __nv_bfloat16 g_ql[MROWS * D_MODEL];
__device__ __nv_bfloat16 g_kh[MROWS * D_MODEL];
__device__ __nv_bfloat16 g_kl[MROWS * D_MODEL];
__device__ __nv_bfloat16 g_vh[MROWS * D_MODEL];
__device__ __nv_bfloat16 g_vl[MROWS * D_MODEL];

// concat weights: [Wq; Wk; Wv; Wo] each transposed [N,K], hi/lo
__device__ __nv_bfloat16 g_wh[4 * D_MODEL * D_MODEL];
__device__ __nv_bfloat16 g_wl[4 * D_MODEL * D_MODEL];

// ---------------------------------------------------------------------------
// PTX helpers (plain sm_103: no tcgen05)
// ---------------------------------------------------------------------------
__device__ __forceinline__ uint32_t smem_u32(const void* p) {
    uint32_t a;
    asm("{ .reg .u64 t; cvta.to.shared.u64 t, %1; cvt.u32.u64 %0, t; }" : "=r"(a) : "l"(p));
    return a;
}
__device__ __forceinline__ void cp16(uint32_t dst, const void* src) {
    asm volatile("cp.async.cg.shared.global [%0], [%1], 16;" :: "r"(dst), "l"(src) : "memory");
}
#define CP_COMMIT() asm volatile("cp.async.commit_group;" ::: "memory")
#define CP_WAIT(n)  asm volatile("cp.async.wait_group %0;" :: "n"(n) : "memory")

#define LDSM_X4(r, addr) \
    asm volatile("ldmatrix.sync.aligned.m8n8.x4.shared.b16 {%0,%1,%2,%3}, [%4];" \
        : "=r"((r)[0]), "=r"((r)[1]), "=r"((r)[2]), "=r"((r)[3]) : "r"(addr))
#define LDSM_T_X4(r, addr) \
    asm volatile("ldmatrix.sync.aligned.m8n8.x4.trans.shared.b16 {%0,%1,%2,%3}, [%4];" \
        : "=r"((r)[0]), "=r"((r)[1]), "=r"((r)[2]), "=r"((r)[3]) : "r"(addr))

#define MMA_BF16(c, a, b) \
    asm volatile("mma.sync.aligned.m16n8k16.row.col.f32.bf16.bf16.f32 " \
        "{%0,%1,%2,%3}, {%4,%5,%6,%7}, {%8,%9}, {%0,%1,%2,%3};" \
        : "+f"((c)[0]), "+f"((c)[1]), "+f"((c)[2]), "+f"((c)[3]) \
        : "r"((a)[0]), "r"((a)[1]), "r"((a)[2]), "r"((a)[3]), "r"((b)[0]), "r"((b)[1]))

__device__ __forceinline__ void split2(float a, float b, uint32_t& hi, uint32_t& lo) {
    __nv_bfloat16 ha = __float2bfloat16(a), hb = __float2bfloat16(b);
    float ra = a - __bfloat162float(ha), rb = b - __bfloat162float(hb);
    __nv_bfloat16 la = __float2bfloat16(ra), lb = __float2bfloat16(rb);
    hi = (uint32_t)__bfloat16_as_ushort(ha) | ((uint32_t)__bfloat16_as_ushort(hb) << 16);
    lo = (uint32_t)__bfloat16_as_ushort(la) | ((uint32_t)__bfloat16_as_ushort(lb) << 16);
}

// ---------------------------------------------------------------------------
// fp32 -> (bf16 hi, bf16 lo) elementwise split
// ---------------------------------------------------------------------------
__global__ void split_e(const float* __restrict__ in, __nv_bfloat16* __restrict__ hi,
                        __nv_bfloat16* __restrict__ lo, int n4) {
    int i = blockIdx.x * blockDim.x + threadIdx.x;
    if (i >= n4) return;
    float4 v = ((const float4*)in)[i];
    __nv_bfloat16 h0 = __float2bfloat16(v.x), h1 = __float2bfloat16(v.y);
    __nv_bfloat16 h2 = __float2bfloat16(v.z), h3 = __float2bfloat16(v.w);
    __nv_bfloat16 l0 = __float2bfloat16(v.x - __bfloat162float(h0));
    __nv_bfloat16 l1 = __float2bfloat16(v.y - __bfloat162float(h1));
    __nv_bfloat16 l2 = __float2bfloat16(v.z - __bfloat162float(h2));
    __nv_bfloat16 l3 = __float2bfloat16(v.w - __bfloat162float(h3));
    ((__nv_bfloat162*)hi)[2*i]   = __nv_bfloat162(h0, h1);
    ((__nv_bfloat162*)hi)[2*i+1] = __nv_bfloat162(h2, h3);
    ((__nv_bfloat162*)lo)[2*i]   = __nv_bfloat162(l0, l1);
    ((__nv_bfloat162*)lo)[2*i+1] = __nv_bfloat162(l2, l3);
}

// fp32 W[K,N] -> transposed bf16 hi/lo [N,K]
__global__ void split_t(const float* __restrict__ in, __nv_bfloat16* __restrict__ hiT,
                        __nv_bfloat16* __restrict__ loT) {
    __shared__ float t[32][33];
    int tx = threadIdx.x, ty = threadIdx.y;
    int bn = blockIdx.x, bk = blockIdx.y;
    #pragma unroll
    for (int j = 0; j < 4; j++) {
        int k = bk * 32 + ty + j * 8;
        t[ty + j * 8][tx] = in[(size_t)k * D_MODEL + bn * 32 + tx];
    }
    __syncthreads();
    #pragma unroll
    for (int j = 0; j < 4; j++) {
        int n = bn * 32 + ty + j * 8;
        float v = t[tx][ty + j * 8];
        __nv_bfloat16 h = __float2bfloat16(v);
        __nv_bfloat16 l = __float2bfloat16(v - __bfloat162float(h));
        size_t off = (size_t)n * D_MODEL + bk * 32 + tx;
        hiT[off] = h;
        loT[off] = l;
    }
}

// ---------------------------------------------------------------------------
// HMMA GEMM over concatenated weights: C = A @ W^T for N = ntiles*256 weight
// rows. Output target selected per 256-wide tileN (Cq/Ck/Cv or single).
// CTA tile 128(M) x 256(N), BK=32, 3-stage cp.async, warp tile 64x64.
// ---------------------------------------------------------------------------
#define PADB   80
#define AMAT   (128 * PADB)
#define BMAT   (256 * PADB)
#define BOFF   (2 * AMAT)
#define STAGEB (2 * AMAT + 2 * BMAT)
#define NSTAGE 3
#define GEMM_SMEM (NSTAGE * STAGEB)

__global__ __launch_bounds__(256)
void gemm_hmma(const __nv_bfloat16* __restrict__ Ah, const __nv_bfloat16* __restrict__ Al,
               const __nv_bfloat16* __restrict__ Bh, const __nv_bfloat16* __restrict__ Bl,
               float* __restrict__ C0, float* __restrict__ C1, float* __restrict__ C2) {
    extern __shared__ char smem[];
    const uint32_t sb = smem_u32(smem);
    const int tid  = threadIdx.x;
    const int wid  = tid >> 5;
    const int lane = tid & 31;
    const int tileN = blockIdx.x;
    const int tileM = blockIdx.y;

    float* C = (tileN < 8) ? C0 : ((tileN < 16) ? C1 : C2);
    const int nloc = tileN & 7;

    const int m0w = (wid >> 2) * 64;
    const int n0w = (wid & 3) * 64;

    const __nv_bfloat16* gpA[2] = {
        Ah + (size_t)tileM * 128 * D_MODEL,
        Al + (size_t)tileM * 128 * D_MODEL };
    const __nv_bfloat16* gpB[2] = {
        Bh + (size_t)tileN * 256 * D_MODEL,
        Bl + (size_t)tileN * 256 * D_MODEL };

    auto load_stage = [&](int s, int k0) {
        uint32_t sbase = sb + s * STAGEB;
        #pragma unroll
        for (int m = 0; m < 2; m++) {
            #pragma unroll
            for (int rep = 0; rep < 2; rep++) {
                int flat = rep * 256 + tid;
                int row = flat >> 2, ch = flat & 3;
                cp16(sbase + m * AMAT + row * PADB + ch * 16,
                     gpA[m] + (size_t)row * D_MODEL + k0 + ch * 8);
            }
        }
        #pragma unroll
        for (int m = 0; m < 2; m++) {
            #pragma unroll
            for (int rep = 0; rep < 4; rep++) {
                int flat = rep * 256 + tid;
                int row = flat >> 2, ch = flat & 3;
                cp16(sbase + BOFF + m * BMAT + row * PADB + ch * 16,
                     gpB[m] + (size_t)row * D_MODEL + k0 + ch * 8);
            }
        }
        CP_COMMIT();
    };

    float acc[4][8][4];
    #pragma unroll
    for (int i = 0; i < 4; i++)
        #pragma unroll
        for (int j = 0; j < 8; j++)
            #pragma unroll
            for (int r = 0; r < 4; r++) acc[i][j][r] = 0.f;

    load_stage(0, 0);
    load_stage(1, 32);

    const int NCH = D_MODEL / 32;
    for (int c = 0; c < NCH; c++) {
        if (c + 2 < NCH) { CP_WAIT(1); } else { CP_WAIT(0); }
        __syncthreads();
        if (c + 2 < NCH) load_stage((c + 2) % NSTAGE, (c + 2) * 32);

        const uint32_t st = sb + (c % NSTAGE) * STAGEB;
        #pragma unroll
        for (int ks = 0; ks < 2; ks++) {
            uint32_t ah[4][4], al[4][4];
            const uint32_t arow = (lane & 15);
            const uint32_t akb  = (ks * 16 + (lane >> 4) * 8) * 2;
            #pragma unroll
            for (int mt = 0; mt < 4; mt++) {
                uint32_t ra = st + (m0w + mt * 16 + arow) * PADB + akb;
                LDSM_X4(ah[mt], ra);
                LDSM_X4(al[mt], ra + AMAT);
            }
            const uint32_t brow = (lane & 7) + ((lane >> 4) & 1) * 8;
            const uint32_t bkb  = (ks * 16 + ((lane >> 3) & 1) * 8) * 2;
            #pragma unroll
            for (int np = 0; np < 4; np++) {
                uint32_t rb = st + BOFF + (n0w + np * 16 + brow) * PADB + bkb;
                uint32_t bh4[4], bl4[4];
                LDSM_X4(bh4, rb);
                LDSM_X4(bl4, rb + BMAT);
                #pragma unroll
                for (int half = 0; half < 2; half++) {
                    const int nt = np * 2 + half;
                    uint32_t* bh = bh4 + half * 2;
                    uint32_t* bl = bl4 + half * 2;
                    #pragma unroll
                    for (int mt = 0; mt < 4; mt++) {
                        MMA_BF16(acc[mt][nt], ah[mt], bh);
                        MMA_BF16(acc[mt][nt], ah[mt], bl);
                        MMA_BF16(acc[mt][nt], al[mt], bh);
                    }
                }
            }
        }
    }

    float* cbase = C + (size_t)tileM * 128 * D_MODEL + nloc * 256;
    const int rq = lane >> 2;
    const int cq = (lane & 3) * 2;
    #pragma unroll
    for (int mt = 0; mt < 4; mt++) {
        #pragma unroll
        for (int nt = 0; nt < 8; nt++) {
            int row = m0w + mt * 16 + rq;
            int col = n0w + nt * 8 + cq;
            *(float2*)(cbase + (size_t)row * D_MODEL + col) =
                make_float2(acc[mt][nt][0], acc[mt][nt][1]);
            *(float2*)(cbase + (size_t)(row + 8) * D_MODEL + col) =
                make_float2(acc[mt][nt][2], acc[mt][nt][3]);
        }
    }
}

// ---------------------------------------------------------------------------
// RoPE + split
// ---------------------------------------------------------------------------
__global__ void rope_split(const float* __restrict__ q, const float* __restrict__ k,
                           const float* __restrict__ v,
                           __nv_bfloat16* __restrict__ qh, __nv_bfloat16* __restrict__ ql,
                           __nv_bfloat16* __restrict__ kh, __nv_bfloat16* __restrict__ kl,
                           __nv_bfloat16* __restrict__ vh, __nv_bfloat16* __restrict__ vl) {
    const int total = MROWS * NHEAD * (HD / 2);
    int idx = blockIdx.x * blockDim.x + threadIdx.x;
    if (idx >= total) return;
    int u   = idx & 63;
    int h   = (idx >> 6) & 15;
    int row = idx >> 10;
    int s   = row & (SEQ - 1);

    float inv_freq = exp2f(-13.287712379549449f * ((float)(2 * u) * (1.0f / 128.0f)));
    float ang = (float)s * inv_freq;
    float sn, cs;
    sincosf(ang, &sn, &cs);

    const float SCF = 0.08838834764831845f * 1.4426950408889634f;

    size_t off = (size_t)row * D_MODEL + h * HD + 2 * u;
    float2 qv = *(const float2*)(q + off);
    float2 kv = *(const float2*)(k + off);
    float2 vv = *(const float2*)(v + off);

    float q0 = (qv.x * cs - qv.y * sn) * SCF;
    float q1 = (qv.x * sn + qv.y * cs) * SCF;
    float k0 = kv.x * cs - kv.y * sn;
    float k1 = kv.x * sn + kv.y * cs;

    uint32_t hi, lo;
    split2(q0, q1, hi, lo);
    *(uint32_t*)(qh + off) = hi;  *(uint32_t*)(ql + off) = lo;
    split2(k0, k1, hi, lo);
    *(uint32_t*)(kh + off) = hi;  *(uint32_t*)(kl + off) = lo;
    split2(vv.x, vv.y, hi, lo);
    *(uint32_t*)(vh + off) = hi;  *(uint32_t*)(vl + off) = lo;
}

// ---------------------------------------------------------------------------
// HMMA flash attention (round-4 core; qt reversed for longest-first sched)
// ---------------------------------------------------------------------------
#define FL_STRIDE 272
#define FL_MAT    (64 * FL_STRIDE)
#define FL_STAGE  (4 * FL_MAT)
#define FL_SMEM   (2 * FL_STAGE)
#define FL_QMAT   (128 * FL_STRIDE)

__global__ __launch_bounds__(256, 1)
void flash_hmma(const __nv_bfloat16* __restrict__ qh, const __nv_bfloat16* __restrict__ ql,
                const __nv_bfloat16* __restrict__ kh, const __nv_bfloat16* __restrict__ kl,
                const __nv_bfloat16* __restrict__ vh, const __nv_bfloat16* __restrict__ vl,
                __nv_bfloat16* __restrict__ oh, __nv_bfloat16* __restrict__ ol) {
    extern __shared__ char smem[];
    const uint32_t sb = smem_u32(smem);
    const int tid  = threadIdx.x;
    const int w    = tid >> 5;
    const int lane = tid & 31;
    const int qt = (int)gridDim.x - 1 - (int)blockIdx.x;   // longest-first
    const int bh = blockIdx.y;
    const int b  = bh >> 4;
    const int h  = bh & 15;

    const size_t gbase = (size_t)b * SEQ * D_MODEL + (size_t)h * HD;
    const int q0 = qt * 128;

    const uint32_t qsm = sb + FL_STAGE;
    {
        const __nv_bfloat16* gq[2] = { qh + gbase + (size_t)q0 * D_MODEL,
                                       ql + gbase + (size_t)q0 * D_MODEL };
        #pragma unroll
        for (int m = 0; m < 2; m++)
            #pragma unroll
            for (int i = 0; i < 8; i++) {
                int idx = i * 256 + tid;
                int r = idx >> 4, c = idx & 15;
                cp16(qsm + m * FL_QMAT + r * FL_STRIDE + c * 16,
                     gq[m] + (size_t)r * D_MODEL + c * 8);
            }
    }
    auto load_chunk = [&](int stage, int kt) {
        uint32_t st = sb + stage * FL_STAGE;
        const __nv_bfloat16* gp[4] = {
            kh + gbase + (size_t)(kt * 64) * D_MODEL,
            kl + gbase + (size_t)(kt * 64) * D_MODEL,
            vh + gbase + (size_t)(kt * 64) * D_MODEL,
            vl + gbase + (size_t)(kt * 64) * D_MODEL };
        #pragma unroll
        for (int m = 0; m < 4; m++)
            #pragma unroll
            for (int i = 0; i < 4; i++) {
                int idx = i * 256 + tid;
                int r = idx >> 4, c = idx & 15;
                cp16(st + m * FL_MAT + r * FL_STRIDE + c * 16,
                     gp[m] + (size_t)r * D_MODEL + c * 8);
            }
        CP_COMMIT();
    };
    load_chunk(0, 0);
    CP_WAIT(0);
    __syncthreads();

    uint32_t fqh[8][4], fql[8][4];
    #pragma unroll
    for (int kk = 0; kk < 8; kk++) {
        uint32_t ra = qsm + (w * 16 + (lane & 15)) * FL_STRIDE + (kk * 16 + (lane >> 4) * 8) * 2;
        LDSM_X4(fqh[kk], ra);
        LDSM_X4(fql[kk], ra + FL_QMAT);
    }
    __syncthreads();
    const int C = 2 * qt + 2;
    if (1 < C) load_chunk(1, 1);

    float o[16][4];
    #pragma unroll
    for (int nt = 0; nt < 16; nt++)
        #pragma unroll
        for (int r = 0; r < 4; r++) o[nt][r] = 0.f;
    float m0 = -1e30f, m1 = -1e30f, l0 = 0.f, l1 = 0.f;

    const int r0 = q0 + w * 16 + (lane >> 2);
    const int r1 = r0 + 8;

    for (int c = 0; c < C; c++) {
        if (c + 1 < C) { CP_WAIT(1); } else { CP_WAIT(0); }
        __syncthreads();
        const uint32_t st = sb + (c & 1) * FL_STAGE;

        const bool skip = (64 * c > q0 + w * 16 + 15);
        if (!skip) {
            float s8[8][4];
            #pragma unroll
            for (int t = 0; t < 8; t++)
                #pragma unroll
                for (int r = 0; r < 4; r++) s8[t][r] = 0.f;

            #pragma unroll
            for (int kk = 0; kk < 8; kk++) {
                #pragma unroll
                for (int np = 0; np < 4; np++) {
                    uint32_t rb = st + (np * 16 + (lane & 7) + ((lane >> 4) & 1) * 8) * FL_STRIDE
                                     + (((lane >> 3) & 1) * 8 + kk * 16) * 2;
                    uint32_t bh4[4], bl4[4];
                    LDSM_X4(bh4, rb);
                    LDSM_X4(bl4, rb + FL_MAT);
                    MMA_BF16(s8[np*2],   fqh[kk], bh4);
                    MMA_BF16(s8[np*2],   fqh[kk], bl4);
                    MMA_BF16(s8[np*2],   fql[kk], bh4);
                    MMA_BF16(s8[np*2+1], fqh[kk], bh4 + 2);
                    MMA_BF16(s8[np*2+1], fqh[kk], bl4 + 2);
                    MMA_BF16(s8[np*2+1], fql[kk], bh4 + 2);
                }
            }

            if (64 * c + 63 > q0 + w * 16) {
                #pragma unroll
                for (int t = 0; t < 8; t++) {
                    int col = c * 64 + t * 8 + (lane & 3) * 2;
                    if (col     > r0) s8[t][0] = -1e30f;
                    if (col + 1 > r0) s8[t][1] = -1e30f;
                    if (col     > r1) s8[t][2] = -1e30f;
                    if (col + 1 > r1) s8[t][3] = -1e30f;
                }
            }

            float mx0 = -1e30f, mx1 = -1e30f;
            #pragma unroll
            for (int t = 0; t < 8; t++) {
                mx0 = fmaxf(mx0, fmaxf(s8[t][0], s8[t][1]));
                mx1 = fmaxf(mx1, fmaxf(s8[t][2], s8[t][3]));
            }
            mx0 = fmaxf(mx0, __shfl_xor_sync(0xffffffffu, mx0, 1));
            mx0 = fmaxf(mx0, __shfl_xor_sync(0xffffffffu, mx0, 2));
            mx1 = fmaxf(mx1, __shfl_xor_sync(0xffffffffu, mx1, 1));
            mx1 = fmaxf(mx1, __shfl_xor_sync(0xffffffffu, mx1, 2));
            float mn0 = fmaxf(m0, mx0), mn1 = fmaxf(m1, mx1);
            float a0 = exp2f(m0 - mn0), a1 = exp2f(m1 - mn1);
            m0 = mn0;  m1 = mn1;
            float sum0 = 0.f, sum1 = 0.f;
            #pragma unroll
            for (int t = 0; t < 8; t++) {
                s8[t][0] = exp2f(s8[t][0] - mn0);
                s8[t][1] = exp2f(s8[t][1] - mn0);
                s8[t][2] = exp2f(s8[t][2] - mn1);
                s8[t][3] = exp2f(s8[t][3] - mn1);
                sum0 += s8[t][0] + s8[t][1];
                sum1 += s8[t][2] + s8[t][3];
            }
            l0 = l0 * a0 + sum0;
            l1 = l1 * a1 + sum1;
            #pragma unroll
            for (int nt = 0; nt < 16; nt++) {
                o[nt][0] *= a0;  o[nt][1] *= a0;
                o[nt][2] *= a1;  o[nt][3] *= a1;
            }

            #pragma unroll
            for (int kk2 = 0; kk2 < 4; kk2++) {
                uint32_t pah[4], pal[4];
                split2(s8[2*kk2][0],   s8[2*kk2][1],   pah[0], pal[0]);
                split2(s8[2*kk2][2],   s8[2*kk2][3],   pah[1], pal[1]);
                split2(s8[2*kk2+1][0], s8[2*kk2+1][1], pah[2], pal[2]);
                split2(s8[2*kk2+1][2], s8[2*kk2+1][3], pah[3], pal[3]);
                #pragma unroll
                for (int np = 0; np < 8; np++) {
                    uint32_t rv = st + 2 * FL_MAT
                                + (kk2 * 16 + (lane & 15)) * FL_STRIDE
                                + (np * 16 + (lane >> 4) * 8) * 2;
                    uint32_t vh4[4], vl4[4];
                    LDSM_T_X4(vh4, rv);
                    LDSM_T_X4(vl4, rv + FL_MAT);
                    MMA_BF16(o[np*2],   pah, vh4);
                    MMA_BF16(o[np*2],   pah, vl4);
                    MMA_BF16(o[np*2],   pal, vh4);
                    MMA_BF16(o[np*2+1], pah, vh4 + 2);
                    MMA_BF16(o[np*2+1], pah, vl4 + 2);
                    MMA_BF16(o[np*2+1], pal, vh4 + 2);
                }
            }
        }
        __syncthreads();
        if (c + 2 < C) load_chunk(c & 1, c + 2);
    }

    l0 += __shfl_xor_sync(0xffffffffu, l0, 1);
    l0 += __shfl_xor_sync(0xffffffffu, l0, 2);
    l1 += __shfl_xor_sync(0xffffffffu, l1, 1);
    l1 += __shfl_xor_sync(0xffffffffu, l1, 2);
    float inv0 = 1.0f / l0, inv1 = 1.0f / l1;

    const size_t orow0 = (size_t)(b * SEQ + r0) * D_MODEL + h * HD;
    const size_t orow1 = (size_t)(b * SEQ + r1) * D_MODEL + h * HD;
    #pragma unroll
    for (int nt = 0; nt < 16; nt++) {
        int col = nt * 8 + (lane & 3) * 2;
        uint32_t hi, lo;
        split2(o[nt][0] * inv0, o[nt][1] * inv0, hi, lo);
        *(uint32_t*)(oh + orow0 + col) = hi;
        *(uint32_t*)(ol + orow0 + col) = lo;
        split2(o[nt][2] * inv1, o[nt][3] * inv1, hi, lo);
        *(uint32_t*)(oh + orow1 + col) = hi;
        *(uint32_t*)(ol + orow1 + col) = lo;
    }
}

// ---------------------------------------------------------------------------
extern "C" void kernel_launch(void* const* d_in, const int* in_sizes, int n_in,
                              void* d_out, int out_size) {
    const float* x  = (const float*)d_in[0];
    const float* Wq = (const float*)d_in[1];
    const float* Wk = (const float*)d_in[2];
    const float* Wv = (const float*)d_in[3];
    const float* Wo = (const float*)d_in[4];
    float* out = (float*)d_out;

    float *qp, *kp, *vp;
    cudaGetSymbolAddress((void**)&qp, g_q);
    cudaGetSymbolAddress((void**)&kp, g_k);
    cudaGetSymbolAddress((void**)&vp, g_v);

    __nv_bfloat16 *xh, *xl, *ah, *al;
    cudaGetSymbolAddress((void**)&xh, g_xh);
    cudaGetSymbolAddress((void**)&xl, g_xl);
    cudaGetSymbolAddress((void**)&ah, g_ah);
    cudaGetSymbolAddress((void**)&al, g_al);

    __nv_bfloat16 *qhp, *qlp, *khp, *klp, *vhp, *vlp;
    cudaGetSymbolAddress((void**)&qhp, g_qh);
    cudaGetSymbolAddress((void**)&qlp, g_ql);
    cudaGetSymbolAddress((void**)&khp, g_kh);
    cudaGetSymbolAddress((void**)&klp, g_kl);
    cudaGetSymbolAddress((void**)&vhp, g_vh);
    cudaGetSymbolAddress((void**)&vlp, g_vl);

    __nv_bfloat16 *wh, *wl;
    cudaGetSymbolAddress((void**)&wh, g_wh);
    cudaGetSymbolAddress((void**)&wl, g_wl);
    const size_t WSZ = (size_t)D_MODEL * D_MODEL;

    cudaFuncSetAttribute(gemm_hmma, cudaFuncAttributeMaxDynamicSharedMemorySize, GEMM_SMEM);
    cudaFuncSetAttribute(flash_hmma, cudaFuncAttributeMaxDynamicSharedMemorySize, FL_SMEM);

    // split inputs (weights into one concatenated [4*2048, 2048] hi/lo pair)
    {
        int n4 = MROWS * D_MODEL / 4;
        split_e<<<(n4 + 255) / 256, 256>>>(x, xh, xl, n4);
        dim3 tb(32, 8), tg(D_MODEL / 32, D_MODEL / 32);
        split_t<<<tg, tb>>>(Wq, wh,           wl);
        split_t<<<tg, tb>>>(Wk, wh + WSZ,     wl + WSZ);
        split_t<<<tg, tb>>>(Wv, wh + 2 * WSZ, wl + 2 * WSZ);
        split_t<<<tg, tb>>>(Wo, wh + 3 * WSZ, wl + 3 * WSZ);
    }

    // fused QKV projection: N = 3*2048 = 24 tiles of 256
    {
        dim3 ggrid(24, MROWS / 128);   // (24, 32) = 768 CTAs
        gemm_hmma<<<ggrid, 256, GEMM_SMEM>>>(xh, xl, wh, wl, qp, kp, vp);
    }

    {
        int total = MROWS * NHEAD * (HD / 2);
        rope_split<<<(total + 255) / 256, 256>>>(qp, kp, vp, qhp, qlp, khp, klp, vhp, vlp);
    }

    {
        dim3 fgrid(SEQ / 128, BATCH * NHEAD);  // (16, 32)
        flash_hmma<<<fgrid, 256, FL_SMEM>>>(qhp, qlp, khp, klp, vhp, vlp, ah, al);
    }

    // output projection: Wo block of the concat buffer
    {
        dim3 ggrid(8, MROWS / 128);    // (8, 32)
        gemm_hmma<<<ggrid, 256, GEMM_SMEM>>>(ah, al, wh + 3 * WSZ, wl + 3 * WSZ,
                                             out, out, out);
    }
}

// round 7
// speedup vs baseline: 3.0604x; 1.0930x over previous
#include <cuda_runtime.h>
#include <cuda_bf16.h>
#include <cstdint>
#include <math.h>

#define D_MODEL 2048
#define SEQ     2048
#define BATCH   2
#define NHEAD   16
#define HD      128
#define MROWS   (BATCH*SEQ)   // 4096

// ---------------------------------------------------------------------------
// Scratch (__device__ globals: allocation-free rule)
// ---------------------------------------------------------------------------
__device__ float g_q[MROWS * D_MODEL];
__device__ float g_k[MROWS * D_MODEL];
__device__ float g_v[MROWS * D_MODEL];

__device__ __nv_bfloat16 g_xh[MROWS * D_MODEL];
__device__ __nv_bfloat16 g_xl[MROWS * D_MODEL];
__device__ __nv_bfloat16 g_ah[MROWS * D_MODEL];
__device__ __nv_bfloat16 g_al[MROWS * D_MODEL];

__device__ __nv_bfloat16 g_qh[MROWS * D_MODEL];
__device__ __nv_bfloat16 g_ql[MROWS * D_MODEL];
__device__ __nv_bfloat16 g_kh[MROWS * D_MODEL];
__device__ __nv_bfloat16 g_kl[MROWS * D_MODEL];
__device__ __nv_bfloat16 g_vh[MROWS * D_MODEL];
__device__ __nv_bfloat16 g_vl[MROWS * D_MODEL];

// concat weights: [Wq; Wk; Wv; Wo] each transposed [N,K], hi/lo
__device__ __nv_bfloat16 g_wh[4 * D_MODEL * D_MODEL];
__device__ __nv_bfloat16 g_wl[4 * D_MODEL * D_MODEL];

// ---------------------------------------------------------------------------
// PTX helpers (plain sm_103: no tcgen05)
// ---------------------------------------------------------------------------
__device__ __forceinline__ uint32_t smem_u32(const void* p) {
    uint32_t a;
    asm("{ .reg .u64 t; cvta.to.shared.u64 t, %1; cvt.u32.u64 %0, t; }" : "=r"(a) : "l"(p));
    return a;
}
__device__ __forceinline__ void cp16(uint32_t dst, const void* src) {
    asm volatile("cp.async.cg.shared.global [%0], [%1], 16;" :: "r"(dst), "l"(src) : "memory");
}
#define CP_COMMIT() asm volatile("cp.async.commit_group;" ::: "memory")
#define CP_WAIT(n)  asm volatile("cp.async.wait_group %0;" :: "n"(n) : "memory")

#define LDSM_X4(r, addr) \
    asm volatile("ldmatrix.sync.aligned.m8n8.x4.shared.b16 {%0,%1,%2,%3}, [%4];" \
        : "=r"((r)[0]), "=r"((r)[1]), "=r"((r)[2]), "=r"((r)[3]) : "r"(addr))
#define LDSM_T_X4(r, addr) \
    asm volatile("ldmatrix.sync.aligned.m8n8.x4.trans.shared.b16 {%0,%1,%2,%3}, [%4];" \
        : "=r"((r)[0]), "=r"((r)[1]), "=r"((r)[2]), "=r"((r)[3]) : "r"(addr))

#define MMA_BF16(c, a, b) \
    asm volatile("mma.sync.aligned.m16n8k16.row.col.f32.bf16.bf16.f32 " \
        "{%0,%1,%2,%3}, {%4,%5,%6,%7}, {%8,%9}, {%0,%1,%2,%3};" \
        : "+f"((c)[0]), "+f"((c)[1]), "+f"((c)[2]), "+f"((c)[3]) \
        : "r"((a)[0]), "r"((a)[1]), "r"((a)[2]), "r"((a)[3]), "r"((b)[0]), "r"((b)[1]))

__device__ __forceinline__ void split2(float a, float b, uint32_t& hi, uint32_t& lo) {
    __nv_bfloat16 ha = __float2bfloat16(a), hb = __float2bfloat16(b);
    float ra = a - __bfloat162float(ha), rb = b - __bfloat162float(hb);
    __nv_bfloat16 la = __float2bfloat16(ra), lb = __float2bfloat16(rb);
    hi = (uint32_t)__bfloat16_as_ushort(ha) | ((uint32_t)__bfloat16_as_ushort(hb) << 16);
    lo = (uint32_t)__bfloat16_as_ushort(la) | ((uint32_t)__bfloat16_as_ushort(lb) << 16);
}

// ---------------------------------------------------------------------------
// fp32 -> (bf16 hi, bf16 lo) elementwise split
// ---------------------------------------------------------------------------
__global__ void split_e(const float* __restrict__ in, __nv_bfloat16* __restrict__ hi,
                        __nv_bfloat16* __restrict__ lo, int n4) {
    int i = blockIdx.x * blockDim.x + threadIdx.x;
    if (i >= n4) return;
    float4 v = ((const float4*)in)[i];
    __nv_bfloat16 h0 = __float2bfloat16(v.x), h1 = __float2bfloat16(v.y);
    __nv_bfloat16 h2 = __float2bfloat16(v.z), h3 = __float2bfloat16(v.w);
    __nv_bfloat16 l0 = __float2bfloat16(v.x - __bfloat162float(h0));
    __nv_bfloat16 l1 = __float2bfloat16(v.y - __bfloat162float(h1));
    __nv_bfloat16 l2 = __float2bfloat16(v.z - __bfloat162float(h2));
    __nv_bfloat16 l3 = __float2bfloat16(v.w - __bfloat162float(h3));
    ((__nv_bfloat162*)hi)[2*i]   = __nv_bfloat162(h0, h1);
    ((__nv_bfloat162*)hi)[2*i+1] = __nv_bfloat162(h2, h3);
    ((__nv_bfloat162*)lo)[2*i]   = __nv_bfloat162(l0, l1);
    ((__nv_bfloat162*)lo)[2*i+1] = __nv_bfloat162(l2, l3);
}

// fp32 W[K,N] -> transposed bf16 hi/lo [N,K]
__global__ void split_t(const float* __restrict__ in, __nv_bfloat16* __restrict__ hiT,
                        __nv_bfloat16* __restrict__ loT) {
    __shared__ float t[32][33];
    int tx = threadIdx.x, ty = threadIdx.y;
    int bn = blockIdx.x, bk = blockIdx.y;
    #pragma unroll
    for (int j = 0; j < 4; j++) {
        int k = bk * 32 + ty + j * 8;
        t[ty + j * 8][tx] = in[(size_t)k * D_MODEL + bn * 32 + tx];
    }
    __syncthreads();
    #pragma unroll
    for (int j = 0; j < 4; j++) {
        int n = bn * 32 + ty + j * 8;
        float v = t[tx][ty + j * 8];
        __nv_bfloat16 h = __float2bfloat16(v);
        __nv_bfloat16 l = __float2bfloat16(v - __bfloat162float(h));
        size_t off = (size_t)n * D_MODEL + bk * 32 + tx;
        hiT[off] = h;
        loT[off] = l;
    }
}

// ---------------------------------------------------------------------------
// HMMA GEMM, occupancy-2 version: CTA 128(M) x 128(N), BK=32, 2-stage
// double buffer (80KB smem/CTA -> 2 CTAs/SM), 8 warps (2x4), warp 64x32.
// Output target selected per 128-wide tileN (Cq/Ck/Cv or single).
// ---------------------------------------------------------------------------
#define PADB   80                    // 40 bf16 per row (32 data + 8 pad)
#define AMAT   (128 * PADB)          // 10240
#define STAGEB (4 * AMAT)            // 40960 (Ah, Al, Bh, Bl)
#define GEMM_SMEM (2 * STAGEB)       // 81920

__global__ __launch_bounds__(256, 2)
void gemm_hmma(const __nv_bfloat16* __restrict__ Ah, const __nv_bfloat16* __restrict__ Al,
               const __nv_bfloat16* __restrict__ Bh, const __nv_bfloat16* __restrict__ Bl,
               float* __restrict__ C0, float* __restrict__ C1, float* __restrict__ C2) {
    extern __shared__ char smem[];
    const uint32_t sb = smem_u32(smem);
    const int tid  = threadIdx.x;
    const int wid  = tid >> 5;
    const int lane = tid & 31;
    const int tileN = blockIdx.x;   // 128-wide
    const int tileM = blockIdx.y;   // 128-tall

    float* C = (tileN < 16) ? C0 : ((tileN < 32) ? C1 : C2);
    const int nloc = tileN & 15;

    const int m0w = (wid >> 2) * 64;   // 0 or 64
    const int n0w = (wid & 3) * 32;    // 0,32,64,96

    const __nv_bfloat16* gp[4] = {
        Ah + (size_t)tileM * 128 * D_MODEL,
        Al + (size_t)tileM * 128 * D_MODEL,
        Bh + (size_t)tileN * 128 * D_MODEL,
        Bl + (size_t)tileN * 128 * D_MODEL };

    const int lrow = tid >> 2;       // 0..63
    const int lch  = tid & 3;        // 16B chunk

    auto load_stage = [&](int s, int k0) {
        uint32_t sbase = sb + s * STAGEB;
        #pragma unroll
        for (int mat = 0; mat < 4; mat++) {
            #pragma unroll
            for (int rep = 0; rep < 2; rep++) {
                int row = lrow + rep * 64;
                cp16(sbase + mat * AMAT + row * PADB + lch * 16,
                     gp[mat] + (size_t)row * D_MODEL + k0 + lch * 8);
            }
        }
        CP_COMMIT();
    };

    float acc[4][4][4];
    #pragma unroll
    for (int i = 0; i < 4; i++)
        #pragma unroll
        for (int j = 0; j < 4; j++)
            #pragma unroll
            for (int r = 0; r < 4; r++) acc[i][j][r] = 0.f;

    load_stage(0, 0);

    const int NCH = D_MODEL / 32;   // 64
    for (int c = 0; c < NCH; c++) {
        CP_WAIT(0);                  // stage c ready (only group in flight)
        __syncthreads();             // also frees stage (c+1)&1 from c-1 use
        if (c + 1 < NCH) load_stage((c + 1) & 1, (c + 1) * 32);

        const uint32_t st = sb + (c & 1) * STAGEB;
        #pragma unroll
        for (int ks = 0; ks < 2; ks++) {
            uint32_t ah[4][4], al[4][4];
            const uint32_t arow = (lane & 15);
            const uint32_t akb  = (ks * 16 + (lane >> 4) * 8) * 2;
            #pragma unroll
            for (int mt = 0; mt < 4; mt++) {
                uint32_t ra = st + (m0w + mt * 16 + arow) * PADB + akb;
                LDSM_X4(ah[mt], ra);
                LDSM_X4(al[mt], ra + AMAT);
            }
            const uint32_t brow = (lane & 7) + ((lane >> 4) & 1) * 8;
            const uint32_t bkb  = (ks * 16 + ((lane >> 3) & 1) * 8) * 2;
            #pragma unroll
            for (int np = 0; np < 2; np++) {
                uint32_t rb = st + 2 * AMAT + (n0w + np * 16 + brow) * PADB + bkb;
                uint32_t bh4[4], bl4[4];
                LDSM_X4(bh4, rb);
                LDSM_X4(bl4, rb + AMAT);
                #pragma unroll
                for (int half = 0; half < 2; half++) {
                    const int nt = np * 2 + half;
                    uint32_t* bh = bh4 + half * 2;
                    uint32_t* bl = bl4 + half * 2;
                    #pragma unroll
                    for (int mt = 0; mt < 4; mt++) {
                        MMA_BF16(acc[mt][nt], ah[mt], bh);
                        MMA_BF16(acc[mt][nt], ah[mt], bl);
                        MMA_BF16(acc[mt][nt], al[mt], bh);
                    }
                }
            }
        }
    }

    // epilogue: direct float2 global stores
    float* cbase = C + (size_t)tileM * 128 * D_MODEL + nloc * 128;
    const int rq = lane >> 2;
    const int cq = (lane & 3) * 2;
    #pragma unroll
    for (int mt = 0; mt < 4; mt++) {
        #pragma unroll
        for (int nt = 0; nt < 4; nt++) {
            int row = m0w + mt * 16 + rq;
            int col = n0w + nt * 8 + cq;
            *(float2*)(cbase + (size_t)row * D_MODEL + col) =
                make_float2(acc[mt][nt][0], acc[mt][nt][1]);
            *(float2*)(cbase + (size_t)(row + 8) * D_MODEL + col) =
                make_float2(acc[mt][nt][2], acc[mt][nt][3]);
        }
    }
}

// ---------------------------------------------------------------------------
// RoPE + split
// ---------------------------------------------------------------------------
__global__ void rope_split(const float* __restrict__ q, const float* __restrict__ k,
                           const float* __restrict__ v,
                           __nv_bfloat16* __restrict__ qh, __nv_bfloat16* __restrict__ ql,
                           __nv_bfloat16* __restrict__ kh, __nv_bfloat16* __restrict__ kl,
                           __nv_bfloat16* __restrict__ vh, __nv_bfloat16* __restrict__ vl) {
    const int total = MROWS * NHEAD * (HD / 2);
    int idx = blockIdx.x * blockDim.x + threadIdx.x;
    if (idx >= total) return;
    int u   = idx & 63;
    int h   = (idx >> 6) & 15;
    int row = idx >> 10;
    int s   = row & (SEQ - 1);

    float inv_freq = exp2f(-13.287712379549449f * ((float)(2 * u) * (1.0f / 128.0f)));
    float ang = (float)s * inv_freq;
    float sn, cs;
    sincosf(ang, &sn, &cs);

    const float SCF = 0.08838834764831845f * 1.4426950408889634f;

    size_t off = (size_t)row * D_MODEL + h * HD + 2 * u;
    float2 qv = *(const float2*)(q + off);
    float2 kv = *(const float2*)(k + off);
    float2 vv = *(const float2*)(v + off);

    float q0 = (qv.x * cs - qv.y * sn) * SCF;
    float q1 = (qv.x * sn + qv.y * cs) * SCF;
    float k0 = kv.x * cs - kv.y * sn;
    float k1 = kv.x * sn + kv.y * cs;

    uint32_t hi, lo;
    split2(q0, q1, hi, lo);
    *(uint32_t*)(qh + off) = hi;  *(uint32_t*)(ql + off) = lo;
    split2(k0, k1, hi, lo);
    *(uint32_t*)(kh + off) = hi;  *(uint32_t*)(kl + off) = lo;
    split2(vv.x, vv.y, hi, lo);
    *(uint32_t*)(vh + off) = hi;  *(uint32_t*)(vl + off) = lo;
}

// ---------------------------------------------------------------------------
// HMMA flash attention (round-4 core; longest-first schedule)
// ---------------------------------------------------------------------------
#define FL_STRIDE 272
#define FL_MAT    (64 * FL_STRIDE)
#define FL_STAGE  (4 * FL_MAT)
#define FL_SMEM   (2 * FL_STAGE)
#define FL_QMAT   (128 * FL_STRIDE)

__global__ __launch_bounds__(256, 1)
void flash_hmma(const __nv_bfloat16* __restrict__ qh, const __nv_bfloat16* __restrict__ ql,
                const __nv_bfloat16* __restrict__ kh, const __nv_bfloat16* __restrict__ kl,
                const __nv_bfloat16* __restrict__ vh, const __nv_bfloat16* __restrict__ vl,
                __nv_bfloat16* __restrict__ oh, __nv_bfloat16* __restrict__ ol) {
    extern __shared__ char smem[];
    const uint32_t sb = smem_u32(smem);
    const int tid  = threadIdx.x;
    const int w    = tid >> 5;
    const int lane = tid & 31;
    const int qt = (int)gridDim.x - 1 - (int)blockIdx.x;   // longest-first
    const int bh = blockIdx.y;
    const int b  = bh >> 4;
    const int h  = bh & 15;

    const size_t gbase = (size_t)b * SEQ * D_MODEL + (size_t)h * HD;
    const int q0 = qt * 128;

    const uint32_t qsm = sb + FL_STAGE;
    {
        const __nv_bfloat16* gq[2] = { qh + gbase + (size_t)q0 * D_MODEL,
                                       ql + gbase + (size_t)q0 * D_MODEL };
        #pragma unroll
        for (int m = 0; m < 2; m++)
            #pragma unroll
            for (int i = 0; i < 8; i++) {
                int idx = i * 256 + tid;
                int r = idx >> 4, c = idx & 15;
                cp16(qsm + m * FL_QMAT + r * FL_STRIDE + c * 16,
                     gq[m] + (size_t)r * D_MODEL + c * 8);
            }
    }
    auto load_chunk = [&](int stage, int kt) {
        uint32_t st = sb + stage * FL_STAGE;
        const __nv_bfloat16* gp[4] = {
            kh + gbase + (size_t)(kt * 64) * D_MODEL,
            kl + gbase + (size_t)(kt * 64) * D_MODEL,
            vh + gbase + (size_t)(kt * 64) * D_MODEL,
            vl + gbase + (size_t)(kt * 64) * D_MODEL };
        #pragma unroll
        for (int m = 0; m < 4; m++)
            #pragma unroll
            for (int i = 0; i < 4; i++) {
                int idx = i * 256 + tid;
                int r = idx >> 4, c = idx & 15;
                cp16(st + m * FL_MAT + r * FL_STRIDE + c * 16,
                     gp[m] + (size_t)r * D_MODEL + c * 8);
            }
        CP_COMMIT();
    };
    load_chunk(0, 0);
    CP_WAIT(0);
    __syncthreads();

    uint32_t fqh[8][4], fql[8][4];
    #pragma unroll
    for (int kk = 0; kk < 8; kk++) {
        uint32_t ra = qsm + (w * 16 + (lane & 15)) * FL_STRIDE + (kk * 16 + (lane >> 4) * 8) * 2;
        LDSM_X4(fqh[kk], ra);
        LDSM_X4(fql[kk], ra + FL_QMAT);
    }
    __syncthreads();
    const int C = 2 * qt + 2;
    if (1 < C) load_chunk(1, 1);

    float o[16][4];
    #pragma unroll
    for (int nt = 0; nt < 16; nt++)
        #pragma unroll
        for (int r = 0; r < 4; r++) o[nt][r] = 0.f;
    float m0 = -1e30f, m1 = -1e30f, l0 = 0.f, l1 = 0.f;

    const int r0 = q0 + w * 16 + (lane >> 2);
    const int r1 = r0 + 8;

    for (int c = 0; c < C; c++) {
        if (c + 1 < C) { CP_WAIT(1); } else { CP_WAIT(0); }
        __syncthreads();
        const uint32_t st = sb + (c & 1) * FL_STAGE;

        const bool skip = (64 * c > q0 + w * 16 + 15);
        if (!skip) {
            float s8[8][4];
            #pragma unroll
            for (int t = 0; t < 8; t++)
                #pragma unroll
                for (int r = 0; r < 4; r++) s8[t][r] = 0.f;

            #pragma unroll
            for (int kk = 0; kk < 8; kk++) {
                #pragma unroll
                for (int np = 0; np < 4; np++) {
                    uint32_t rb = st + (np * 16 + (lane & 7) + ((lane >> 4) & 1) * 8) * FL_STRIDE
                                     + (((lane >> 3) & 1) * 8 + kk * 16) * 2;
                    uint32_t bh4[4], bl4[4];
                    LDSM_X4(bh4, rb);
                    LDSM_X4(bl4, rb + FL_MAT);
                    MMA_BF16(s8[np*2],   fqh[kk], bh4);
                    MMA_BF16(s8[np*2],   fqh[kk], bl4);
                    MMA_BF16(s8[np*2],   fql[kk], bh4);
                    MMA_BF16(s8[np*2+1], fqh[kk], bh4 + 2);
                    MMA_BF16(s8[np*2+1], fqh[kk], bl4 + 2);
                    MMA_BF16(s8[np*2+1], fql[kk], bh4 + 2);
                }
            }

            if (64 * c + 63 > q0 + w * 16) {
                #pragma unroll
                for (int t = 0; t < 8; t++) {
                    int col = c * 64 + t * 8 + (lane & 3) * 2;
                    if (col     > r0) s8[t][0] = -1e30f;
                    if (col + 1 > r0) s8[t][1] = -1e30f;
                    if (col     > r1) s8[t][2] = -1e30f;
                    if (col + 1 > r1) s8[t][3] = -1e30f;
                }
            }

            float mx0 = -1e30f, mx1 = -1e30f;
            #pragma unroll
            for (int t = 0; t < 8; t++) {
                mx0 = fmaxf(mx0, fmaxf(s8[t][0], s8[t][1]));
                mx1 = fmaxf(mx1, fmaxf(s8[t][2], s8[t][3]));
            }
            mx0 = fmaxf(mx0, __shfl_xor_sync(0xffffffffu, mx0, 1));
            mx0 = fmaxf(mx0, __shfl_xor_sync(0xffffffffu, mx0, 2));
            mx1 = fmaxf(mx1, __shfl_xor_sync(0xffffffffu, mx1, 1));
            mx1 = fmaxf(mx1, __shfl_xor_sync(0xffffffffu, mx1, 2));
            float mn0 = fmaxf(m0, mx0), mn1 = fmaxf(m1, mx1);
            float a0 = exp2f(m0 - mn0), a1 = exp2f(m1 - mn1);
            m0 = mn0;  m1 = mn1;
            float sum0 = 0.f, sum1 = 0.f;
            #pragma unroll
            for (int t = 0; t < 8; t++) {
                s8[t][0] = exp2f(s8[t][0] - mn0);
                s8[t][1] = exp2f(s8[t][1] - mn0);
                s8[t][2] = exp2f(s8[t][2] - mn1);
                s8[t][3] = exp2f(s8[t][3] - mn1);
                sum0 += s8[t][0] + s8[t][1];
                sum1 += s8[t][2] + s8[t][3];
            }
            l0 = l0 * a0 + sum0;
            l1 = l1 * a1 + sum1;
            #pragma unroll
            for (int nt = 0; nt < 16; nt++) {
                o[nt][0] *= a0;  o[nt][1] *= a0;
                o[nt][2] *= a1;  o[nt][3] *= a1;
            }

            #pragma unroll
            for (int kk2 = 0; kk2 < 4; kk2++) {
                uint32_t pah[4], pal[4];
                split2(s8[2*kk2][0],   s8[2*kk2][1],   pah[0], pal[0]);
                split2(s8[2*kk2][2],   s8[2*kk2][3],   pah[1], pal[1]);
                split2(s8[2*kk2+1][0], s8[2*kk2+1][1], pah[2], pal[2]);
                split2(s8[2*kk2+1][2], s8[2*kk2+1][3], pah[3], pal[3]);
                #pragma unroll
                for (int np = 0; np < 8; np++) {
                    uint32_t rv = st + 2 * FL_MAT
                                + (kk2 * 16 + (lane & 15)) * FL_STRIDE
                                + (np * 16 + (lane >> 4) * 8) * 2;
                    uint32_t vh4[4], vl4[4];
                    LDSM_T_X4(vh4, rv);
                    LDSM_T_X4(vl4, rv + FL_MAT);
                    MMA_BF16(o[np*2],   pah, vh4);
                    MMA_BF16(o[np*2],   pah, vl4);
                    MMA_BF16(o[np*2],   pal, vh4);
                    MMA_BF16(o[np*2+1], pah, vh4 + 2);
                    MMA_BF16(o[np*2+1], pah, vl4 + 2);
                    MMA_BF16(o[np*2+1], pal, vh4 + 2);
                }
            }
        }
        __syncthreads();
        if (c + 2 < C) load_chunk(c & 1, c + 2);
    }

    l0 += __shfl_xor_sync(0xffffffffu, l0, 1);
    l0 += __shfl_xor_sync(0xffffffffu, l0, 2);
    l1 += __shfl_xor_sync(0xffffffffu, l1, 1);
    l1 += __shfl_xor_sync(0xffffffffu, l1, 2);
    float inv0 = 1.0f / l0, inv1 = 1.0f / l1;

    const size_t orow0 = (size_t)(b * SEQ + r0) * D_MODEL + h * HD;
    const size_t orow1 = (size_t)(b * SEQ + r1) * D_MODEL + h * HD;
    #pragma unroll
    for (int nt = 0; nt < 16; nt++) {
        int col = nt * 8 + (lane & 3) * 2;
        uint32_t hi, lo;
        split2(o[nt][0] * inv0, o[nt][1] * inv0, hi, lo);
        *(uint32_t*)(oh + orow0 + col) = hi;
        *(uint32_t*)(ol + orow0 + col) = lo;
        split2(o[nt][2] * inv1, o[nt][3] * inv1, hi, lo);
        *(uint32_t*)(oh + orow1 + col) = hi;
        *(uint32_t*)(ol + orow1 + col) = lo;
    }
}

// ---------------------------------------------------------------------------
extern "C" void kernel_launch(void* const* d_in, const int* in_sizes, int n_in,
                              void* d_out, int out_size) {
    const float* x  = (const float*)d_in[0];
    const float* Wq = (const float*)d_in[1];
    const float* Wk = (const float*)d_in[2];
    const float* Wv = (const float*)d_in[3];
    const float* Wo = (const float*)d_in[4];
    float* out = (float*)d_out;

    float *qp, *kp, *vp;
    cudaGetSymbolAddress((void**)&qp, g_q);
    cudaGetSymbolAddress((void**)&kp, g_k);
    cudaGetSymbolAddress((void**)&vp, g_v);

    __nv_bfloat16 *xh, *xl, *ah, *al;
    cudaGetSymbolAddress((void**)&xh, g_xh);
    cudaGetSymbolAddress((void**)&xl, g_xl);
    cudaGetSymbolAddress((void**)&ah, g_ah);
    cudaGetSymbolAddress((void**)&al, g_al);

    __nv_bfloat16 *qhp, *qlp, *khp, *klp, *vhp, *vlp;
    cudaGetSymbolAddress((void**)&qhp, g_qh);
    cudaGetSymbolAddress((void**)&qlp, g_ql);
    cudaGetSymbolAddress((void**)&khp, g_kh);
    cudaGetSymbolAddress((void**)&klp, g_kl);
    cudaGetSymbolAddress((void**)&vhp, g_vh);
    cudaGetSymbolAddress((void**)&vlp, g_vl);

    __nv_bfloat16 *wh, *wl;
    cudaGetSymbolAddress((void**)&wh, g_wh);
    cudaGetSymbolAddress((void**)&wl, g_wl);
    const size_t WSZ = (size_t)D_MODEL * D_MODEL;

    cudaFuncSetAttribute(gemm_hmma, cudaFuncAttributeMaxDynamicSharedMemorySize, GEMM_SMEM);
    cudaFuncSetAttribute(flash_hmma, cudaFuncAttributeMaxDynamicSharedMemorySize, FL_SMEM);

    // split inputs (weights into one concatenated [4*2048, 2048] hi/lo pair)
    {
        int n4 = MROWS * D_MODEL / 4;
        split_e<<<(n4 + 255) / 256, 256>>>(x, xh, xl, n4);
        dim3 tb(32, 8), tg(D_MODEL / 32, D_MODEL / 32);
        split_t<<<tg, tb>>>(Wq, wh,           wl);
        split_t<<<tg, tb>>>(Wk, wh + WSZ,     wl + WSZ);
        split_t<<<tg, tb>>>(Wv, wh + 2 * WSZ, wl + 2 * WSZ);
        split_t<<<tg, tb>>>(Wo, wh + 3 * WSZ, wl + 3 * WSZ);
    }

    // fused QKV projection: N = 3*2048 = 48 tiles of 128
    {
        dim3 ggrid(48, MROWS / 128);   // (48, 32) = 1536 CTAs, occ 2
        gemm_hmma<<<ggrid, 256, GEMM_SMEM>>>(xh, xl, wh, wl, qp, kp, vp);
    }

    {
        int total = MROWS * NHEAD * (HD / 2);
        rope_split<<<(total + 255) / 256, 256>>>(qp, kp, vp, qhp, qlp, khp, klp, vhp, vlp);
    }

    {
        dim3 fgrid(SEQ / 128, BATCH * NHEAD);  // (16, 32)
        flash_hmma<<<fgrid, 256, FL_SMEM>>>(qhp, qlp, khp, klp, vhp, vlp, ah, al);
    }

    // output projection: Wo block of the concat buffer
    {
        dim3 ggrid(16, MROWS / 128);   // (16, 32) = 512 CTAs
        gemm_hmma<<<ggrid, 256, GEMM_SMEM>>>(ah, al, wh + 3 * WSZ, wl + 3 * WSZ,
                                             out, out, out);
    }
}

// round 8
// speedup vs baseline: 3.7710x; 1.2322x over previous
#include <cuda_runtime.h>
#include <cuda_bf16.h>
#include <cstdint>
#include <math.h>

#define D_MODEL 2048
#define SEQ     2048
#define BATCH   2
#define NHEAD   16
#define HD      128
#define MROWS   (BATCH*SEQ)   // 4096

// Packed tile-image geometry (matches GEMM smem layout exactly)
#define PADB     80                    // bytes per 32-elem bf16 row (64 data + 16 pad)
#define AMAT     (128 * PADB)          // 10240 B: one 128x32 bf16 matrix image
#define BLKB     (2 * AMAT)            // 20480 B: hi||lo block
#define STAGEB   (2 * BLKB)            // 40960 B: A(hi,lo) + B(hi,lo)

// ---------------------------------------------------------------------------
// Scratch (__device__ globals: allocation-free rule)
// ---------------------------------------------------------------------------
__device__ float g_q[MROWS * D_MODEL];
__device__ float g_k[MROWS * D_MODEL];
__device__ float g_v[MROWS * D_MODEL];

__device__ __nv_bfloat16 g_qh[MROWS * D_MODEL];
__device__ __nv_bfloat16 g_ql[MROWS * D_MODEL];
__device__ __nv_bfloat16 g_kh[MROWS * D_MODEL];
__device__ __nv_bfloat16 g_kl[MROWS * D_MODEL];
__device__ __nv_bfloat16 g_vh[MROWS * D_MODEL];
__device__ __nv_bfloat16 g_vl[MROWS * D_MODEL];

// packed operand images: [tile][kchunk] blocks of 20480B (hi 10240 || lo 10240)
__device__ unsigned char g_xpack[32 * 64 * BLKB];   // x: 32 M-tiles
__device__ unsigned char g_apack[32 * 64 * BLKB];   // attention output
__device__ unsigned char g_wpack[64 * 64 * BLKB];   // Wq,Wk,Wv,Wo: 16 N-tiles each

// ---------------------------------------------------------------------------
// PTX helpers (plain sm_103: no tcgen05; bulk-copy + mbarrier are sm_90 base)
// ---------------------------------------------------------------------------
__device__ __forceinline__ uint32_t smem_u32(const void* p) {
    uint32_t a;
    asm("{ .reg .u64 t; cvta.to.shared.u64 t, %1; cvt.u32.u64 %0, t; }" : "=r"(a) : "l"(p));
    return a;
}
__device__ __forceinline__ void cp16(uint32_t dst, const void* src) {
    asm volatile("cp.async.cg.shared.global [%0], [%1], 16;" :: "r"(dst), "l"(src) : "memory");
}
#define CP_COMMIT() asm volatile("cp.async.commit_group;" ::: "memory")
#define CP_WAIT(n)  asm volatile("cp.async.wait_group %0;" :: "n"(n) : "memory")

#define MBAR_INIT(a, n) asm volatile("mbarrier.init.shared.b64 [%0], %1;" :: "r"(a), "r"(n) : "memory")
#define MBAR_EXPECT(a, n) \
    asm volatile("mbarrier.arrive.expect_tx.shared.b64 _, [%0], %1;" :: "r"(a), "r"(n) : "memory")
#define MBAR_WAIT(a, ph) do { \
    uint32_t _m = (a), _p = (ph), _d; \
    asm volatile("{\n\t.reg .pred p;\n\tmbarrier.try_wait.parity.acquire.cta.shared::cta.b64 p, [%1], %2;\n\tselp.b32 %0,1,0,p;\n\t}" \
        : "=r"(_d) : "r"(_m), "r"(_p) : "memory"); \
    if (!_d) { \
        asm volatile("{\n\t.reg .pred P1;\n\tWL%=: mbarrier.try_wait.parity.acquire.cta.shared::cta.b64 P1, [%0], %1, 0x989680;\n\t@P1 bra.uni WD%=;\n\tbra.uni WL%=;\n\tWD%=:\n\t}" \
            :: "r"(_m), "r"(_p) : "memory"); \
    } } while (0)

#define BULK_G2S(dst, src, bytes, mbar) \
    asm volatile("cp.async.bulk.shared::cta.global.mbarrier::complete_tx::bytes [%0], [%1], %2, [%3];" \
        :: "r"(dst), "l"(src), "r"(bytes), "r"(mbar) : "memory")

#define LDSM_X4(r, addr) \
    asm volatile("ldmatrix.sync.aligned.m8n8.x4.shared.b16 {%0,%1,%2,%3}, [%4];" \
        : "=r"((r)[0]), "=r"((r)[1]), "=r"((r)[2]), "=r"((r)[3]) : "r"(addr))
#define LDSM_T_X4(r, addr) \
    asm volatile("ldmatrix.sync.aligned.m8n8.x4.trans.shared.b16 {%0,%1,%2,%3}, [%4];" \
        : "=r"((r)[0]), "=r"((r)[1]), "=r"((r)[2]), "=r"((r)[3]) : "r"(addr))

#define MMA_BF16(c, a, b) \
    asm volatile("mma.sync.aligned.m16n8k16.row.col.f32.bf16.bf16.f32 " \
        "{%0,%1,%2,%3}, {%4,%5,%6,%7}, {%8,%9}, {%0,%1,%2,%3};" \
        : "+f"((c)[0]), "+f"((c)[1]), "+f"((c)[2]), "+f"((c)[3]) \
        : "r"((a)[0]), "r"((a)[1]), "r"((a)[2]), "r"((a)[3]), "r"((b)[0]), "r"((b)[1]))

__device__ __forceinline__ void split2(float a, float b, uint32_t& hi, uint32_t& lo) {
    __nv_bfloat16 ha = __float2bfloat16(a), hb = __float2bfloat16(b);
    float ra = a - __bfloat162float(ha), rb = b - __bfloat162float(hb);
    __nv_bfloat16 la = __float2bfloat16(ra), lb = __float2bfloat16(rb);
    hi = (uint32_t)__bfloat16_as_ushort(ha) | ((uint32_t)__bfloat16_as_ushort(hb) << 16);
    lo = (uint32_t)__bfloat16_as_ushort(la) | ((uint32_t)__bfloat16_as_ushort(lb) << 16);
}

// ---------------------------------------------------------------------------
// x (fp32 row-major) -> packed hi/lo tile images
// ---------------------------------------------------------------------------
__global__ void split_e_pack(const float* __restrict__ in, unsigned char* __restrict__ pack) {
    int t = blockIdx.x * blockDim.x + threadIdx.x;
    if (t >= MROWS * D_MODEL / 8) return;
    int ch  = t & 3;            // 16B chunk within 32-col block
    int row = (t >> 2) & 127;   // row within M-tile
    int c   = (t >> 9) & 63;    // k-chunk
    int tm  = t >> 15;          // M-tile

    const float* src = in + ((size_t)(tm * 128 + row)) * D_MODEL + c * 32 + ch * 8;
    float4 v0 = *(const float4*)src;
    float4 v1 = *(const float4*)(src + 4);
    uint32_t h[4], l[4];
    split2(v0.x, v0.y, h[0], l[0]);
    split2(v0.z, v0.w, h[1], l[1]);
    split2(v1.x, v1.y, h[2], l[2]);
    split2(v1.z, v1.w, h[3], l[3]);

    unsigned char* blk = pack + ((size_t)(tm * 64 + c)) * BLKB;
    *(uint4*)(blk + row * PADB + ch * 16)        = make_uint4(h[0], h[1], h[2], h[3]);
    *(uint4*)(blk + AMAT + row * PADB + ch * 16) = make_uint4(l[0], l[1], l[2], l[3]);
}

// W[K,N] fp32 -> transposed packed hi/lo tile images (B operand, [N,K] k-major)
__global__ void split_t_pack(const float* __restrict__ in, unsigned char* __restrict__ pack,
                             int wbase) {
    __shared__ float t[32][33];
    int tx = threadIdx.x, ty = threadIdx.y;
    int bn = blockIdx.x, bk = blockIdx.y;
    #pragma unroll
    for (int j = 0; j < 4; j++) {
        int k = bk * 32 + ty + j * 8;
        t[ty + j * 8][tx] = in[(size_t)k * D_MODEL + bn * 32 + tx];
    }
    __syncthreads();
    #pragma unroll
    for (int j = 0; j < 4; j++) {
        int n = bn * 32 + ty + j * 8;
        int k = bk * 32 + tx;
        float v = t[tx][ty + j * 8];
        __nv_bfloat16 hb = __float2bfloat16(v);
        __nv_bfloat16 lb = __float2bfloat16(v - __bfloat162float(hb));
        size_t boff = ((size_t)((wbase + (n >> 7)) * 64 + bk)) * BLKB
                    + (uint32_t)(n & 127) * PADB + ((k & 31) >> 3) * 16 + (k & 7) * 2;
        *(__nv_bfloat16*)(pack + boff)        = hb;
        *(__nv_bfloat16*)(pack + boff + AMAT) = lb;
    }
}

// ---------------------------------------------------------------------------
// HMMA GEMM with bulk-copy loads: CTA 128x128, BK=32, 2-stage, occ 2.
// A from Apack[tileM][c], B from Wpack[wbase+tileN][c]; 2 UBLKCP per chunk.
// ---------------------------------------------------------------------------
#define GEMM_SMEM (2 * STAGEB + 16)   // 81936

__global__ __launch_bounds__(256, 2)
void gemm_hmma(const unsigned char* __restrict__ Apack,
               const unsigned char* __restrict__ Wpack, int wbase,
               float* __restrict__ C0, float* __restrict__ C1, float* __restrict__ C2) {
    extern __shared__ char smem[];
    const uint32_t sb = smem_u32(smem);
    const int tid  = threadIdx.x;
    const int wid  = tid >> 5;
    const int lane = tid & 31;
    const int tileN = blockIdx.x;
    const int tileM = blockIdx.y;

    float* C = (tileN < 16) ? C0 : ((tileN < 32) ? C1 : C2);
    const int nloc = tileN & 15;

    const int m0w = (wid >> 2) * 64;
    const int n0w = (wid & 3) * 32;

    const uint32_t mb0 = sb + 2 * STAGEB;
    if (tid == 0) { MBAR_INIT(mb0, 1); MBAR_INIT(mb0 + 8, 1); }
    __syncthreads();

    auto issue_load = [&](int s, int c) {
        if (tid == 0) {
            uint32_t mb = mb0 + s * 8;
            MBAR_EXPECT(mb, (uint32_t)STAGEB);
            BULK_G2S(sb + s * STAGEB,
                     Apack + ((size_t)(tileM * 64 + c)) * BLKB, (uint32_t)BLKB, mb);
            BULK_G2S(sb + s * STAGEB + BLKB,
                     Wpack + ((size_t)((wbase + tileN) * 64 + c)) * BLKB, (uint32_t)BLKB, mb);
        }
    };

    float acc[4][4][4];
    #pragma unroll
    for (int i = 0; i < 4; i++)
        #pragma unroll
        for (int j = 0; j < 4; j++)
            #pragma unroll
            for (int r = 0; r < 4; r++) acc[i][j][r] = 0.f;

    issue_load(0, 0);
    issue_load(1, 1);

    const int NCH = D_MODEL / 32;   // 64
    for (int c = 0; c < NCH; c++) {
        const int s = c & 1;
        MBAR_WAIT(mb0 + s * 8, (c >> 1) & 1);

        const uint32_t st = sb + s * STAGEB;
        #pragma unroll
        for (int ks = 0; ks < 2; ks++) {
            uint32_t ah[4][4], al[4][4];
            const uint32_t arow = (lane & 15);
            const uint32_t akb  = (ks * 16 + (lane >> 4) * 8) * 2;
            #pragma unroll
            for (int mt = 0; mt < 4; mt++) {
                uint32_t ra = st + (m0w + mt * 16 + arow) * PADB + akb;
                LDSM_X4(ah[mt], ra);
                LDSM_X4(al[mt], ra + AMAT);
            }
            const uint32_t brow = (lane & 7) + ((lane >> 4) & 1) * 8;
            const uint32_t bkb  = (ks * 16 + ((lane >> 3) & 1) * 8) * 2;
            #pragma unroll
            for (int np = 0; np < 2; np++) {
                uint32_t rb = st + BLKB + (n0w + np * 16 + brow) * PADB + bkb;
                uint32_t bh4[4], bl4[4];
                LDSM_X4(bh4, rb);
                LDSM_X4(bl4, rb + AMAT);
                #pragma unroll
                for (int half = 0; half < 2; half++) {
                    const int nt = np * 2 + half;
                    uint32_t* bh = bh4 + half * 2;
                    uint32_t* bl = bl4 + half * 2;
                    #pragma unroll
                    for (int mt = 0; mt < 4; mt++) {
                        MMA_BF16(acc[mt][nt], ah[mt], bh);
                        MMA_BF16(acc[mt][nt], ah[mt], bl);
                        MMA_BF16(acc[mt][nt], al[mt], bh);
                    }
                }
            }
        }
        __syncthreads();
        if (c + 2 < NCH) issue_load(s, c + 2);
    }

    float* cbase = C + (size_t)tileM * 128 * D_MODEL + nloc * 128;
    const int rq = lane >> 2;
    const int cq = (lane & 3) * 2;
    #pragma unroll
    for (int mt = 0; mt < 4; mt++) {
        #pragma unroll
        for (int nt = 0; nt < 4; nt++) {
            int row = m0w + mt * 16 + rq;
            int col = n0w + nt * 8 + cq;
            *(float2*)(cbase + (size_t)row * D_MODEL + col) =
                make_float2(acc[mt][nt][0], acc[mt][nt][1]);
            *(float2*)(cbase + (size_t)(row + 8) * D_MODEL + col) =
                make_float2(acc[mt][nt][2], acc[mt][nt][3]);
        }
    }
}

// ---------------------------------------------------------------------------
// RoPE + split (unchanged)
// ---------------------------------------------------------------------------
__global__ void rope_split(const float* __restrict__ q, const float* __restrict__ k,
                           const float* __restrict__ v,
                           __nv_bfloat16* __restrict__ qh, __nv_bfloat16* __restrict__ ql,
                           __nv_bfloat16* __restrict__ kh, __nv_bfloat16* __restrict__ kl,
                           __nv_bfloat16* __restrict__ vh, __nv_bfloat16* __restrict__ vl) {
    const int total = MROWS * NHEAD * (HD / 2);
    int idx = blockIdx.x * blockDim.x + threadIdx.x;
    if (idx >= total) return;
    int u   = idx & 63;
    int h   = (idx >> 6) & 15;
    int row = idx >> 10;
    int s   = row & (SEQ - 1);

    float inv_freq = exp2f(-13.287712379549449f * ((float)(2 * u) * (1.0f / 128.0f)));
    float ang = (float)s * inv_freq;
    float sn, cs;
    sincosf(ang, &sn, &cs);

    const float SCF = 0.08838834764831845f * 1.4426950408889634f;

    size_t off = (size_t)row * D_MODEL + h * HD + 2 * u;
    float2 qv = *(const float2*)(q + off);
    float2 kv = *(const float2*)(k + off);
    float2 vv = *(const float2*)(v + off);

    float q0 = (qv.x * cs - qv.y * sn) * SCF;
    float q1 = (qv.x * sn + qv.y * cs) * SCF;
    float k0 = kv.x * cs - kv.y * sn;
    float k1 = kv.x * sn + kv.y * cs;

    uint32_t hi, lo;
    split2(q0, q1, hi, lo);
    *(uint32_t*)(qh + off) = hi;  *(uint32_t*)(ql + off) = lo;
    split2(k0, k1, hi, lo);
    *(uint32_t*)(kh + off) = hi;  *(uint32_t*)(kl + off) = lo;
    split2(vv.x, vv.y, hi, lo);
    *(uint32_t*)(vh + off) = hi;  *(uint32_t*)(vl + off) = lo;
}

// ---------------------------------------------------------------------------
// HMMA flash attention (round-4 core; epilogue now writes packed A image)
// ---------------------------------------------------------------------------
#define FL_STRIDE 272
#define FL_MAT    (64 * FL_STRIDE)
#define FL_STAGE  (4 * FL_MAT)
#define FL_SMEM   (2 * FL_STAGE)
#define FL_QMAT   (128 * FL_STRIDE)

__global__ __launch_bounds__(256, 1)
void flash_hmma(const __nv_bfloat16* __restrict__ qh, const __nv_bfloat16* __restrict__ ql,
                const __nv_bfloat16* __restrict__ kh, const __nv_bfloat16* __restrict__ kl,
                const __nv_bfloat16* __restrict__ vh, const __nv_bfloat16* __restrict__ vl,
                unsigned char* __restrict__ apack) {
    extern __shared__ char smem[];
    const uint32_t sb = smem_u32(smem);
    const int tid  = threadIdx.x;
    const int w    = tid >> 5;
    const int lane = tid & 31;
    const int qt = (int)gridDim.x - 1 - (int)blockIdx.x;   // longest-first
    const int bh = blockIdx.y;
    const int b  = bh >> 4;
    const int h  = bh & 15;

    const size_t gbase = (size_t)b * SEQ * D_MODEL + (size_t)h * HD;
    const int q0 = qt * 128;

    const uint32_t qsm = sb + FL_STAGE;
    {
        const __nv_bfloat16* gq[2] = { qh + gbase + (size_t)q0 * D_MODEL,
                                       ql + gbase + (size_t)q0 * D_MODEL };
        #pragma unroll
        for (int m = 0; m < 2; m++)
            #pragma unroll
            for (int i = 0; i < 8; i++) {
                int idx = i * 256 + tid;
                int r = idx >> 4, c = idx & 15;
                cp16(qsm + m * FL_QMAT + r * FL_STRIDE + c * 16,
                     gq[m] + (size_t)r * D_MODEL + c * 8);
            }
    }
    auto load_chunk = [&](int stage, int kt) {
        uint32_t st = sb + stage * FL_STAGE;
        const __nv_bfloat16* gp[4] = {
            kh + gbase + (size_t)(kt * 64) * D_MODEL,
            kl + gbase + (size_t)(kt * 64) * D_MODEL,
            vh + gbase + (size_t)(kt * 64) * D_MODEL,
            vl + gbase + (size_t)(kt * 64) * D_MODEL };
        #pragma unroll
        for (int m = 0; m < 4; m++)
            #pragma unroll
            for (int i = 0; i < 4; i++) {
                int idx = i * 256 + tid;
                int r = idx >> 4, c = idx & 15;
                cp16(st + m * FL_MAT + r * FL_STRIDE + c * 16,
                     gp[m] + (size_t)r * D_MODEL + c * 8);
            }
        CP_COMMIT();
    };
    load_chunk(0, 0);
    CP_WAIT(0);
    __syncthreads();

    uint32_t fqh[8][4], fql[8][4];
    #pragma unroll
    for (int kk = 0; kk < 8; kk++) {
        uint32_t ra = qsm + (w * 16 + (lane & 15)) * FL_STRIDE + (kk * 16 + (lane >> 4) * 8) * 2;
        LDSM_X4(fqh[kk], ra);
        LDSM_X4(fql[kk], ra + FL_QMAT);
    }
    __syncthreads();
    const int C = 2 * qt + 2;
    if (1 < C) load_chunk(1, 1);

    float o[16][4];
    #pragma unroll
    for (int nt = 0; nt < 16; nt++)
        #pragma unroll
        for (int r = 0; r < 4; r++) o[nt][r] = 0.f;
    float m0 = -1e30f, m1 = -1e30f, l0 = 0.f, l1 = 0.f;

    const int r0 = q0 + w * 16 + (lane >> 2);
    const int r1 = r0 + 8;

    for (int c = 0; c < C; c++) {
        if (c + 1 < C) { CP_WAIT(1); } else { CP_WAIT(0); }
        __syncthreads();
        const uint32_t st = sb + (c & 1) * FL_STAGE;

        const bool skip = (64 * c > q0 + w * 16 + 15);
        if (!skip) {
            float s8[8][4];
            #pragma unroll
            for (int t = 0; t < 8; t++)
                #pragma unroll
                for (int r = 0; r < 4; r++) s8[t][r] = 0.f;

            #pragma unroll
            for (int kk = 0; kk < 8; kk++) {
                #pragma unroll
                for (int np = 0; np < 4; np++) {
                    uint32_t rb = st + (np * 16 + (lane & 7) + ((lane >> 4) & 1) * 8) * FL_STRIDE
                                     + (((lane >> 3) & 1) * 8 + kk * 16) * 2;
                    uint32_t bh4[4], bl4[4];
                    LDSM_X4(bh4, rb);
                    LDSM_X4(bl4, rb + FL_MAT);
                    MMA_BF16(s8[np*2],   fqh[kk], bh4);
                    MMA_BF16(s8[np*2],   fqh[kk], bl4);
                    MMA_BF16(s8[np*2],   fql[kk], bh4);
                    MMA_BF16(s8[np*2+1], fqh[kk], bh4 + 2);
                    MMA_BF16(s8[np*2+1], fqh[kk], bl4 + 2);
                    MMA_BF16(s8[np*2+1], fql[kk], bh4 + 2);
                }
            }

            if (64 * c + 63 > q0 + w * 16) {
                #pragma unroll
                for (int t = 0; t < 8; t++) {
                    int col = c * 64 + t * 8 + (lane & 3) * 2;
                    if (col     > r0) s8[t][0] = -1e30f;
                    if (col + 1 > r0) s8[t][1] = -1e30f;
                    if (col     > r1) s8[t][2] = -1e30f;
                    if (col + 1 > r1) s8[t][3] = -1e30f;
                }
            }

            float mx0 = -1e30f, mx1 = -1e30f;
            #pragma unroll
            for (int t = 0; t < 8; t++) {
                mx0 = fmaxf(mx0, fmaxf(s8[t][0], s8[t][1]));
                mx1 = fmaxf(mx1, fmaxf(s8[t][2], s8[t][3]));
            }
            mx0 = fmaxf(mx0, __shfl_xor_sync(0xffffffffu, mx0, 1));
            mx0 = fmaxf(mx0, __shfl_xor_sync(0xffffffffu, mx0, 2));
            mx1 = fmaxf(mx1, __shfl_xor_sync(0xffffffffu, mx1, 1));
            mx1 = fmaxf(mx1, __shfl_xor_sync(0xffffffffu, mx1, 2));
            float mn0 = fmaxf(m0, mx0), mn1 = fmaxf(m1, mx1);
            float a0 = exp2f(m0 - mn0), a1 = exp2f(m1 - mn1);
            m0 = mn0;  m1 = mn1;
            float sum0 = 0.f, sum1 = 0.f;
            #pragma unroll
            for (int t = 0; t < 8; t++) {
                s8[t][0] = exp2f(s8[t][0] - mn0);
                s8[t][1] = exp2f(s8[t][1] - mn0);
                s8[t][2] = exp2f(s8[t][2] - mn1);
                s8[t][3] = exp2f(s8[t][3] - mn1);
                sum0 += s8[t][0] + s8[t][1];
                sum1 += s8[t][2] + s8[t][3];
            }
            l0 = l0 * a0 + sum0;
            l1 = l1 * a1 + sum1;
            #pragma unroll
            for (int nt = 0; nt < 16; nt++) {
                o[nt][0] *= a0;  o[nt][1] *= a0;
                o[nt][2] *= a1;  o[nt][3] *= a1;
            }

            #pragma unroll
            for (int kk2 = 0; kk2 < 4; kk2++) {
                uint32_t pah[4], pal[4];
                split2(s8[2*kk2][0],   s8[2*kk2][1],   pah[0], pal[0]);
                split2(s8[2*kk2][2],   s8[2*kk2][3],   pah[1], pal[1]);
                split2(s8[2*kk2+1][0], s8[2*kk2+1][1], pah[2], pal[2]);
                split2(s8[2*kk2+1][2], s8[2*kk2+1][3], pah[3], pal[3]);
                #pragma unroll
                for (int np = 0; np < 8; np++) {
                    uint32_t rv = st + 2 * FL_MAT
                                + (kk2 * 16 + (lane & 15)) * FL_STRIDE
                                + (np * 16 + (lane >> 4) * 8) * 2;
                    uint32_t vh4[4], vl4[4];
                    LDSM_T_X4(vh4, rv);
                    LDSM_T_X4(vl4, rv + FL_MAT);
                    MMA_BF16(o[np*2],   pah, vh4);
                    MMA_BF16(o[np*2],   pah, vl4);
                    MMA_BF16(o[np*2],   pal, vh4);
                    MMA_BF16(o[np*2+1], pah, vh4 + 2);
                    MMA_BF16(o[np*2+1], pah, vl4 + 2);
                    MMA_BF16(o[np*2+1], pal, vh4 + 2);
                }
            }
        }
        __syncthreads();
        if (c + 2 < C) load_chunk(c & 1, c + 2);
    }

    l0 += __shfl_xor_sync(0xffffffffu, l0, 1);
    l0 += __shfl_xor_sync(0xffffffffu, l0, 2);
    l1 += __shfl_xor_sync(0xffffffffu, l1, 1);
    l1 += __shfl_xor_sync(0xffffffffu, l1, 2);
    float inv0 = 1.0f / l0, inv1 = 1.0f / l1;

    // epilogue: write normalized output directly into packed A image
    const int gr0 = b * SEQ + r0;
    const int gr1 = b * SEQ + r1;
    #pragma unroll
    for (int nt = 0; nt < 16; nt++) {
        int colh = nt * 8 + (lane & 3) * 2;          // 0..127 within head
        int c    = h * 4 + (colh >> 5);              // k-chunk of global col
        uint32_t inoff = ((uint32_t)(colh & 31) >> 3) * 16 + (colh & 7) * 2;
        uint32_t hi, lo;
        size_t b0 = ((size_t)((gr0 >> 7) * 64 + c)) * BLKB + (uint32_t)(gr0 & 127) * PADB + inoff;
        split2(o[nt][0] * inv0, o[nt][1] * inv0, hi, lo);
        *(uint32_t*)(apack + b0)        = hi;
        *(uint32_t*)(apack + b0 + AMAT) = lo;
        size_t b1 = ((size_t)((gr1 >> 7) * 64 + c)) * BLKB + (uint32_t)(gr1 & 127) * PADB + inoff;
        split2(o[nt][2] * inv1, o[nt][3] * inv1, hi, lo);
        *(uint32_t*)(apack + b1)        = hi;
        *(uint32_t*)(apack + b1 + AMAT) = lo;
    }
}

// ---------------------------------------------------------------------------
extern "C" void kernel_launch(void* const* d_in, const int* in_sizes, int n_in,
                              void* d_out, int out_size) {
    const float* x  = (const float*)d_in[0];
    const float* Wq = (const float*)d_in[1];
    const float* Wk = (const float*)d_in[2];
    const float* Wv = (const float*)d_in[3];
    const float* Wo = (const float*)d_in[4];
    float* out = (float*)d_out;

    float *qp, *kp, *vp;
    cudaGetSymbolAddress((void**)&qp, g_q);
    cudaGetSymbolAddress((void**)&kp, g_k);
    cudaGetSymbolAddress((void**)&vp, g_v);

    __nv_bfloat16 *qhp, *qlp, *khp, *klp, *vhp, *vlp;
    cudaGetSymbolAddress((void**)&qhp, g_qh);
    cudaGetSymbolAddress((void**)&qlp, g_ql);
    cudaGetSymbolAddress((void**)&khp, g_kh);
    cudaGetSymbolAddress((void**)&klp, g_kl);
    cudaGetSymbolAddress((void**)&vhp, g_vh);
    cudaGetSymbolAddress((void**)&vlp, g_vl);

    unsigned char *xpk, *apk, *wpk;
    cudaGetSymbolAddress((void**)&xpk, g_xpack);
    cudaGetSymbolAddress((void**)&apk, g_apack);
    cudaGetSymbolAddress((void**)&wpk, g_wpack);

    cudaFuncSetAttribute(gemm_hmma, cudaFuncAttributeMaxDynamicSharedMemorySize, GEMM_SMEM);
    cudaFuncSetAttribute(flash_hmma, cudaFuncAttributeMaxDynamicSharedMemorySize, FL_SMEM);

    // pack weights (Wq,Wk,Wv first) and x
    {
        dim3 tb(32, 8), tg(D_MODEL / 32, D_MODEL / 32);
        split_t_pack<<<tg, tb>>>(Wq, wpk, 0);
        split_t_pack<<<tg, tb>>>(Wk, wpk, 16);
        split_t_pack<<<tg, tb>>>(Wv, wpk, 32);
        int n8 = MROWS * D_MODEL / 8;
        split_e_pack<<<(n8 + 255) / 256, 256>>>(x, xpk);
    }

    // fused QKV projection
    {
        dim3 ggrid(48, MROWS / 128);   // (48, 32)
        gemm_hmma<<<ggrid, 256, GEMM_SMEM>>>(xpk, wpk, 0, qp, kp, vp);
    }

    {
        int total = MROWS * NHEAD * (HD / 2);
        rope_split<<<(total + 255) / 256, 256>>>(qp, kp, vp, qhp, qlp, khp, klp, vhp, vlp);
    }

    {
        dim3 fgrid(SEQ / 128, BATCH * NHEAD);  // (16, 32)
        flash_hmma<<<fgrid, 256, FL_SMEM>>>(qhp, qlp, khp, klp, vhp, vlp, apk);
    }

    // pack Wo (independent of flash) then output projection
    {
        dim3 tb(32, 8), tg(D_MODEL / 32, D_MODEL / 32);
        split_t_pack<<<tg, tb>>>(Wo, wpk, 48);
        dim3 ggrid(16, MROWS / 128);   // (16, 32)
        gemm_hmma<<<ggrid, 256, GEMM_SMEM>>>(apk, wpk, 48, out, out, out);
    }
}

// round 9
// speedup vs baseline: 3.9728x; 1.0535x over previous
#include <cuda_runtime.h>
#include <cuda_bf16.h>
#include <cstdint>
#include <math.h>

#define D_MODEL 2048
#define SEQ     2048
#define BATCH   2
#define NHEAD   16
#define HD      128
#define MROWS   (BATCH*SEQ)   // 4096

// Packed GEMM tile-image geometry (matches GEMM smem layout exactly)
#define PADB     80                    // bytes per 32-elem bf16 row
#define AMAT     (128 * PADB)          // 10240 B
#define BLKB     (2 * AMAT)            // 20480 B: hi||lo block
#define STAGEB   (2 * BLKB)            // 40960 B: A + B

// Packed flash image geometry
#define FL_STRIDE 272                   // 128 bf16 (256B) + 16B pad
#define FL_MAT    (64 * FL_STRIDE)      // 17408
#define FL_STAGE  (4 * FL_MAT)          // 69632: kh,kl,vh,vl
#define FL_QMAT   (128 * FL_STRIDE)     // 34816
#define FL_QBLK   (2 * FL_QMAT)         // 69632: qh,ql
#define FL_SMEM   (2 * FL_STAGE + 32)

// ---------------------------------------------------------------------------
// Scratch (__device__ globals: allocation-free rule)
// ---------------------------------------------------------------------------
__device__ float g_q[MROWS * D_MODEL];
__device__ float g_k[MROWS * D_MODEL];
__device__ float g_v[MROWS * D_MODEL];

__device__ __align__(128) unsigned char g_xpack[32 * 64 * BLKB];
__device__ __align__(128) unsigned char g_apack[32 * 64 * BLKB];
__device__ __align__(128) unsigned char g_wpack[64 * 64 * BLKB];
__device__ __align__(128) unsigned char g_qpack[32 * 16 * FL_QBLK];   // [bh][qt]
__device__ __align__(128) unsigned char g_kvpack[32 * 32 * FL_STAGE]; // [bh][kt]

// ---------------------------------------------------------------------------
// PTX helpers (plain sm_103: no tcgen05; bulk-copy + mbarrier are sm_90 base)
// ---------------------------------------------------------------------------
__device__ __forceinline__ uint32_t smem_u32(const void* p) {
    uint32_t a;
    asm("{ .reg .u64 t; cvta.to.shared.u64 t, %1; cvt.u32.u64 %0, t; }" : "=r"(a) : "l"(p));
    return a;
}
#define MBAR_INIT(a, n) asm volatile("mbarrier.init.shared.b64 [%0], %1;" :: "r"(a), "r"(n) : "memory")
#define MBAR_EXPECT(a, n) \
    asm volatile("mbarrier.arrive.expect_tx.shared.b64 _, [%0], %1;" :: "r"(a), "r"(n) : "memory")
#define MBAR_WAIT(a, ph) do { \
    uint32_t _m = (a), _p = (ph), _d; \
    asm volatile("{\n\t.reg .pred p;\n\tmbarrier.try_wait.parity.acquire.cta.shared::cta.b64 p, [%1], %2;\n\tselp.b32 %0,1,0,p;\n\t}" \
        : "=r"(_d) : "r"(_m), "r"(_p) : "memory"); \
    if (!_d) { \
        asm volatile("{\n\t.reg .pred P1;\n\tWL%=: mbarrier.try_wait.parity.acquire.cta.shared::cta.b64 P1, [%0], %1, 0x989680;\n\t@P1 bra.uni WD%=;\n\tbra.uni WL%=;\n\tWD%=:\n\t}" \
            :: "r"(_m), "r"(_p) : "memory"); \
    } } while (0)

#define BULK_G2S(dst, src, bytes, mbar) \
    asm volatile("cp.async.bulk.shared::cta.global.mbarrier::complete_tx::bytes [%0], [%1], %2, [%3];" \
        :: "r"(dst), "l"(src), "r"(bytes), "r"(mbar) : "memory")

#define LDSM_X4(r, addr) \
    asm volatile("ldmatrix.sync.aligned.m8n8.x4.shared.b16 {%0,%1,%2,%3}, [%4];" \
        : "=r"((r)[0]), "=r"((r)[1]), "=r"((r)[2]), "=r"((r)[3]) : "r"(addr))
#define LDSM_T_X4(r, addr) \
    asm volatile("ldmatrix.sync.aligned.m8n8.x4.trans.shared.b16 {%0,%1,%2,%3}, [%4];" \
        : "=r"((r)[0]), "=r"((r)[1]), "=r"((r)[2]), "=r"((r)[3]) : "r"(addr))

#define MMA_BF16(c, a, b) \
    asm volatile("mma.sync.aligned.m16n8k16.row.col.f32.bf16.bf16.f32 " \
        "{%0,%1,%2,%3}, {%4,%5,%6,%7}, {%8,%9}, {%0,%1,%2,%3};" \
        : "+f"((c)[0]), "+f"((c)[1]), "+f"((c)[2]), "+f"((c)[3]) \
        : "r"((a)[0]), "r"((a)[1]), "r"((a)[2]), "r"((a)[3]), "r"((b)[0]), "r"((b)[1]))

__device__ __forceinline__ void split2(float a, float b, uint32_t& hi, uint32_t& lo) {
    __nv_bfloat16 ha = __float2bfloat16(a), hb = __float2bfloat16(b);
    float ra = a - __bfloat162float(ha), rb = b - __bfloat162float(hb);
    __nv_bfloat16 la = __float2bfloat16(ra), lb = __float2bfloat16(rb);
    hi = (uint32_t)__bfloat16_as_ushort(ha) | ((uint32_t)__bfloat16_as_ushort(hb) << 16);
    lo = (uint32_t)__bfloat16_as_ushort(la) | ((uint32_t)__bfloat16_as_ushort(lb) << 16);
}

// ---------------------------------------------------------------------------
// x (fp32 row-major) -> packed hi/lo GEMM tile images
// ---------------------------------------------------------------------------
__global__ void split_e_pack(const float* __restrict__ in, unsigned char* __restrict__ pack) {
    int t = blockIdx.x * blockDim.x + threadIdx.x;
    if (t >= MROWS * D_MODEL / 8) return;
    int ch  = t & 3;
    int row = (t >> 2) & 127;
    int c   = (t >> 9) & 63;
    int tm  = t >> 15;

    const float* src = in + ((size_t)(tm * 128 + row)) * D_MODEL + c * 32 + ch * 8;
    float4 v0 = *(const float4*)src;
    float4 v1 = *(const float4*)(src + 4);
    uint32_t h[4], l[4];
    split2(v0.x, v0.y, h[0], l[0]);
    split2(v0.z, v0.w, h[1], l[1]);
    split2(v1.x, v1.y, h[2], l[2]);
    split2(v1.z, v1.w, h[3], l[3]);

    unsigned char* blk = pack + ((size_t)(tm * 64 + c)) * BLKB;
    *(uint4*)(blk + row * PADB + ch * 16)        = make_uint4(h[0], h[1], h[2], h[3]);
    *(uint4*)(blk + AMAT + row * PADB + ch * 16) = make_uint4(l[0], l[1], l[2], l[3]);
}

// W[K,N] fp32 -> transposed packed hi/lo tile images
__global__ void split_t_pack(const float* __restrict__ in, unsigned char* __restrict__ pack,
                             int wbase) {
    __shared__ float t[32][33];
    int tx = threadIdx.x, ty = threadIdx.y;
    int bn = blockIdx.x, bk = blockIdx.y;
    #pragma unroll
    for (int j = 0; j < 4; j++) {
        int k = bk * 32 + ty + j * 8;
        t[ty + j * 8][tx] = in[(size_t)k * D_MODEL + bn * 32 + tx];
    }
    __syncthreads();
    #pragma unroll
    for (int j = 0; j < 4; j++) {
        int n = bn * 32 + ty + j * 8;
        int k = bk * 32 + tx;
        float v = t[tx][ty + j * 8];
        __nv_bfloat16 hb = __float2bfloat16(v);
        __nv_bfloat16 lb = __float2bfloat16(v - __bfloat162float(hb));
        size_t boff = ((size_t)((wbase + (n >> 7)) * 64 + bk)) * BLKB
                    + (uint32_t)(n & 127) * PADB + ((k & 31) >> 3) * 16 + (k & 7) * 2;
        *(__nv_bfloat16*)(pack + boff)        = hb;
        *(__nv_bfloat16*)(pack + boff + AMAT) = lb;
    }
}

// ---------------------------------------------------------------------------
// HMMA GEMM with bulk-copy loads + L2 rasterization swizzle.
// CTA 128x128, BK=32, 2-stage, occ 2. tileM varies fastest within 8-wide
// N-groups so a wave's working set fits L2.
// ---------------------------------------------------------------------------
#define GEMM_SMEM (2 * STAGEB + 16)

__global__ __launch_bounds__(256, 2)
void gemm_hmma(const unsigned char* __restrict__ Apack,
               const unsigned char* __restrict__ Wpack, int wbase,
               float* __restrict__ C0, float* __restrict__ C1, float* __restrict__ C2) {
    extern __shared__ char smem[];
    const uint32_t sb = smem_u32(smem);
    const int tid  = threadIdx.x;
    const int wid  = tid >> 5;
    const int lane = tid & 31;

    // swizzle: within a group of 8 N-tiles, tileM varies fastest
    const int bid = blockIdx.x + (int)gridDim.x * blockIdx.y;
    const int MT  = gridDim.y;            // 32
    const int gsz = 8 * MT;               // 256
    const int tileM = (bid % gsz) % MT;
    const int tileN = (bid / gsz) * 8 + (bid % gsz) / MT;

    float* C = (tileN < 16) ? C0 : ((tileN < 32) ? C1 : C2);
    const int nloc = tileN & 15;

    const int m0w = (wid >> 2) * 64;
    const int n0w = (wid & 3) * 32;

    const uint32_t mb0 = sb + 2 * STAGEB;
    if (tid == 0) { MBAR_INIT(mb0, 1); MBAR_INIT(mb0 + 8, 1); }
    __syncthreads();

    auto issue_load = [&](int s, int c) {
        if (tid == 0) {
            uint32_t mb = mb0 + s * 8;
            MBAR_EXPECT(mb, (uint32_t)STAGEB);
            BULK_G2S(sb + s * STAGEB,
                     Apack + ((size_t)(tileM * 64 + c)) * BLKB, (uint32_t)BLKB, mb);
            BULK_G2S(sb + s * STAGEB + BLKB,
                     Wpack + ((size_t)((wbase + tileN) * 64 + c)) * BLKB, (uint32_t)BLKB, mb);
        }
    };

    float acc[4][4][4];
    #pragma unroll
    for (int i = 0; i < 4; i++)
        #pragma unroll
        for (int j = 0; j < 4; j++)
            #pragma unroll
            for (int r = 0; r < 4; r++) acc[i][j][r] = 0.f;

    issue_load(0, 0);
    issue_load(1, 1);

    const int NCH = D_MODEL / 32;   // 64
    for (int c = 0; c < NCH; c++) {
        const int s = c & 1;
        MBAR_WAIT(mb0 + s * 8, (c >> 1) & 1);

        const uint32_t st = sb + s * STAGEB;
        #pragma unroll
        for (int ks = 0; ks < 2; ks++) {
            uint32_t ah[4][4], al[4][4];
            const uint32_t arow = (lane & 15);
            const uint32_t akb  = (ks * 16 + (lane >> 4) * 8) * 2;
            #pragma unroll
            for (int mt = 0; mt < 4; mt++) {
                uint32_t ra = st + (m0w + mt * 16 + arow) * PADB + akb;
                LDSM_X4(ah[mt], ra);
                LDSM_X4(al[mt], ra + AMAT);
            }
            const uint32_t brow = (lane & 7) + ((lane >> 4) & 1) * 8;
            const uint32_t bkb  = (ks * 16 + ((lane >> 3) & 1) * 8) * 2;
            #pragma unroll
            for (int np = 0; np < 2; np++) {
                uint32_t rb = st + BLKB + (n0w + np * 16 + brow) * PADB + bkb;
                uint32_t bh4[4], bl4[4];
                LDSM_X4(bh4, rb);
                LDSM_X4(bl4, rb + AMAT);
                #pragma unroll
                for (int half = 0; half < 2; half++) {
                    const int nt = np * 2 + half;
                    uint32_t* bh = bh4 + half * 2;
                    uint32_t* bl = bl4 + half * 2;
                    #pragma unroll
                    for (int mt = 0; mt < 4; mt++) {
                        MMA_BF16(acc[mt][nt], ah[mt], bh);
                        MMA_BF16(acc[mt][nt], ah[mt], bl);
                        MMA_BF16(acc[mt][nt], al[mt], bh);
                    }
                }
            }
        }
        __syncthreads();
        if (c + 2 < NCH) issue_load(s, c + 2);
    }

    float* cbase = C + (size_t)tileM * 128 * D_MODEL + nloc * 128;
    const int rq = lane >> 2;
    const int cq = (lane & 3) * 2;
    #pragma unroll
    for (int mt = 0; mt < 4; mt++) {
        #pragma unroll
        for (int nt = 0; nt < 4; nt++) {
            int row = m0w + mt * 16 + rq;
            int col = n0w + nt * 8 + cq;
            *(float2*)(cbase + (size_t)row * D_MODEL + col) =
                make_float2(acc[mt][nt][0], acc[mt][nt][1]);
            *(float2*)(cbase + (size_t)(row + 8) * D_MODEL + col) =
                make_float2(acc[mt][nt][2], acc[mt][nt][3]);
        }
    }
}

// ---------------------------------------------------------------------------
// RoPE + split directly into packed flash images (Q scaled by rsqrt*log2e)
// ---------------------------------------------------------------------------
__global__ void rope_split(const float* __restrict__ q, const float* __restrict__ k,
                           const float* __restrict__ v,
                           unsigned char* __restrict__ qpack,
                           unsigned char* __restrict__ kvpack) {
    const int total = MROWS * NHEAD * (HD / 2);
    int idx = blockIdx.x * blockDim.x + threadIdx.x;
    if (idx >= total) return;
    int u   = idx & 63;
    int h   = (idx >> 6) & 15;
    int row = idx >> 10;          // 0..4095
    int s   = row & (SEQ - 1);
    int b   = row >> 11;
    int bh  = b * NHEAD + h;

    float inv_freq = exp2f(-13.287712379549449f * ((float)(2 * u) * (1.0f / 128.0f)));
    float ang = (float)s * inv_freq;
    float sn, cs;
    sincosf(ang, &sn, &cs);

    const float SCF = 0.08838834764831845f * 1.4426950408889634f;

    size_t off = (size_t)row * D_MODEL + h * HD + 2 * u;
    float2 qv = *(const float2*)(q + off);
    float2 kv = *(const float2*)(k + off);
    float2 vv = *(const float2*)(v + off);

    float q0 = (qv.x * cs - qv.y * sn) * SCF;
    float q1 = (qv.x * sn + qv.y * cs) * SCF;
    float k0 = kv.x * cs - kv.y * sn;
    float k1 = kv.x * sn + kv.y * cs;

    uint32_t hi, lo;

    // Q image: [bh][qt][qh|ql][row 0..127][256B row + 16B pad]
    {
        int qt = s >> 7, qrow = s & 127;
        size_t base = ((size_t)(bh * 16 + qt)) * FL_QBLK + (uint32_t)qrow * FL_STRIDE + u * 4;
        split2(q0, q1, hi, lo);
        *(uint32_t*)(qpack + base)           = hi;
        *(uint32_t*)(qpack + base + FL_QMAT) = lo;
    }
    // KV image: [bh][kt][kh|kl|vh|vl][row 0..63][...]
    {
        int kt = s >> 6, krow = s & 63;
        size_t base = ((size_t)(bh * 32 + kt)) * FL_STAGE + (uint32_t)krow * FL_STRIDE + u * 4;
        split2(k0, k1, hi, lo);
        *(uint32_t*)(kvpack + base)              = hi;
        *(uint32_t*)(kvpack + base + FL_MAT)     = lo;
        split2(vv.x, vv.y, hi, lo);
        *(uint32_t*)(kvpack + base + 2 * FL_MAT) = hi;
        *(uint32_t*)(kvpack + base + 3 * FL_MAT) = lo;
    }
}

// ---------------------------------------------------------------------------
// HMMA flash attention with bulk-copy loads (1 UBLKCP per K/V chunk).
// ---------------------------------------------------------------------------
__global__ __launch_bounds__(256, 1)
void flash_hmma(const unsigned char* __restrict__ qpack,
                const unsigned char* __restrict__ kvpack,
                unsigned char* __restrict__ apack) {
    extern __shared__ char smem[];
    const uint32_t sb = smem_u32(smem);
    const int tid  = threadIdx.x;
    const int w    = tid >> 5;
    const int lane = tid & 31;
    const int qt = (int)gridDim.x - 1 - (int)blockIdx.x;   // longest-first
    const int bh = blockIdx.y;
    const int b  = bh >> 4;
    const int h  = bh & 15;

    const int q0 = qt * 128;
    const int C  = 2 * qt + 2;

    const uint32_t qsm = sb + FL_STAGE;      // Q staged in stage-1 region
    const uint32_t mb0 = sb + 2 * FL_STAGE;  // mbars: mb0, mb0+8 (stages), mb0+16 (Q)

    if (tid == 0) { MBAR_INIT(mb0, 1); MBAR_INIT(mb0 + 8, 1); MBAR_INIT(mb0 + 16, 1); }
    __syncthreads();

    const unsigned char* kvbase = kvpack + ((size_t)bh * 32) * FL_STAGE;

    if (tid == 0) {
        MBAR_EXPECT(mb0 + 16, (uint32_t)FL_QBLK);
        BULK_G2S(qsm, qpack + ((size_t)(bh * 16 + qt)) * FL_QBLK, (uint32_t)FL_QBLK, mb0 + 16);
        MBAR_EXPECT(mb0, (uint32_t)FL_STAGE);
        BULK_G2S(sb, kvbase, (uint32_t)FL_STAGE, mb0);
    }

    MBAR_WAIT(mb0 + 16, 0);
    uint32_t fqh[8][4], fql[8][4];
    #pragma unroll
    for (int kk = 0; kk < 8; kk++) {
        uint32_t ra = qsm + (w * 16 + (lane & 15)) * FL_STRIDE + (kk * 16 + (lane >> 4) * 8) * 2;
        LDSM_X4(fqh[kk], ra);
        LDSM_X4(fql[kk], ra + FL_QMAT);
    }
    __syncthreads();                 // all warps done with Q smem (stage 1)
    if (1 < C && tid == 0) {
        MBAR_EXPECT(mb0 + 8, (uint32_t)FL_STAGE);
        BULK_G2S(sb + FL_STAGE, kvbase + FL_STAGE, (uint32_t)FL_STAGE, mb0 + 8);
    }

    float o[16][4];
    #pragma unroll
    for (int nt = 0; nt < 16; nt++)
        #pragma unroll
        for (int r = 0; r < 4; r++) o[nt][r] = 0.f;
    float m0 = -1e30f, m1 = -1e30f, l0 = 0.f, l1 = 0.f;

    const int r0 = q0 + w * 16 + (lane >> 2);
    const int r1 = r0 + 8;

    for (int c = 0; c < C; c++) {
        const int s = c & 1;
        MBAR_WAIT(mb0 + s * 8, (c >> 1) & 1);
        const uint32_t st = sb + s * FL_STAGE;

        const bool skip = (64 * c > q0 + w * 16 + 15);
        if (!skip) {
            float s8[8][4];
            #pragma unroll
            for (int t = 0; t < 8; t++)
                #pragma unroll
                for (int r = 0; r < 4; r++) s8[t][r] = 0.f;

            #pragma unroll
            for (int kk = 0; kk < 8; kk++) {
                #pragma unroll
                for (int np = 0; np < 4; np++) {
                    uint32_t rb = st + (np * 16 + (lane & 7) + ((lane >> 4) & 1) * 8) * FL_STRIDE
                                     + (((lane >> 3) & 1) * 8 + kk * 16) * 2;
                    uint32_t bh4[4], bl4[4];
                    LDSM_X4(bh4, rb);
                    LDSM_X4(bl4, rb + FL_MAT);
                    MMA_BF16(s8[np*2],   fqh[kk], bh4);
                    MMA_BF16(s8[np*2],   fqh[kk], bl4);
                    MMA_BF16(s8[np*2],   fql[kk], bh4);
                    MMA_BF16(s8[np*2+1], fqh[kk], bh4 + 2);
                    MMA_BF16(s8[np*2+1], fqh[kk], bl4 + 2);
                    MMA_BF16(s8[np*2+1], fql[kk], bh4 + 2);
                }
            }

            if (64 * c + 63 > q0 + w * 16) {
                #pragma unroll
                for (int t = 0; t < 8; t++) {
                    int col = c * 64 + t * 8 + (lane & 3) * 2;
                    if (col     > r0) s8[t][0] = -1e30f;
                    if (col + 1 > r0) s8[t][1] = -1e30f;
                    if (col     > r1) s8[t][2] = -1e30f;
                    if (col + 1 > r1) s8[t][3] = -1e30f;
                }
            }

            float mx0 = -1e30f, mx1 = -1e30f;
            #pragma unroll
            for (int t = 0; t < 8; t++) {
                mx0 = fmaxf(mx0, fmaxf(s8[t][0], s8[t][1]));
                mx1 = fmaxf(mx1, fmaxf(s8[t][2], s8[t][3]));
            }
            mx0 = fmaxf(mx0, __shfl_xor_sync(0xffffffffu, mx0, 1));
            mx0 = fmaxf(mx0, __shfl_xor_sync(0xffffffffu, mx0, 2));
            mx1 = fmaxf(mx1, __shfl_xor_sync(0xffffffffu, mx1, 1));
            mx1 = fmaxf(mx1, __shfl_xor_sync(0xffffffffu, mx1, 2));
            float mn0 = fmaxf(m0, mx0), mn1 = fmaxf(m1, mx1);
            float a0 = exp2f(m0 - mn0), a1 = exp2f(m1 - mn1);
            m0 = mn0;  m1 = mn1;
            float sum0 = 0.f, sum1 = 0.f;
            #pragma unroll
            for (int t = 0; t < 8; t++) {
                s8[t][0] = exp2f(s8[t][0] - mn0);
                s8[t][1] = exp2f(s8[t][1] - mn0);
                s8[t][2] = exp2f(s8[t][2] - mn1);
                s8[t][3] = exp2f(s8[t][3] - mn1);
                sum0 += s8[t][0] + s8[t][1];
                sum1 += s8[t][2] + s8[t][3];
            }
            l0 = l0 * a0 + sum0;
            l1 = l1 * a1 + sum1;
            #pragma unroll
            for (int nt = 0; nt < 16; nt++) {
                o[nt][0] *= a0;  o[nt][1] *= a0;
                o[nt][2] *= a1;  o[nt][3] *= a1;
            }

            #pragma unroll
            for (int kk2 = 0; kk2 < 4; kk2++) {
                uint32_t pah[4], pal[4];
                split2(s8[2*kk2][0],   s8[2*kk2][1],   pah[0], pal[0]);
                split2(s8[2*kk2][2],   s8[2*kk2][3],   pah[1], pal[1]);
                split2(s8[2*kk2+1][0], s8[2*kk2+1][1], pah[2], pal[2]);
                split2(s8[2*kk2+1][2], s8[2*kk2+1][3], pah[3], pal[3]);
                #pragma unroll
                for (int np = 0; np < 8; np++) {
                    uint32_t rv = st + 2 * FL_MAT
                                + (kk2 * 16 + (lane & 15)) * FL_STRIDE
                                + (np * 16 + (lane >> 4) * 8) * 2;
                    uint32_t vh4[4], vl4[4];
                    LDSM_T_X4(vh4, rv);
                    LDSM_T_X4(vl4, rv + FL_MAT);
                    MMA_BF16(o[np*2],   pah, vh4);
                    MMA_BF16(o[np*2],   pah, vl4);
                    MMA_BF16(o[np*2],   pal, vh4);
                    MMA_BF16(o[np*2+1], pah, vh4 + 2);
                    MMA_BF16(o[np*2+1], pah, vl4 + 2);
                    MMA_BF16(o[np*2+1], pal, vh4 + 2);
                }
            }
        }
        __syncthreads();
        if (c + 2 < C && tid == 0) {
            MBAR_EXPECT(mb0 + s * 8, (uint32_t)FL_STAGE);
            BULK_G2S(sb + s * FL_STAGE, kvbase + (size_t)(c + 2) * FL_STAGE,
                     (uint32_t)FL_STAGE, mb0 + s * 8);
        }
    }

    l0 += __shfl_xor_sync(0xffffffffu, l0, 1);
    l0 += __shfl_xor_sync(0xffffffffu, l0, 2);
    l1 += __shfl_xor_sync(0xffffffffu, l1, 1);
    l1 += __shfl_xor_sync(0xffffffffu, l1, 2);
    float inv0 = 1.0f / l0, inv1 = 1.0f / l1;

    // epilogue: write normalized output directly into packed A image
    const int gr0 = b * SEQ + r0;
    const int gr1 = b * SEQ + r1;
    #pragma unroll
    for (int nt = 0; nt < 16; nt++) {
        int colh = nt * 8 + (lane & 3) * 2;
        int c    = h * 4 + (colh >> 5);
        uint32_t inoff = ((uint32_t)(colh & 31) >> 3) * 16 + (colh & 7) * 2;
        uint32_t hi, lo;
        size_t b0 = ((size_t)((gr0 >> 7) * 64 + c)) * BLKB + (uint32_t)(gr0 & 127) * PADB + inoff;
        split2(o[nt][0] * inv0, o[nt][1] * inv0, hi, lo);
        *(uint32_t*)(apack + b0)        = hi;
        *(uint32_t*)(apack + b0 + AMAT) = lo;
        size_t b1 = ((size_t)((gr1 >> 7) * 64 + c)) * BLKB + (uint32_t)(gr1 & 127) * PADB + inoff;
        split2(o[nt][2] * inv1, o[nt][3] * inv1, hi, lo);
        *(uint32_t*)(apack + b1)        = hi;
        *(uint32_t*)(apack + b1 + AMAT) = lo;
    }
}

// ---------------------------------------------------------------------------
extern "C" void kernel_launch(void* const* d_in, const int* in_sizes, int n_in,
                              void* d_out, int out_size) {
    const float* x  = (const float*)d_in[0];
    const float* Wq = (const float*)d_in[1];
    const float* Wk = (const float*)d_in[2];
    const float* Wv = (const float*)d_in[3];
    const float* Wo = (const float*)d_in[4];
    float* out = (float*)d_out;

    float *qp, *kp, *vp;
    cudaGetSymbolAddress((void**)&qp, g_q);
    cudaGetSymbolAddress((void**)&kp, g_k);
    cudaGetSymbolAddress((void**)&vp, g_v);

    unsigned char *xpk, *apk, *wpk, *qpk, *kvpk;
    cudaGetSymbolAddress((void**)&xpk, g_xpack);
    cudaGetSymbolAddress((void**)&apk, g_apack);
    cudaGetSymbolAddress((void**)&wpk, g_wpack);
    cudaGetSymbolAddress((void**)&qpk, g_qpack);
    cudaGetSymbolAddress((void**)&kvpk, g_kvpack);

    cudaFuncSetAttribute(gemm_hmma, cudaFuncAttributeMaxDynamicSharedMemorySize, GEMM_SMEM);
    cudaFuncSetAttribute(flash_hmma, cudaFuncAttributeMaxDynamicSharedMemorySize, FL_SMEM);

    // pack weights (Wq,Wk,Wv first) and x
    {
        dim3 tb(32, 8), tg(D_MODEL / 32, D_MODEL / 32);
        split_t_pack<<<tg, tb>>>(Wq, wpk, 0);
        split_t_pack<<<tg, tb>>>(Wk, wpk, 16);
        split_t_pack<<<tg, tb>>>(Wv, wpk, 32);
        int n8 = MROWS * D_MODEL / 8;
        split_e_pack<<<(n8 + 255) / 256, 256>>>(x, xpk);
    }

    // fused QKV projection
    {
        dim3 ggrid(48, MROWS / 128);   // (48, 32)
        gemm_hmma<<<ggrid, 256, GEMM_SMEM>>>(xpk, wpk, 0, qp, kp, vp);
    }

    {
        int total = MROWS * NHEAD * (HD / 2);
        rope_split<<<(total + 255) / 256, 256>>>(qp, kp, vp, qpk, kvpk);
    }

    {
        dim3 fgrid(SEQ / 128, BATCH * NHEAD);  // (16, 32)
        flash_hmma<<<fgrid, 256, FL_SMEM>>>(qpk, kvpk, apk);
    }

    // pack Wo (independent of flash) then output projection
    {
        dim3 tb(32, 8), tg(D_MODEL / 32, D_MODEL / 32);
        split_t_pack<<<tg, tb>>>(Wo, wpk, 48);
        dim3 ggrid(16, MROWS / 128);   // (16, 32)
        gemm_hmma<<<ggrid, 256, GEMM_SMEM>>>(apk, wpk, 48, out, out, out);
    }
}